// round 4
// baseline (speedup 1.0000x reference)
#include <cuda_runtime.h>
#include <cstdint>
#include <cstddef>

#define N_NODES 16384
#define E_EDGES 262144
#define F_IN    1024
#define H1_DIM  256
#define NZ_DIM  64

// ---------------- scratch ----------------------------------------------------
__device__ float g_support1[N_NODES * H1_DIM];
__device__ float g_hidden1 [N_NODES * H1_DIM];
__device__ float g_support2[N_NODES * NZ_DIM];
__device__ int   g_off   [N_NODES + 1];
__device__ int   g_cursor[N_NODES];
__device__ int2  g_srcw  [E_EDGES];

// ---------------- helpers -----------------------------------------------------
__device__ __forceinline__ uint32_t f2tf32(float x) {
    uint32_t u;
    asm("cvt.rna.tf32.f32 %0, %1;" : "=r"(u) : "f"(x));
    return u;
}
__device__ __forceinline__ void cp16(uint32_t s, const void* g) {
    asm volatile("cp.async.cg.shared.global [%0], [%1], 16;\n" ::"r"(s), "l"(g));
}
__device__ __forceinline__ void cp_commit() {
    asm volatile("cp.async.commit_group;\n");
}
template <int N>
__device__ __forceinline__ void cp_wait() {
    asm volatile("cp.async.wait_group %0;\n" ::"n"(N));
}
__device__ __forceinline__ void mma_tf32(float (&d)[4], const uint32_t (&a)[4],
                                         const uint32_t (&b)[2]) {
    asm volatile(
        "mma.sync.aligned.m16n8k8.row.col.f32.tf32.tf32.f32 "
        "{%0,%1,%2,%3}, {%4,%5,%6,%7}, {%8,%9}, {%0,%1,%2,%3};"
        : "+f"(d[0]), "+f"(d[1]), "+f"(d[2]), "+f"(d[3])
        : "r"(a[0]), "r"(a[1]), "r"(a[2]), "r"(a[3]), "r"(b[0]), "r"(b[1]));
}

// ---------------- CSR build ----------------------------------------------------
__global__ void k_zero_counts() {
    int i = blockIdx.x * blockDim.x + threadIdx.x;
    ((int4*)g_cursor)[i] = make_int4(0, 0, 0, 0);
}
__global__ void k_hist(const int* __restrict__ ei) {
    int e = blockIdx.x * blockDim.x + threadIdx.x;
    if (e < E_EDGES) atomicAdd(&g_cursor[ei[E_EDGES + e]], 1);
}
__global__ void k_scan() {
    __shared__ int part[256];
    const int t = threadIdx.x;
    const int base = t * (N_NODES / 256);
    int s = 0;
#pragma unroll
    for (int j = 0; j < N_NODES / 256; j++) s += g_cursor[base + j];
    part[t] = s;
    __syncthreads();
    for (int off = 1; off < 256; off <<= 1) {
        int v = (t >= off) ? part[t - off] : 0;
        __syncthreads();
        part[t] += v;
        __syncthreads();
    }
    int run = part[t] - s;
#pragma unroll
    for (int j = 0; j < N_NODES / 256; j++) {
        int idx = base + j;
        int c = g_cursor[idx];
        g_off[idx] = run;
        g_cursor[idx] = run;
        run += c;
    }
    if (t == 255) g_off[N_NODES] = run;
}
__global__ void k_scatter(const int* __restrict__ ei, const float* __restrict__ ew) {
    int e = blockIdx.x * blockDim.x + threadIdx.x;
    if (e < E_EDGES) {
        int d = ei[E_EDGES + e];
        int p = atomicAdd(&g_cursor[d], 1);
        g_srcw[p] = make_int2(ei[e], __float_as_int(ew[e]));
    }
}

// ---------------- SpMM + ReLU (smem-staged edges, MLP=8) ----------------------
__global__ void __launch_bounds__(256) k_spmm_relu_256(
    const float* __restrict__ in, float* __restrict__ out) {
    __shared__ int2 se[256];
    const int row = blockIdx.x;
    const int t   = threadIdx.x;
    const int beg = g_off[row], end = g_off[row + 1];
    float acc = 0.f;
    for (int cs = beg; cs < end; cs += 256) {
        int m = min(256, end - cs);
        __syncthreads();
        if (t < m) se[t] = g_srcw[cs + t];
        __syncthreads();
        int j = 0;
        for (; j + 8 <= m; j += 8) {
            float r[8];
            int2  v[8];
#pragma unroll
            for (int u = 0; u < 8; u++) v[u] = se[j + u];
#pragma unroll
            for (int u = 0; u < 8; u++)
                r[u] = __ldg(&in[(size_t)v[u].x * H1_DIM + t]);
#pragma unroll
            for (int u = 0; u < 8; u++)
                acc += __int_as_float(v[u].y) * r[u];
        }
        for (; j < m; j++) {
            int2 v = se[j];
            acc += __int_as_float(v.y) * __ldg(&in[(size_t)v.x * H1_DIM + t]);
        }
    }
    out[(size_t)row * H1_DIM + t] = fmaxf(acc, 0.f);
}

__global__ void __launch_bounds__(256) k_spmm_relu_64(
    const float* __restrict__ in, float* __restrict__ out) {
    __shared__ int2 se[4][64];
    __shared__ int sdeg[4];
    const int t    = threadIdx.x;
    const int sub  = t >> 6;
    const int lane = t & 63;
    const int row  = blockIdx.x * 4 + sub;
    const int beg  = g_off[row];
    if (t < 4) sdeg[t] = g_off[blockIdx.x * 4 + t + 1] - g_off[blockIdx.x * 4 + t];
    __syncthreads();
    const int deg  = sdeg[sub];
    const int nch  = (max(max(sdeg[0], sdeg[1]), max(sdeg[2], sdeg[3])) + 63) >> 6;
    float acc = 0.f;
    for (int ch = 0; ch < nch; ch++) {
        int m = min(64, deg - ch * 64);
        __syncthreads();
        if (lane < m) se[sub][lane] = g_srcw[beg + ch * 64 + lane];
        __syncthreads();
        int j = 0;
        for (; j + 8 <= m; j += 8) {
            float r[8];
            int2  v[8];
#pragma unroll
            for (int u = 0; u < 8; u++) v[u] = se[sub][j + u];
#pragma unroll
            for (int u = 0; u < 8; u++)
                r[u] = __ldg(&in[(size_t)v[u].x * NZ_DIM + lane]);
#pragma unroll
            for (int u = 0; u < 8; u++)
                acc += __int_as_float(v[u].y) * r[u];
        }
        for (; j < m; j++) {
            int2 v = se[sub][j];
            acc += __int_as_float(v.y) * __ldg(&in[(size_t)v.x * NZ_DIM + lane]);
        }
    }
    out[(size_t)row * NZ_DIM + lane] = fmaxf(acc, 0.f);
}

// ---------------- 3-stage pipelined TF32 GEMM (B row-major [K,Nc]) -------------
template <int BM, int BN, int BK>
__global__ void __launch_bounds__(256, 2)
k_gemm(const float* __restrict__ A, const float* __restrict__ B,
       float* __restrict__ C, int M, int Nc, int K) {
    constexpr int WM = BM / 2, WN = BN / 4;
    constexpr int MI = WM / 16, NI = WN / 8;
    constexpr int AP = BK + 4;
    constexpr int BP = BN + 8;
    constexpr int ASZ = BM * AP;
    constexpr int BSZ = BK * BP;
    constexpr int ACH = BM * BK / (4 * 256);
    constexpr int BCH = BK * BN / (4 * 256);
    constexpr int STG = 3;

    extern __shared__ float sm[];
    float* sA0 = sm;                   // STG stages of A, then STG stages of B
    float* sB0 = sm + STG * ASZ;
    const uint32_t smem_u32 = (uint32_t)__cvta_generic_to_shared(sm);

    const int tid  = threadIdx.x;
    const int warp = tid >> 5, lane = tid & 31;
    const int wm = warp & 1, wn = warp >> 1;
    const int bm0 = blockIdx.y * BM, bn0 = blockIdx.x * BN;
    const int g = lane >> 2, c = lane & 3;

    float acc[MI][NI][4];
#pragma unroll
    for (int mi = 0; mi < MI; mi++)
#pragma unroll
        for (int ni = 0; ni < NI; ni++)
#pragma unroll
            for (int j = 0; j < 4; j++) acc[mi][ni][j] = 0.f;

    const int NT = K / BK;

    auto load_tiles = [&](int kt, int st) {
        const float* Ag = A + (size_t)bm0 * K + kt * BK;
        uint32_t abase = smem_u32 + (uint32_t)(st * ASZ) * 4u;
#pragma unroll
        for (int i = 0; i < ACH; i++) {
            int v = tid + i * 256;
            int r = v / (BK / 4), col = (v % (BK / 4)) * 4;
            cp16(abase + (uint32_t)(r * AP + col) * 4u, Ag + (size_t)r * K + col);
        }
        const float* Bg = B + (size_t)(kt * BK) * Nc + bn0;
        uint32_t bbase = smem_u32 + (uint32_t)(STG * ASZ + st * BSZ) * 4u;
#pragma unroll
        for (int i = 0; i < BCH; i++) {
            int v = tid + i * 256;
            int r = v / (BN / 4), col = (v % (BN / 4)) * 4;
            cp16(bbase + (uint32_t)(r * BP + col) * 4u, Bg + (size_t)r * Nc + col);
        }
    };

    load_tiles(0, 0);
    cp_commit();
    load_tiles(1, 1);
    cp_commit();

    for (int kt = 0; kt < NT; kt++) {
        cp_wait<1>();
        __syncthreads();

        // prefetch kt+2 into stage (kt+2)%3 — not read until 2 iterations later
        int pf = kt + 2;
        if (pf < NT) load_tiles(pf, pf % STG);
        cp_commit();   // always commit so pending-group count stays exact

        const float* sA = sA0 + (kt % STG) * ASZ;
        const float* sB = sB0 + (kt % STG) * BSZ;
#pragma unroll
        for (int ks = 0; ks < BK / 8; ks++) {
            const int k0 = ks * 8;
            uint32_t af[MI][4];
            uint32_t bf[NI][2];
#pragma unroll
            for (int mi = 0; mi < MI; mi++) {
                int r = wm * WM + mi * 16 + g;
                af[mi][0] = f2tf32(sA[r * AP + k0 + c]);
                af[mi][1] = f2tf32(sA[(r + 8) * AP + k0 + c]);
                af[mi][2] = f2tf32(sA[r * AP + k0 + 4 + c]);
                af[mi][3] = f2tf32(sA[(r + 8) * AP + k0 + 4 + c]);
            }
#pragma unroll
            for (int ni = 0; ni < NI; ni++) {
                int n = wn * WN + ni * 8 + g;
                bf[ni][0] = f2tf32(sB[(k0 + c) * BP + n]);
                bf[ni][1] = f2tf32(sB[(k0 + 4 + c) * BP + n]);
            }
#pragma unroll
            for (int mi = 0; mi < MI; mi++)
#pragma unroll
                for (int ni = 0; ni < NI; ni++)
                    mma_tf32(acc[mi][ni], af[mi], bf[ni]);
        }
    }

    __syncthreads();
#pragma unroll
    for (int mi = 0; mi < MI; mi++)
#pragma unroll
        for (int ni = 0; ni < NI; ni++) {
            int r  = bm0 + wm * WM + mi * 16 + g;
            int cc = bn0 + wn * WN + ni * 8 + c * 2;
            *reinterpret_cast<float2*>(&C[(size_t)r * Nc + cc]) =
                make_float2(acc[mi][ni][0], acc[mi][ni][1]);
            *reinterpret_cast<float2*>(&C[(size_t)(r + 8) * Nc + cc]) =
                make_float2(acc[mi][ni][2], acc[mi][ni][3]);
        }
}

// ---------------- z @ z^T, symmetric: lower-triangle blocks only --------------
__global__ void __launch_bounds__(256, 2)
k_zzt(const float* __restrict__ Z, float* __restrict__ C) {
    constexpr int P  = 68;
    constexpr int TP = 132;
    extern __shared__ float sm[];
    float* sA = sm;
    float* sB = sm + 128 * P;
    const uint32_t smem_u32 = (uint32_t)__cvta_generic_to_shared(sm);

    const int tid  = threadIdx.x;
    const int warp = tid >> 5, lane = tid & 31;
    const int wm = warp & 1, wn = warp >> 1;
    const int g = lane >> 2, c = lane & 3;

    int t = blockIdx.x;
    int bi = (int)((sqrtf(8.f * (float)t + 1.f) - 1.f) * 0.5f);
    while ((bi + 1) * (bi + 2) / 2 <= t) bi++;
    while (bi * (bi + 1) / 2 > t) bi--;
    int bj = t - bi * (bi + 1) / 2;
    const int bm0 = bi * 128;
    const int bn0 = bj * 128;

#pragma unroll
    for (int i = 0; i < 8; i++) {
        int v = tid + i * 256;
        int r = v / 16, col = (v % 16) * 4;
        cp16(smem_u32 + (uint32_t)(r * P + col) * 4u,
             Z + (size_t)(bm0 + r) * NZ_DIM + col);
    }
#pragma unroll
    for (int i = 0; i < 8; i++) {
        int v = tid + i * 256;
        int r = v / 16, col = (v % 16) * 4;
        cp16(smem_u32 + (uint32_t)(128 * P + r * P + col) * 4u,
             Z + (size_t)(bn0 + r) * NZ_DIM + col);
    }
    cp_commit();
    cp_wait<0>();
    __syncthreads();

    float acc[4][4][4];
#pragma unroll
    for (int mi = 0; mi < 4; mi++)
#pragma unroll
        for (int ni = 0; ni < 4; ni++)
#pragma unroll
            for (int j = 0; j < 4; j++) acc[mi][ni][j] = 0.f;

#pragma unroll
    for (int ks = 0; ks < 8; ks++) {
        const int k0 = ks * 8;
        uint32_t af[4][4];
        uint32_t bf[4][2];
#pragma unroll
        for (int mi = 0; mi < 4; mi++) {
            int r = wm * 64 + mi * 16 + g;
            af[mi][0] = f2tf32(sA[r * P + k0 + c]);
            af[mi][1] = f2tf32(sA[(r + 8) * P + k0 + c]);
            af[mi][2] = f2tf32(sA[r * P + k0 + 4 + c]);
            af[mi][3] = f2tf32(sA[(r + 8) * P + k0 + 4 + c]);
        }
#pragma unroll
        for (int ni = 0; ni < 4; ni++) {
            int n = wn * 32 + ni * 8 + g;
            bf[ni][0] = f2tf32(sB[n * P + k0 + c]);
            bf[ni][1] = f2tf32(sB[n * P + k0 + 4 + c]);
        }
#pragma unroll
        for (int mi = 0; mi < 4; mi++)
#pragma unroll
            for (int ni = 0; ni < 4; ni++)
                mma_tf32(acc[mi][ni], af[mi], bf[ni]);
    }

#pragma unroll
    for (int mi = 0; mi < 4; mi++)
#pragma unroll
        for (int ni = 0; ni < 4; ni++) {
            int r  = bm0 + wm * 64 + mi * 16 + g;
            int cc = bn0 + wn * 32 + ni * 8 + c * 2;
            *reinterpret_cast<float2*>(&C[(size_t)r * N_NODES + cc]) =
                make_float2(acc[mi][ni][0], acc[mi][ni][1]);
            *reinterpret_cast<float2*>(&C[(size_t)(r + 8) * N_NODES + cc]) =
                make_float2(acc[mi][ni][2], acc[mi][ni][3]);
        }

    if (bi == bj) return;

    __syncthreads();
#pragma unroll
    for (int mi = 0; mi < 4; mi++)
#pragma unroll
        for (int ni = 0; ni < 4; ni++) {
            int r  = wm * 64 + mi * 16 + g;
            int cc = wn * 32 + ni * 8 + c * 2;
            sm[(size_t)cc * TP + r]           = acc[mi][ni][0];
            sm[(size_t)(cc + 1) * TP + r]     = acc[mi][ni][1];
            sm[(size_t)cc * TP + r + 8]       = acc[mi][ni][2];
            sm[(size_t)(cc + 1) * TP + r + 8] = acc[mi][ni][3];
        }
    __syncthreads();
#pragma unroll
    for (int i = 0; i < 16; i++) {
        int v = tid + i * 256;
        int j = v >> 5, col = (v & 31) * 4;
        float4 q = *reinterpret_cast<const float4*>(&sm[(size_t)j * TP + col]);
        *reinterpret_cast<float4*>(&C[(size_t)(bn0 + j) * N_NODES + bm0 + col]) = q;
    }
}

// ---------------- launch --------------------------------------------------------
extern "C" void kernel_launch(void* const* d_in, const int* in_sizes, int n_in,
                              void* d_out, int out_size) {
    const float* x  = (const float*)d_in[0];
    const float* W1 = (const float*)d_in[1];
    const float* W2 = (const float*)d_in[2];
    const float* ew = (const float*)d_in[3];
    const int*   ei = (const int*)d_in[4];

    float* out  = (float*)d_out;
    float* abar = out;
    float* z    = out + (size_t)N_NODES * N_NODES;

    float *s1, *h1, *s2;
    cudaGetSymbolAddress((void**)&s1, g_support1);
    cudaGetSymbolAddress((void**)&h1, g_hidden1);
    cudaGetSymbolAddress((void**)&s2, g_support2);

    constexpr int SM_G1  = 3 * (128 * 36 + 32 * 136) * 4;  // 107520
    constexpr int SM_G2  = 3 * (128 * 36 + 32 * 72) * 4;   // 82944
    constexpr int SM_ZZT = 2 * 128 * 68 * 4;               // 69632

    cudaFuncSetAttribute(k_gemm<128, 128, 32>,
                         cudaFuncAttributeMaxDynamicSharedMemorySize, SM_G1);
    cudaFuncSetAttribute(k_gemm<128, 64, 32>,
                         cudaFuncAttributeMaxDynamicSharedMemorySize, SM_G2);
    cudaFuncSetAttribute(k_zzt,
                         cudaFuncAttributeMaxDynamicSharedMemorySize, SM_ZZT);

    // CSR-by-dst
    k_zero_counts<<<N_NODES / 1024, 256>>>();
    k_hist<<<E_EDGES / 256, 256>>>(ei);
    k_scan<<<1, 256>>>();
    k_scatter<<<E_EDGES / 256, 256>>>(ei, ew);

    // support1 = x @ W1
    k_gemm<128, 128, 32><<<dim3(H1_DIM / 128, N_NODES / 128), 256, SM_G1>>>(
        x, W1, s1, N_NODES, H1_DIM, F_IN);

    // hidden1 = relu(spmm(support1))
    k_spmm_relu_256<<<N_NODES, 256>>>(s1, h1);

    // support2 = hidden1 @ W2
    k_gemm<128, 64, 32><<<dim3(1, N_NODES / 128), 256, SM_G2>>>(
        h1, W2, s2, N_NODES, NZ_DIM, H1_DIM);

    // z = relu(spmm(support2))
    k_spmm_relu_64<<<N_NODES / 4, 256>>>(s2, z);

    // a_bar = z @ z^T (triangular grid, off-diag tiles stored twice)
    const int ntile = N_NODES / 128;
    k_zzt<<<ntile * (ntile + 1) / 2, 256, SM_ZZT>>>(z, abar);
}

// round 6
// speedup vs baseline: 1.0375x; 1.0375x over previous
#include <cuda_runtime.h>
#include <cstdint>
#include <cstddef>

#define N_NODES 16384
#define E_EDGES 262144
#define F_IN    1024
#define H1_DIM  256
#define NZ_DIM  64

// ---------------- scratch ----------------------------------------------------
__device__ float g_support1[N_NODES * H1_DIM];
__device__ float g_hidden1 [N_NODES * H1_DIM];   // rounded-to-tf32 values
__device__ float g_support2[N_NODES * NZ_DIM];
__device__ float g_w1t[H1_DIM * F_IN];           // W1^T, tf32-rna rounded
__device__ float g_w2t[NZ_DIM * H1_DIM];         // W2^T, tf32-rna rounded
__device__ float g_zr [N_NODES * NZ_DIM];        // z, tf32-rna rounded
__device__ int   g_off   [N_NODES + 1];
__device__ int   g_cursor[N_NODES];
__device__ int2  g_srcw  [E_EDGES];

// ---------------- helpers -----------------------------------------------------
__device__ __forceinline__ float tf32rna(float x) {
    uint32_t u;
    asm("cvt.rna.tf32.f32 %0, %1;" : "=r"(u) : "f"(x));
    return __uint_as_float(u);
}
__device__ __forceinline__ uint32_t f2tf32(float x) {
    uint32_t u;
    asm("cvt.rna.tf32.f32 %0, %1;" : "=r"(u) : "f"(x));
    return u;
}
__device__ __forceinline__ void cp16(uint32_t s, const void* g) {
    asm volatile("cp.async.cg.shared.global [%0], [%1], 16;\n" ::"r"(s), "l"(g));
}
__device__ __forceinline__ void cp_commit() {
    asm volatile("cp.async.commit_group;\n");
}
template <int N>
__device__ __forceinline__ void cp_wait() {
    asm volatile("cp.async.wait_group %0;\n" ::"n"(N));
}
__device__ __forceinline__ void mma_tf32(float (&d)[4], const uint32_t (&a)[4],
                                         const uint32_t (&b)[2]) {
    asm volatile(
        "mma.sync.aligned.m16n8k8.row.col.f32.tf32.tf32.f32 "
        "{%0,%1,%2,%3}, {%4,%5,%6,%7}, {%8,%9}, {%0,%1,%2,%3};"
        : "+f"(d[0]), "+f"(d[1]), "+f"(d[2]), "+f"(d[3])
        : "r"(a[0]), "r"(a[1]), "r"(a[2]), "r"(a[3]), "r"(b[0]), "r"(b[1]));
}

// ---------------- CSR build ----------------------------------------------------
__global__ void k_zero_counts() {
    int i = blockIdx.x * blockDim.x + threadIdx.x;
    ((int4*)g_cursor)[i] = make_int4(0, 0, 0, 0);
}
__global__ void k_hist(const int* __restrict__ ei) {
    int e = blockIdx.x * blockDim.x + threadIdx.x;
    if (e < E_EDGES) atomicAdd(&g_cursor[ei[E_EDGES + e]], 1);
}
__global__ void k_scan() {
    __shared__ int part[256];
    const int t = threadIdx.x;
    const int base = t * (N_NODES / 256);
    int s = 0;
#pragma unroll
    for (int j = 0; j < N_NODES / 256; j++) s += g_cursor[base + j];
    part[t] = s;
    __syncthreads();
    for (int off = 1; off < 256; off <<= 1) {
        int v = (t >= off) ? part[t - off] : 0;
        __syncthreads();
        part[t] += v;
        __syncthreads();
    }
    int run = part[t] - s;
#pragma unroll
    for (int j = 0; j < N_NODES / 256; j++) {
        int idx = base + j;
        int c = g_cursor[idx];
        g_off[idx] = run;
        g_cursor[idx] = run;
        run += c;
    }
    if (t == 255) g_off[N_NODES] = run;
}
__global__ void k_scatter(const int* __restrict__ ei, const float* __restrict__ ew) {
    int e = blockIdx.x * blockDim.x + threadIdx.x;
    if (e < E_EDGES) {
        int d = ei[E_EDGES + e];
        int p = atomicAdd(&g_cursor[d], 1);
        g_srcw[p] = make_int2(ei[e], __float_as_int(ew[e]));
    }
}

// ---------------- weight transpose + rna rounding -------------------------------
__global__ void k_transpose_rna(const float* __restrict__ in, float* __restrict__ out,
                                int R, int C) {
    __shared__ float tile[32][33];
    const int bx = blockIdx.x * 32;
    const int by = blockIdx.y * 32;
    const int x = threadIdx.x, y0 = threadIdx.y;
#pragma unroll
    for (int j = y0; j < 32; j += 8)
        tile[j][x] = in[(size_t)(by + j) * C + bx + x];
    __syncthreads();
#pragma unroll
    for (int j = y0; j < 32; j += 8)
        out[(size_t)(bx + j) * R + by + x] = tf32rna(tile[x][j]);
}

// ---------------- SpMM + ReLU (smem-staged edges, MLP=8) ----------------------
__global__ void __launch_bounds__(256) k_spmm_relu_256(
    const float* __restrict__ in, float* __restrict__ out) {
    __shared__ int2 se[256];
    const int row = blockIdx.x;
    const int t   = threadIdx.x;
    const int beg = g_off[row], end = g_off[row + 1];
    float acc = 0.f;
    for (int cs = beg; cs < end; cs += 256) {
        int m = min(256, end - cs);
        __syncthreads();
        if (t < m) se[t] = g_srcw[cs + t];
        __syncthreads();
        int j = 0;
        for (; j + 8 <= m; j += 8) {
            float r[8];
            int2  v[8];
#pragma unroll
            for (int u = 0; u < 8; u++) v[u] = se[j + u];
#pragma unroll
            for (int u = 0; u < 8; u++)
                r[u] = __ldg(&in[(size_t)v[u].x * H1_DIM + t]);
#pragma unroll
            for (int u = 0; u < 8; u++)
                acc += __int_as_float(v[u].y) * r[u];
        }
        for (; j < m; j++) {
            int2 v = se[j];
            acc += __int_as_float(v.y) * __ldg(&in[(size_t)v.x * H1_DIM + t]);
        }
    }
    // h1 feeds only gemm2 -> store pre-rounded to tf32 (rna)
    out[(size_t)row * H1_DIM + t] = tf32rna(fmaxf(acc, 0.f));
}

__global__ void __launch_bounds__(256) k_spmm_relu_64(
    const float* __restrict__ in, float* __restrict__ out,
    float* __restrict__ outr) {
    __shared__ int2 se[4][64];
    __shared__ int sdeg[4];
    const int t    = threadIdx.x;
    const int sub  = t >> 6;
    const int lane = t & 63;
    const int row  = blockIdx.x * 4 + sub;
    const int beg  = g_off[row];
    if (t < 4) sdeg[t] = g_off[blockIdx.x * 4 + t + 1] - g_off[blockIdx.x * 4 + t];
    __syncthreads();
    const int deg  = sdeg[sub];
    const int nch  = (max(max(sdeg[0], sdeg[1]), max(sdeg[2], sdeg[3])) + 63) >> 6;
    float acc = 0.f;
    for (int ch = 0; ch < nch; ch++) {
        int m = min(64, deg - ch * 64);
        __syncthreads();
        if (lane < m) se[sub][lane] = g_srcw[beg + ch * 64 + lane];
        __syncthreads();
        int j = 0;
        for (; j + 8 <= m; j += 8) {
            float r[8];
            int2  v[8];
#pragma unroll
            for (int u = 0; u < 8; u++) v[u] = se[sub][j + u];
#pragma unroll
            for (int u = 0; u < 8; u++)
                r[u] = __ldg(&in[(size_t)v[u].x * NZ_DIM + lane]);
#pragma unroll
            for (int u = 0; u < 8; u++)
                acc += __int_as_float(v[u].y) * r[u];
        }
        for (; j < m; j++) {
            int2 v = se[sub][j];
            acc += __int_as_float(v.y) * __ldg(&in[(size_t)v.x * NZ_DIM + lane]);
        }
    }
    float rv = fmaxf(acc, 0.f);
    out [(size_t)row * NZ_DIM + lane] = rv;          // exact z (output)
    outr[(size_t)row * NZ_DIM + lane] = tf32rna(rv); // rounded copy for zzt
}

// ---------------- TF32 mma.sync GEMM, 32x64 warp tiles --------------------------
// C[M,Nc] = A[M,K] @ Bt[Nc,K]^T.  Bt pre-rounded to tf32; A cvt'd iff ACVT.
// Warps 4x2: wr=warp>>1 rows (WM=32), wc=warp&1 cols (WN=BN/2). MI=2.
template <int BN, bool ACVT>
__global__ void __launch_bounds__(256, 2)
k_gemm_s(const float* __restrict__ A, const float* __restrict__ Bt,
         float* __restrict__ C, int Nc, int K) {
    constexpr int BM = 128, BK = 32, P = 36;
    constexpr int WN = BN / 2, NI = WN / 8;
    constexpr int ASZ = BM * P, BSZ = BN * P;
    constexpr int BCH = BN * BK / (4 * 256);

    extern __shared__ float sm[];
    float* sA0 = sm;
    float* sB0 = sm + 2 * ASZ;
    const uint32_t smem_u32 = (uint32_t)__cvta_generic_to_shared(sm);

    const int tid  = threadIdx.x;
    const int warp = tid >> 5, lane = tid & 31;
    const int wr = warp >> 1, wc = warp & 1;
    const int bm0 = blockIdx.y * BM, bn0 = blockIdx.x * BN;
    const int g = lane >> 2, c = lane & 3;

    float acc[2][NI][4];
#pragma unroll
    for (int mi = 0; mi < 2; mi++)
#pragma unroll
        for (int ni = 0; ni < NI; ni++)
#pragma unroll
            for (int j = 0; j < 4; j++) acc[mi][ni][j] = 0.f;

    const int NT = K / BK;

    auto load_tiles = [&](int kt, int st) {
        const float* Ag = A + (size_t)bm0 * K + kt * BK;
        uint32_t abase = smem_u32 + (uint32_t)(st * ASZ) * 4u;
#pragma unroll
        for (int i = 0; i < 4; i++) {
            int v = tid + i * 256;
            int r = v >> 3, col = (v & 7) * 4;
            cp16(abase + (uint32_t)(r * P + col) * 4u, Ag + (size_t)r * K + col);
        }
        const float* Bg = Bt + (size_t)bn0 * K + kt * BK;
        uint32_t bbase = smem_u32 + (uint32_t)(2 * ASZ + st * BSZ) * 4u;
#pragma unroll
        for (int i = 0; i < BCH; i++) {
            int v = tid + i * 256;
            int r = v >> 3, col = (v & 7) * 4;
            cp16(bbase + (uint32_t)(r * P + col) * 4u, Bg + (size_t)r * K + col);
        }
    };

    load_tiles(0, 0);
    cp_commit();

    for (int kt = 0; kt < NT; kt++) {
        if (kt + 1 < NT) {
            load_tiles(kt + 1, (kt + 1) & 1);
            cp_commit();
            cp_wait<1>();
        } else {
            cp_wait<0>();
        }
        __syncthreads();

        const float* sA = sA0 + (kt & 1) * ASZ;
        const float* sB = sB0 + (kt & 1) * BSZ;
#pragma unroll
        for (int ks = 0; ks < BK / 8; ks++) {
            const int k0 = ks * 8;
            uint32_t af[2][4];
            uint32_t bf[NI][2];
#pragma unroll
            for (int mi = 0; mi < 2; mi++) {
                int r = wr * 32 + mi * 16 + g;
                if (ACVT) {
                    af[mi][0] = f2tf32(sA[r * P + k0 + c]);
                    af[mi][1] = f2tf32(sA[(r + 8) * P + k0 + c]);
                    af[mi][2] = f2tf32(sA[r * P + k0 + 4 + c]);
                    af[mi][3] = f2tf32(sA[(r + 8) * P + k0 + 4 + c]);
                } else {
                    af[mi][0] = __float_as_uint(sA[r * P + k0 + c]);
                    af[mi][1] = __float_as_uint(sA[(r + 8) * P + k0 + c]);
                    af[mi][2] = __float_as_uint(sA[r * P + k0 + 4 + c]);
                    af[mi][3] = __float_as_uint(sA[(r + 8) * P + k0 + 4 + c]);
                }
            }
#pragma unroll
            for (int ni = 0; ni < NI; ni++) {
                int n = wc * WN + ni * 8 + g;
                bf[ni][0] = __float_as_uint(sB[n * P + k0 + c]);
                bf[ni][1] = __float_as_uint(sB[n * P + k0 + 4 + c]);
            }
#pragma unroll
            for (int mi = 0; mi < 2; mi++)
#pragma unroll
                for (int ni = 0; ni < NI; ni++)
                    mma_tf32(acc[mi][ni], af[mi], bf[ni]);
        }
        __syncthreads();
    }

#pragma unroll
    for (int mi = 0; mi < 2; mi++)
#pragma unroll
        for (int ni = 0; ni < NI; ni++) {
            int r  = bm0 + wr * 32 + mi * 16 + g;
            int cc = bn0 + wc * WN + ni * 8 + c * 2;
            *reinterpret_cast<float2*>(&C[(size_t)r * Nc + cc]) =
                make_float2(acc[mi][ni][0], acc[mi][ni][1]);
            *reinterpret_cast<float2*>(&C[(size_t)(r + 8) * Nc + cc]) =
                make_float2(acc[mi][ni][2], acc[mi][ni][3]);
        }
}

// ---------------- z @ z^T, symmetric (input pre-rounded: no cvt) ---------------
__global__ void __launch_bounds__(256, 2)
k_zzt(const float* __restrict__ Z, float* __restrict__ C) {
    constexpr int P  = 68;
    constexpr int TP = 132;
    extern __shared__ float sm[];
    float* sA = sm;
    float* sB = sm + 128 * P;
    const uint32_t smem_u32 = (uint32_t)__cvta_generic_to_shared(sm);

    const int tid  = threadIdx.x;
    const int warp = tid >> 5, lane = tid & 31;
    const int wm = warp & 1, wn = warp >> 1;
    const int g = lane >> 2, c = lane & 3;

    int t = blockIdx.x;
    int bi = (int)((sqrtf(8.f * (float)t + 1.f) - 1.f) * 0.5f);
    while ((bi + 1) * (bi + 2) / 2 <= t) bi++;
    while (bi * (bi + 1) / 2 > t) bi--;
    int bj = t - bi * (bi + 1) / 2;
    const int bm0 = bi * 128;
    const int bn0 = bj * 128;

#pragma unroll
    for (int i = 0; i < 8; i++) {
        int v = tid + i * 256;
        int r = v / 16, col = (v % 16) * 4;
        cp16(smem_u32 + (uint32_t)(r * P + col) * 4u,
             Z + (size_t)(bm0 + r) * NZ_DIM + col);
    }
#pragma unroll
    for (int i = 0; i < 8; i++) {
        int v = tid + i * 256;
        int r = v / 16, col = (v % 16) * 4;
        cp16(smem_u32 + (uint32_t)(128 * P + r * P + col) * 4u,
             Z + (size_t)(bn0 + r) * NZ_DIM + col);
    }
    cp_commit();
    cp_wait<0>();
    __syncthreads();

    float acc[4][4][4];
#pragma unroll
    for (int mi = 0; mi < 4; mi++)
#pragma unroll
        for (int ni = 0; ni < 4; ni++)
#pragma unroll
            for (int j = 0; j < 4; j++) acc[mi][ni][j] = 0.f;

#pragma unroll
    for (int ks = 0; ks < 8; ks++) {
        const int k0 = ks * 8;
        uint32_t af[4][4];
        uint32_t bf[4][2];
#pragma unroll
        for (int mi = 0; mi < 4; mi++) {
            int r = wm * 64 + mi * 16 + g;
            af[mi][0] = __float_as_uint(sA[r * P + k0 + c]);
            af[mi][1] = __float_as_uint(sA[(r + 8) * P + k0 + c]);
            af[mi][2] = __float_as_uint(sA[r * P + k0 + 4 + c]);
            af[mi][3] = __float_as_uint(sA[(r + 8) * P + k0 + 4 + c]);
        }
#pragma unroll
        for (int ni = 0; ni < 4; ni++) {
            int n = wn * 32 + ni * 8 + g;
            bf[ni][0] = __float_as_uint(sB[n * P + k0 + c]);
            bf[ni][1] = __float_as_uint(sB[n * P + k0 + 4 + c]);
        }
#pragma unroll
        for (int mi = 0; mi < 4; mi++)
#pragma unroll
            for (int ni = 0; ni < 4; ni++)
                mma_tf32(acc[mi][ni], af[mi], bf[ni]);
    }

#pragma unroll
    for (int mi = 0; mi < 4; mi++)
#pragma unroll
        for (int ni = 0; ni < 4; ni++) {
            int r  = bm0 + wm * 64 + mi * 16 + g;
            int cc = bn0 + wn * 32 + ni * 8 + c * 2;
            *reinterpret_cast<float2*>(&C[(size_t)r * N_NODES + cc]) =
                make_float2(acc[mi][ni][0], acc[mi][ni][1]);
            *reinterpret_cast<float2*>(&C[(size_t)(r + 8) * N_NODES + cc]) =
                make_float2(acc[mi][ni][2], acc[mi][ni][3]);
        }

    if (bi == bj) return;

    __syncthreads();
#pragma unroll
    for (int mi = 0; mi < 4; mi++)
#pragma unroll
        for (int ni = 0; ni < 4; ni++) {
            int r  = wm * 64 + mi * 16 + g;
            int cc = wn * 32 + ni * 8 + c * 2;
            sm[(size_t)cc * TP + r]           = acc[mi][ni][0];
            sm[(size_t)(cc + 1) * TP + r]     = acc[mi][ni][1];
            sm[(size_t)cc * TP + r + 8]       = acc[mi][ni][2];
            sm[(size_t)(cc + 1) * TP + r + 8] = acc[mi][ni][3];
        }
    __syncthreads();
#pragma unroll
    for (int i = 0; i < 16; i++) {
        int v = tid + i * 256;
        int j = v >> 5, col = (v & 31) * 4;
        float4 q = *reinterpret_cast<const float4*>(&sm[(size_t)j * TP + col]);
        *reinterpret_cast<float4*>(&C[(size_t)(bn0 + j) * N_NODES + bm0 + col]) = q;
    }
}

// ---------------- launch --------------------------------------------------------
extern "C" void kernel_launch(void* const* d_in, const int* in_sizes, int n_in,
                              void* d_out, int out_size) {
    const float* x  = (const float*)d_in[0];
    const float* W1 = (const float*)d_in[1];
    const float* W2 = (const float*)d_in[2];
    const float* ew = (const float*)d_in[3];
    const int*   ei = (const int*)d_in[4];

    float* out  = (float*)d_out;
    float* abar = out;
    float* z    = out + (size_t)N_NODES * N_NODES;

    float *s1, *h1, *s2, *w1t, *w2t, *zr;
    cudaGetSymbolAddress((void**)&s1,  g_support1);
    cudaGetSymbolAddress((void**)&h1,  g_hidden1);
    cudaGetSymbolAddress((void**)&s2,  g_support2);
    cudaGetSymbolAddress((void**)&w1t, g_w1t);
    cudaGetSymbolAddress((void**)&w2t, g_w2t);
    cudaGetSymbolAddress((void**)&zr,  g_zr);

    constexpr int SM_G1  = 2 * (128 * 36 + 128 * 36) * 4;  // 73728
    constexpr int SM_G2  = 2 * (128 * 36 + 64 * 36) * 4;   // 55296
    constexpr int SM_ZZT = 2 * 128 * 68 * 4;               // 69632

    cudaFuncSetAttribute(k_gemm_s<128, true>,
                         cudaFuncAttributeMaxDynamicSharedMemorySize, SM_G1);
    cudaFuncSetAttribute(k_gemm_s<64, false>,
                         cudaFuncAttributeMaxDynamicSharedMemorySize, SM_G2);
    cudaFuncSetAttribute(k_zzt,
                         cudaFuncAttributeMaxDynamicSharedMemorySize, SM_ZZT);

    // order: gemm1 is the 4th launch (ncu capture slot)
    k_zero_counts<<<N_NODES / 1024, 256>>>();                         // 1
    k_transpose_rna<<<dim3(H1_DIM / 32, F_IN / 32), dim3(32, 8)>>>(   // 2
        W1, w1t, F_IN, H1_DIM);
    k_transpose_rna<<<dim3(NZ_DIM / 32, H1_DIM / 32), dim3(32, 8)>>>( // 3
        W2, w2t, H1_DIM, NZ_DIM);
    k_gemm_s<128, true><<<dim3(H1_DIM / 128, N_NODES / 128), 256, SM_G1>>>( // 4
        x, w1t, s1, H1_DIM, F_IN);
    k_hist<<<E_EDGES / 256, 256>>>(ei);                               // 5
    k_scan<<<1, 256>>>();                                             // 6
    k_scatter<<<E_EDGES / 256, 256>>>(ei, ew);                        // 7
    k_spmm_relu_256<<<N_NODES, 256>>>(s1, h1);                        // 8
    k_gemm_s<64, false><<<dim3(1, N_NODES / 128), 256, SM_G2>>>(      // 9
        h1, w2t, s2, NZ_DIM, H1_DIM);
    k_spmm_relu_64<<<N_NODES / 4, 256>>>(s2, z, zr);                  // 10
    const int ntile = N_NODES / 128;
    k_zzt<<<ntile * (ntile + 1) / 2, 256, SM_ZZT>>>(zr, abar);        // 11
}

// round 7
// speedup vs baseline: 1.1680x; 1.1258x over previous
#include <cuda_runtime.h>
#include <cstdint>
#include <cstddef>

#define N_NODES 16384
#define E_EDGES 262144
#define F_IN    1024
#define H1_DIM  256
#define NZ_DIM  64

// ---------------- scratch ----------------------------------------------------
__device__ float g_support1[N_NODES * H1_DIM];
__device__ float g_hidden1 [N_NODES * H1_DIM];   // rounded-to-tf32 values
__device__ float g_support2[N_NODES * NZ_DIM];
__device__ float g_w1t[H1_DIM * F_IN];           // W1^T, tf32-rna rounded
__device__ float g_w2t[NZ_DIM * H1_DIM];         // W2^T, tf32-rna rounded
__device__ float g_zr [N_NODES * NZ_DIM];        // z, tf32-rna rounded
__device__ int   g_off   [N_NODES + 1];
__device__ int   g_cursor[N_NODES];
__device__ int2  g_srcw  [E_EDGES];

// ---------------- helpers -----------------------------------------------------
__device__ __forceinline__ float tf32rna(float x) {
    uint32_t u;
    asm("cvt.rna.tf32.f32 %0, %1;" : "=r"(u) : "f"(x));
    return __uint_as_float(u);
}
__device__ __forceinline__ uint32_t f2tf32(float x) {
    uint32_t u;
    asm("cvt.rna.tf32.f32 %0, %1;" : "=r"(u) : "f"(x));
    return u;
}
__device__ __forceinline__ void cp16(uint32_t s, const void* g) {
    asm volatile("cp.async.cg.shared.global [%0], [%1], 16;\n" ::"r"(s), "l"(g));
}
__device__ __forceinline__ void cp_commit() {
    asm volatile("cp.async.commit_group;\n");
}
template <int N>
__device__ __forceinline__ void cp_wait() {
    asm volatile("cp.async.wait_group %0;\n" ::"n"(N));
}
__device__ __forceinline__ void mma_tf32(float (&d)[4], const uint32_t (&a)[4],
                                         const uint32_t (&b)[2]) {
    asm volatile(
        "mma.sync.aligned.m16n8k8.row.col.f32.tf32.tf32.f32 "
        "{%0,%1,%2,%3}, {%4,%5,%6,%7}, {%8,%9}, {%0,%1,%2,%3};"
        : "+f"(d[0]), "+f"(d[1]), "+f"(d[2]), "+f"(d[3])
        : "r"(a[0]), "r"(a[1]), "r"(a[2]), "r"(a[3]), "r"(b[0]), "r"(b[1]));
}

// ---------------- CSR build ----------------------------------------------------
__global__ void k_zero_counts() {
    int i = blockIdx.x * blockDim.x + threadIdx.x;
    ((int4*)g_cursor)[i] = make_int4(0, 0, 0, 0);
}
__global__ void k_hist(const int* __restrict__ ei) {
    int e = blockIdx.x * blockDim.x + threadIdx.x;
    if (e < E_EDGES) atomicAdd(&g_cursor[ei[E_EDGES + e]], 1);
}
__global__ void k_scan() {
    __shared__ int part[256];
    const int t = threadIdx.x;
    const int base = t * (N_NODES / 256);
    int s = 0;
#pragma unroll
    for (int j = 0; j < N_NODES / 256; j++) s += g_cursor[base + j];
    part[t] = s;
    __syncthreads();
    for (int off = 1; off < 256; off <<= 1) {
        int v = (t >= off) ? part[t - off] : 0;
        __syncthreads();
        part[t] += v;
        __syncthreads();
    }
    int run = part[t] - s;
#pragma unroll
    for (int j = 0; j < N_NODES / 256; j++) {
        int idx = base + j;
        int c = g_cursor[idx];
        g_off[idx] = run;
        g_cursor[idx] = run;
        run += c;
    }
    if (t == 255) g_off[N_NODES] = run;
}
__global__ void k_scatter(const int* __restrict__ ei, const float* __restrict__ ew) {
    int e = blockIdx.x * blockDim.x + threadIdx.x;
    if (e < E_EDGES) {
        int d = ei[E_EDGES + e];
        int p = atomicAdd(&g_cursor[d], 1);
        g_srcw[p] = make_int2(ei[e], __float_as_int(ew[e]));
    }
}

// ---------------- weight transpose + rna rounding -------------------------------
__global__ void k_transpose_rna(const float* __restrict__ in, float* __restrict__ out,
                                int R, int C) {
    __shared__ float tile[32][33];
    const int bx = blockIdx.x * 32;
    const int by = blockIdx.y * 32;
    const int x = threadIdx.x, y0 = threadIdx.y;
#pragma unroll
    for (int j = y0; j < 32; j += 8)
        tile[j][x] = in[(size_t)(by + j) * C + bx + x];
    __syncthreads();
#pragma unroll
    for (int j = y0; j < 32; j += 8)
        out[(size_t)(bx + j) * R + by + x] = tf32rna(tile[x][j]);
}

// ---------------- SpMM + ReLU (smem-staged edges, MLP=8) ----------------------
__global__ void __launch_bounds__(256) k_spmm_relu_256(
    const float* __restrict__ in, float* __restrict__ out) {
    __shared__ int2 se[256];
    const int row = blockIdx.x;
    const int t   = threadIdx.x;
    const int beg = g_off[row], end = g_off[row + 1];
    float acc = 0.f;
    for (int cs = beg; cs < end; cs += 256) {
        int m = min(256, end - cs);
        __syncthreads();
        if (t < m) se[t] = g_srcw[cs + t];
        __syncthreads();
        int j = 0;
        for (; j + 8 <= m; j += 8) {
            float r[8];
            int2  v[8];
#pragma unroll
            for (int u = 0; u < 8; u++) v[u] = se[j + u];
#pragma unroll
            for (int u = 0; u < 8; u++)
                r[u] = __ldg(&in[(size_t)v[u].x * H1_DIM + t]);
#pragma unroll
            for (int u = 0; u < 8; u++)
                acc += __int_as_float(v[u].y) * r[u];
        }
        for (; j < m; j++) {
            int2 v = se[j];
            acc += __int_as_float(v.y) * __ldg(&in[(size_t)v.x * H1_DIM + t]);
        }
    }
    out[(size_t)row * H1_DIM + t] = tf32rna(fmaxf(acc, 0.f));
}

__global__ void __launch_bounds__(256) k_spmm_relu_64(
    const float* __restrict__ in, float* __restrict__ out,
    float* __restrict__ outr) {
    __shared__ int2 se[4][64];
    __shared__ int sdeg[4];
    const int t    = threadIdx.x;
    const int sub  = t >> 6;
    const int lane = t & 63;
    const int row  = blockIdx.x * 4 + sub;
    const int beg  = g_off[row];
    if (t < 4) sdeg[t] = g_off[blockIdx.x * 4 + t + 1] - g_off[blockIdx.x * 4 + t];
    __syncthreads();
    const int deg  = sdeg[sub];
    const int nch  = (max(max(sdeg[0], sdeg[1]), max(sdeg[2], sdeg[3])) + 63) >> 6;
    float acc = 0.f;
    for (int ch = 0; ch < nch; ch++) {
        int m = min(64, deg - ch * 64);
        __syncthreads();
        if (lane < m) se[sub][lane] = g_srcw[beg + ch * 64 + lane];
        __syncthreads();
        int j = 0;
        for (; j + 8 <= m; j += 8) {
            float r[8];
            int2  v[8];
#pragma unroll
            for (int u = 0; u < 8; u++) v[u] = se[sub][j + u];
#pragma unroll
            for (int u = 0; u < 8; u++)
                r[u] = __ldg(&in[(size_t)v[u].x * NZ_DIM + lane]);
#pragma unroll
            for (int u = 0; u < 8; u++)
                acc += __int_as_float(v[u].y) * r[u];
        }
        for (; j < m; j++) {
            int2 v = se[sub][j];
            acc += __int_as_float(v.y) * __ldg(&in[(size_t)v.x * NZ_DIM + lane]);
        }
    }
    float rv = fmaxf(acc, 0.f);
    out [(size_t)row * NZ_DIM + lane] = rv;
    outr[(size_t)row * NZ_DIM + lane] = tf32rna(rv);
}

// ---------------- big single-wave GEMM: 512 thr, BM=256, BN=128 -----------------
// C[M,Nc] = A[M,K] @ Bt[Nc,K]^T.  Warps 8x2 (WM=32, WN=64). A cvt'd (raw fp32).
__global__ void __launch_bounds__(512, 1)
k_gemm_big(const float* __restrict__ A, const float* __restrict__ Bt,
           float* __restrict__ C, int Nc, int K) {
    constexpr int BM = 256, BN = 128, BK = 32, P = 36;
    constexpr int ASZ = BM * P, BSZ = BN * P;

    extern __shared__ float sm[];
    float* sA0 = sm;
    float* sB0 = sm + 2 * ASZ;
    const uint32_t smem_u32 = (uint32_t)__cvta_generic_to_shared(sm);

    const int tid  = threadIdx.x;
    const int warp = tid >> 5, lane = tid & 31;
    const int wr = warp >> 1, wc = warp & 1;
    const int bm0 = blockIdx.y * BM, bn0 = blockIdx.x * BN;
    const int g = lane >> 2, c = lane & 3;

    float acc[2][8][4];
#pragma unroll
    for (int mi = 0; mi < 2; mi++)
#pragma unroll
        for (int ni = 0; ni < 8; ni++)
#pragma unroll
            for (int j = 0; j < 4; j++) acc[mi][ni][j] = 0.f;

    const int NT = K / BK;

    auto load_tiles = [&](int kt, int st) {
        const float* Ag = A + (size_t)bm0 * K + kt * BK;
        uint32_t abase = smem_u32 + (uint32_t)(st * ASZ) * 4u;
#pragma unroll
        for (int i = 0; i < 4; i++) {           // 256x32 f32 = 2048 vec4
            int v = tid + i * 512;
            int r = v >> 3, col = (v & 7) * 4;
            cp16(abase + (uint32_t)(r * P + col) * 4u, Ag + (size_t)r * K + col);
        }
        const float* Bg = Bt + (size_t)bn0 * K + kt * BK;
        uint32_t bbase = smem_u32 + (uint32_t)(2 * ASZ + st * BSZ) * 4u;
#pragma unroll
        for (int i = 0; i < 2; i++) {           // 128x32 f32 = 1024 vec4
            int v = tid + i * 512;
            int r = v >> 3, col = (v & 7) * 4;
            cp16(bbase + (uint32_t)(r * P + col) * 4u, Bg + (size_t)r * K + col);
        }
    };

    load_tiles(0, 0);
    cp_commit();

    for (int kt = 0; kt < NT; kt++) {
        if (kt + 1 < NT) {
            load_tiles(kt + 1, (kt + 1) & 1);
            cp_commit();
            cp_wait<1>();
        } else {
            cp_wait<0>();
        }
        __syncthreads();

        const float* sA = sA0 + (kt & 1) * ASZ;
        const float* sB = sB0 + (kt & 1) * BSZ;
#pragma unroll
        for (int ks = 0; ks < BK / 8; ks++) {
            const int k0 = ks * 8;
            uint32_t af[2][4];
            uint32_t bf[8][2];
#pragma unroll
            for (int mi = 0; mi < 2; mi++) {
                int r = wr * 32 + mi * 16 + g;
                af[mi][0] = f2tf32(sA[r * P + k0 + c]);
                af[mi][1] = f2tf32(sA[(r + 8) * P + k0 + c]);
                af[mi][2] = f2tf32(sA[r * P + k0 + 4 + c]);
                af[mi][3] = f2tf32(sA[(r + 8) * P + k0 + 4 + c]);
            }
#pragma unroll
            for (int ni = 0; ni < 8; ni++) {
                int n = wc * 64 + ni * 8 + g;
                bf[ni][0] = __float_as_uint(sB[n * P + k0 + c]);
                bf[ni][1] = __float_as_uint(sB[n * P + k0 + 4 + c]);
            }
#pragma unroll
            for (int mi = 0; mi < 2; mi++)
#pragma unroll
                for (int ni = 0; ni < 8; ni++)
                    mma_tf32(acc[mi][ni], af[mi], bf[ni]);
        }
        __syncthreads();
    }

#pragma unroll
    for (int mi = 0; mi < 2; mi++)
#pragma unroll
        for (int ni = 0; ni < 8; ni++) {
            int r  = bm0 + wr * 32 + mi * 16 + g;
            int cc = bn0 + wc * 64 + ni * 8 + c * 2;
            *reinterpret_cast<float2*>(&C[(size_t)r * Nc + cc]) =
                make_float2(acc[mi][ni][0], acc[mi][ni][1]);
            *reinterpret_cast<float2*>(&C[(size_t)(r + 8) * Nc + cc]) =
                make_float2(acc[mi][ni][2], acc[mi][ni][3]);
        }
}

// ---------------- small GEMM (gemm2): 256 thr, BN=64, B pre-rounded ------------
template <int BN, bool ACVT>
__global__ void __launch_bounds__(256, 2)
k_gemm_s(const float* __restrict__ A, const float* __restrict__ Bt,
         float* __restrict__ C, int Nc, int K) {
    constexpr int BM = 128, BK = 32, P = 36;
    constexpr int WN = BN / 2, NI = WN / 8;
    constexpr int ASZ = BM * P, BSZ = BN * P;
    constexpr int BCH = BN * BK / (4 * 256);

    extern __shared__ float sm[];
    float* sA0 = sm;
    float* sB0 = sm + 2 * ASZ;
    const uint32_t smem_u32 = (uint32_t)__cvta_generic_to_shared(sm);

    const int tid  = threadIdx.x;
    const int warp = tid >> 5, lane = tid & 31;
    const int wr = warp >> 1, wc = warp & 1;
    const int bm0 = blockIdx.y * BM, bn0 = blockIdx.x * BN;
    const int g = lane >> 2, c = lane & 3;

    float acc[2][NI][4];
#pragma unroll
    for (int mi = 0; mi < 2; mi++)
#pragma unroll
        for (int ni = 0; ni < NI; ni++)
#pragma unroll
            for (int j = 0; j < 4; j++) acc[mi][ni][j] = 0.f;

    const int NT = K / BK;

    auto load_tiles = [&](int kt, int st) {
        const float* Ag = A + (size_t)bm0 * K + kt * BK;
        uint32_t abase = smem_u32 + (uint32_t)(st * ASZ) * 4u;
#pragma unroll
        for (int i = 0; i < 4; i++) {
            int v = tid + i * 256;
            int r = v >> 3, col = (v & 7) * 4;
            cp16(abase + (uint32_t)(r * P + col) * 4u, Ag + (size_t)r * K + col);
        }
        const float* Bg = Bt + (size_t)bn0 * K + kt * BK;
        uint32_t bbase = smem_u32 + (uint32_t)(2 * ASZ + st * BSZ) * 4u;
#pragma unroll
        for (int i = 0; i < BCH; i++) {
            int v = tid + i * 256;
            int r = v >> 3, col = (v & 7) * 4;
            cp16(bbase + (uint32_t)(r * P + col) * 4u, Bg + (size_t)r * K + col);
        }
    };

    load_tiles(0, 0);
    cp_commit();

    for (int kt = 0; kt < NT; kt++) {
        if (kt + 1 < NT) {
            load_tiles(kt + 1, (kt + 1) & 1);
            cp_commit();
            cp_wait<1>();
        } else {
            cp_wait<0>();
        }
        __syncthreads();

        const float* sA = sA0 + (kt & 1) * ASZ;
        const float* sB = sB0 + (kt & 1) * BSZ;
#pragma unroll
        for (int ks = 0; ks < BK / 8; ks++) {
            const int k0 = ks * 8;
            uint32_t af[2][4];
            uint32_t bf[NI][2];
#pragma unroll
            for (int mi = 0; mi < 2; mi++) {
                int r = wr * 32 + mi * 16 + g;
                if (ACVT) {
                    af[mi][0] = f2tf32(sA[r * P + k0 + c]);
                    af[mi][1] = f2tf32(sA[(r + 8) * P + k0 + c]);
                    af[mi][2] = f2tf32(sA[r * P + k0 + 4 + c]);
                    af[mi][3] = f2tf32(sA[(r + 8) * P + k0 + 4 + c]);
                } else {
                    af[mi][0] = __float_as_uint(sA[r * P + k0 + c]);
                    af[mi][1] = __float_as_uint(sA[(r + 8) * P + k0 + c]);
                    af[mi][2] = __float_as_uint(sA[r * P + k0 + 4 + c]);
                    af[mi][3] = __float_as_uint(sA[(r + 8) * P + k0 + 4 + c]);
                }
            }
#pragma unroll
            for (int ni = 0; ni < NI; ni++) {
                int n = wc * WN + ni * 8 + g;
                bf[ni][0] = __float_as_uint(sB[n * P + k0 + c]);
                bf[ni][1] = __float_as_uint(sB[n * P + k0 + 4 + c]);
            }
#pragma unroll
            for (int mi = 0; mi < 2; mi++)
#pragma unroll
                for (int ni = 0; ni < NI; ni++)
                    mma_tf32(acc[mi][ni], af[mi], bf[ni]);
        }
        __syncthreads();
    }

#pragma unroll
    for (int mi = 0; mi < 2; mi++)
#pragma unroll
        for (int ni = 0; ni < NI; ni++) {
            int r  = bm0 + wr * 32 + mi * 16 + g;
            int cc = bn0 + wc * WN + ni * 8 + c * 2;
            *reinterpret_cast<float2*>(&C[(size_t)r * Nc + cc]) =
                make_float2(acc[mi][ni][0], acc[mi][ni][1]);
            *reinterpret_cast<float2*>(&C[(size_t)(r + 8) * Nc + cc]) =
                make_float2(acc[mi][ni][2], acc[mi][ni][3]);
        }
}

// ---------------- z @ z^T, symmetric (input pre-rounded: no cvt) ---------------
__global__ void __launch_bounds__(256, 2)
k_zzt(const float* __restrict__ Z, float* __restrict__ C) {
    constexpr int P  = 68;
    constexpr int TP = 132;
    extern __shared__ float sm[];
    float* sA = sm;
    float* sB = sm + 128 * P;
    const uint32_t smem_u32 = (uint32_t)__cvta_generic_to_shared(sm);

    const int tid  = threadIdx.x;
    const int warp = tid >> 5, lane = tid & 31;
    const int wm = warp & 1, wn = warp >> 1;
    const int g = lane >> 2, c = lane & 3;

    int t = blockIdx.x;
    int bi = (int)((sqrtf(8.f * (float)t + 1.f) - 1.f) * 0.5f);
    while ((bi + 1) * (bi + 2) / 2 <= t) bi++;
    while (bi * (bi + 1) / 2 > t) bi--;
    int bj = t - bi * (bi + 1) / 2;
    const int bm0 = bi * 128;
    const int bn0 = bj * 128;

#pragma unroll
    for (int i = 0; i < 8; i++) {
        int v = tid + i * 256;
        int r = v / 16, col = (v % 16) * 4;
        cp16(smem_u32 + (uint32_t)(r * P + col) * 4u,
             Z + (size_t)(bm0 + r) * NZ_DIM + col);
    }
#pragma unroll
    for (int i = 0; i < 8; i++) {
        int v = tid + i * 256;
        int r = v / 16, col = (v % 16) * 4;
        cp16(smem_u32 + (uint32_t)(128 * P + r * P + col) * 4u,
             Z + (size_t)(bn0 + r) * NZ_DIM + col);
    }
    cp_commit();
    cp_wait<0>();
    __syncthreads();

    float acc[4][4][4];
#pragma unroll
    for (int mi = 0; mi < 4; mi++)
#pragma unroll
        for (int ni = 0; ni < 4; ni++)
#pragma unroll
            for (int j = 0; j < 4; j++) acc[mi][ni][j] = 0.f;

#pragma unroll
    for (int ks = 0; ks < 8; ks++) {
        const int k0 = ks * 8;
        uint32_t af[4][4];
        uint32_t bf[4][2];
#pragma unroll
        for (int mi = 0; mi < 4; mi++) {
            int r = wm * 64 + mi * 16 + g;
            af[mi][0] = __float_as_uint(sA[r * P + k0 + c]);
            af[mi][1] = __float_as_uint(sA[(r + 8) * P + k0 + c]);
            af[mi][2] = __float_as_uint(sA[r * P + k0 + 4 + c]);
            af[mi][3] = __float_as_uint(sA[(r + 8) * P + k0 + 4 + c]);
        }
#pragma unroll
        for (int ni = 0; ni < 4; ni++) {
            int n = wn * 32 + ni * 8 + g;
            bf[ni][0] = __float_as_uint(sB[n * P + k0 + c]);
            bf[ni][1] = __float_as_uint(sB[n * P + k0 + 4 + c]);
        }
#pragma unroll
        for (int mi = 0; mi < 4; mi++)
#pragma unroll
            for (int ni = 0; ni < 4; ni++)
                mma_tf32(acc[mi][ni], af[mi], bf[ni]);
    }

#pragma unroll
    for (int mi = 0; mi < 4; mi++)
#pragma unroll
        for (int ni = 0; ni < 4; ni++) {
            int r  = bm0 + wm * 64 + mi * 16 + g;
            int cc = bn0 + wn * 32 + ni * 8 + c * 2;
            *reinterpret_cast<float2*>(&C[(size_t)r * N_NODES + cc]) =
                make_float2(acc[mi][ni][0], acc[mi][ni][1]);
            *reinterpret_cast<float2*>(&C[(size_t)(r + 8) * N_NODES + cc]) =
                make_float2(acc[mi][ni][2], acc[mi][ni][3]);
        }

    if (bi == bj) return;

    __syncthreads();
#pragma unroll
    for (int mi = 0; mi < 4; mi++)
#pragma unroll
        for (int ni = 0; ni < 4; ni++) {
            int r  = wm * 64 + mi * 16 + g;
            int cc = wn * 32 + ni * 8 + c * 2;
            sm[(size_t)cc * TP + r]           = acc[mi][ni][0];
            sm[(size_t)(cc + 1) * TP + r]     = acc[mi][ni][1];
            sm[(size_t)cc * TP + r + 8]       = acc[mi][ni][2];
            sm[(size_t)(cc + 1) * TP + r + 8] = acc[mi][ni][3];
        }
    __syncthreads();
#pragma unroll
    for (int i = 0; i < 16; i++) {
        int v = tid + i * 256;
        int j = v >> 5, col = (v & 31) * 4;
        float4 q = *reinterpret_cast<const float4*>(&sm[(size_t)j * TP + col]);
        *reinterpret_cast<float4*>(&C[(size_t)(bn0 + j) * N_NODES + bm0 + col]) = q;
    }
}

// ---------------- stream/event singletons (host objects; created once) --------
struct AuxRes {
    cudaStream_t s2;
    cudaEvent_t  evFork, evJoin;
    AuxRes() {
        cudaStreamCreateWithFlags(&s2, cudaStreamNonBlocking);
        cudaEventCreateWithFlags(&evFork, cudaEventDisableTiming);
        cudaEventCreateWithFlags(&evJoin, cudaEventDisableTiming);
    }
};

// ---------------- launch --------------------------------------------------------
extern "C" void kernel_launch(void* const* d_in, const int* in_sizes, int n_in,
                              void* d_out, int out_size) {
    static AuxRes aux;   // one-time host-side resources (no device memory)

    const float* x  = (const float*)d_in[0];
    const float* W1 = (const float*)d_in[1];
    const float* W2 = (const float*)d_in[2];
    const float* ew = (const float*)d_in[3];
    const int*   ei = (const int*)d_in[4];

    float* out  = (float*)d_out;
    float* abar = out;
    float* z    = out + (size_t)N_NODES * N_NODES;

    float *s1, *h1, *s2buf, *w1t, *w2t, *zr;
    cudaGetSymbolAddress((void**)&s1,  g_support1);
    cudaGetSymbolAddress((void**)&h1,  g_hidden1);
    cudaGetSymbolAddress((void**)&s2buf, g_support2);
    cudaGetSymbolAddress((void**)&w1t, g_w1t);
    cudaGetSymbolAddress((void**)&w2t, g_w2t);
    cudaGetSymbolAddress((void**)&zr,  g_zr);

    constexpr int SM_BIG = 2 * (256 * 36 + 128 * 36) * 4;  // 110592
    constexpr int SM_G2  = 2 * (128 * 36 + 64 * 36) * 4;   // 55296
    constexpr int SM_ZZT = 2 * 128 * 68 * 4;               // 69632

    cudaFuncSetAttribute(k_gemm_big,
                         cudaFuncAttributeMaxDynamicSharedMemorySize, SM_BIG);
    cudaFuncSetAttribute(k_gemm_s<64, false>,
                         cudaFuncAttributeMaxDynamicSharedMemorySize, SM_G2);
    cudaFuncSetAttribute(k_zzt,
                         cudaFuncAttributeMaxDynamicSharedMemorySize, SM_ZZT);

    // fork: CSR chain on aux.s2, GEMM path on default stream
    cudaEventRecord(aux.evFork, 0);
    cudaStreamWaitEvent(aux.s2, aux.evFork, 0);

    // default-stream path (gemm1 is 4th kernel call -> ncu capture slot)
    k_transpose_rna<<<dim3(H1_DIM / 32, F_IN / 32), dim3(32, 8)>>>(   // 1
        W1, w1t, F_IN, H1_DIM);
    k_zero_counts<<<N_NODES / 1024, 256, 0, aux.s2>>>();              // 2 (s2)
    k_transpose_rna<<<dim3(NZ_DIM / 32, H1_DIM / 32), dim3(32, 8)>>>( // 3
        W2, w2t, H1_DIM, NZ_DIM);
    k_gemm_big<<<dim3(H1_DIM / 128, N_NODES / 256), 512, SM_BIG>>>(   // 4
        x, w1t, s1, H1_DIM, F_IN);
    k_hist<<<E_EDGES / 256, 256, 0, aux.s2>>>(ei);                    // 5 (s2)
    k_scan<<<1, 256, 0, aux.s2>>>();                                  // 6 (s2)
    k_scatter<<<E_EDGES / 256, 256, 0, aux.s2>>>(ei, ew);             // 7 (s2)

    // join: spmm1 needs CSR + gemm1
    cudaEventRecord(aux.evJoin, aux.s2);
    cudaStreamWaitEvent(0, aux.evJoin, 0);

    k_spmm_relu_256<<<N_NODES, 256>>>(s1, h1);                        // 8
    k_gemm_s<64, false><<<dim3(1, N_NODES / 128), 256, SM_G2>>>(      // 9
        h1, w2t, s2buf, NZ_DIM, H1_DIM);
    k_spmm_relu_64<<<N_NODES / 4, 256>>>(s2buf, z, zr);               // 10
    const int ntile = N_NODES / 128;
    k_zzt<<<ntile * (ntile + 1) / 2, 256, SM_ZZT>>>(zr, abar);        // 11
}

// round 9
// speedup vs baseline: 1.3330x; 1.1412x over previous
#include <cuda_runtime.h>
#include <cuda_fp16.h>
#include <cstdint>
#include <cstddef>

#define N_NODES 16384
#define E_EDGES 262144
#define F_IN    1024
#define H1_DIM  256
#define NZ_DIM  64

// ---------------- scratch ----------------------------------------------------
__device__ __half g_s1h[N_NODES * H1_DIM];   // support1 (fp16)
__device__ __half g_h1h[N_NODES * H1_DIM];   // hidden1  (fp16)
__device__ __half g_s2h[N_NODES * NZ_DIM];   // support2 (fp16)
__device__ __half g_w1t[H1_DIM * F_IN];      // W1^T fp16
__device__ __half g_w2t[NZ_DIM * H1_DIM];    // W2^T fp16
__device__ __half g_zrh[N_NODES * NZ_DIM];   // z fp16 (zzt operand)
__device__ int    g_off   [N_NODES + 1];
__device__ int    g_cursor[N_NODES];
__device__ int2   g_srcw  [E_EDGES];

// ---------------- helpers -----------------------------------------------------
__device__ __forceinline__ void cp16(uint32_t s, const void* g) {
    asm volatile("cp.async.cg.shared.global [%0], [%1], 16;\n" ::"r"(s), "l"(g));
}
__device__ __forceinline__ void cp_commit() {
    asm volatile("cp.async.commit_group;\n");
}
template <int N>
__device__ __forceinline__ void cp_wait() {
    asm volatile("cp.async.wait_group %0;\n" ::"n"(N));
}
__device__ __forceinline__ uint32_t pack_h2(float lo, float hi) {
    __half2 h = __floats2half2_rn(lo, hi);
    return *reinterpret_cast<uint32_t*>(&h);
}
__device__ __forceinline__ void mma_f16(float (&d)[4], const uint32_t (&a)[4],
                                        const uint32_t (&b)[2]) {
    asm volatile(
        "mma.sync.aligned.m16n8k16.row.col.f32.f16.f16.f32 "
        "{%0,%1,%2,%3}, {%4,%5,%6,%7}, {%8,%9}, {%0,%1,%2,%3};"
        : "+f"(d[0]), "+f"(d[1]), "+f"(d[2]), "+f"(d[3])
        : "r"(a[0]), "r"(a[1]), "r"(a[2]), "r"(a[3]), "r"(b[0]), "r"(b[1]));
}

// ---------------- CSR build ----------------------------------------------------
__global__ void k_zero_counts() {
    int i = blockIdx.x * blockDim.x + threadIdx.x;
    ((int4*)g_cursor)[i] = make_int4(0, 0, 0, 0);
}
__global__ void k_hist(const int* __restrict__ ei) {
    int e = blockIdx.x * blockDim.x + threadIdx.x;
    if (e < E_EDGES) atomicAdd(&g_cursor[ei[E_EDGES + e]], 1);
}
__global__ void k_scan() {
    __shared__ int part[256];
    const int t = threadIdx.x;
    const int base = t * (N_NODES / 256);
    int s = 0;
#pragma unroll
    for (int j = 0; j < N_NODES / 256; j++) s += g_cursor[base + j];
    part[t] = s;
    __syncthreads();
    for (int off = 1; off < 256; off <<= 1) {
        int v = (t >= off) ? part[t - off] : 0;
        __syncthreads();
        part[t] += v;
        __syncthreads();
    }
    int run = part[t] - s;
#pragma unroll
    for (int j = 0; j < N_NODES / 256; j++) {
        int idx = base + j;
        int c = g_cursor[idx];
        g_off[idx] = run;
        g_cursor[idx] = run;
        run += c;
    }
    if (t == 255) g_off[N_NODES] = run;
}
__global__ void k_scatter(const int* __restrict__ ei, const float* __restrict__ ew) {
    int e = blockIdx.x * blockDim.x + threadIdx.x;
    if (e < E_EDGES) {
        int d = ei[E_EDGES + e];
        int p = atomicAdd(&g_cursor[d], 1);
        g_srcw[p] = make_int2(ei[e], __float_as_int(ew[e]));
    }
}

// ---------------- weight transpose -> fp16 -------------------------------------
__global__ void k_transpose_h(const float* __restrict__ in, __half* __restrict__ out,
                              int R, int C) {
    __shared__ float tile[32][33];
    const int bx = blockIdx.x * 32;
    const int by = blockIdx.y * 32;
    const int x = threadIdx.x, y0 = threadIdx.y;
#pragma unroll
    for (int j = y0; j < 32; j += 8)
        tile[j][x] = in[(size_t)(by + j) * C + bx + x];
    __syncthreads();
#pragma unroll
    for (int j = y0; j < 32; j += 8)
        out[(size_t)(bx + j) * R + by + x] = __float2half_rn(tile[x][j]);
}

// ---------------- SpMM + ReLU (fp16 gather, fp32 accumulate) -------------------
__global__ void __launch_bounds__(256) k_spmm_relu_256h(
    const __half* __restrict__ in, __half* __restrict__ out) {
    __shared__ int2 se[256];
    const int row = blockIdx.x;
    const int t   = threadIdx.x;
    const int beg = g_off[row], end = g_off[row + 1];
    float acc = 0.f;
    for (int cs = beg; cs < end; cs += 256) {
        int m = min(256, end - cs);
        __syncthreads();
        if (t < m) se[t] = g_srcw[cs + t];
        __syncthreads();
        int j = 0;
        for (; j + 8 <= m; j += 8) {
            float r[8];
            int2  v[8];
#pragma unroll
            for (int u = 0; u < 8; u++) v[u] = se[j + u];
#pragma unroll
            for (int u = 0; u < 8; u++)
                r[u] = __half2float(__ldg(&in[(size_t)v[u].x * H1_DIM + t]));
#pragma unroll
            for (int u = 0; u < 8; u++)
                acc += __int_as_float(v[u].y) * r[u];
        }
        for (; j < m; j++) {
            int2 v = se[j];
            acc += __int_as_float(v.y) *
                   __half2float(__ldg(&in[(size_t)v.x * H1_DIM + t]));
        }
    }
    out[(size_t)row * H1_DIM + t] = __float2half_rn(fmaxf(acc, 0.f));
}

__global__ void __launch_bounds__(256) k_spmm_relu_64h(
    const __half* __restrict__ in, float* __restrict__ out,
    __half* __restrict__ outr) {
    __shared__ int2 se[4][64];
    __shared__ int sdeg[4];
    const int t    = threadIdx.x;
    const int sub  = t >> 6;
    const int lane = t & 63;
    const int row  = blockIdx.x * 4 + sub;
    const int beg  = g_off[row];
    if (t < 4) sdeg[t] = g_off[blockIdx.x * 4 + t + 1] - g_off[blockIdx.x * 4 + t];
    __syncthreads();
    const int deg  = sdeg[sub];
    const int nch  = (max(max(sdeg[0], sdeg[1]), max(sdeg[2], sdeg[3])) + 63) >> 6;
    float acc = 0.f;
    for (int ch = 0; ch < nch; ch++) {
        int m = min(64, deg - ch * 64);
        __syncthreads();
        if (lane < m) se[sub][lane] = g_srcw[beg + ch * 64 + lane];
        __syncthreads();
        int j = 0;
        for (; j + 8 <= m; j += 8) {
            float r[8];
            int2  v[8];
#pragma unroll
            for (int u = 0; u < 8; u++) v[u] = se[sub][j + u];
#pragma unroll
            for (int u = 0; u < 8; u++)
                r[u] = __half2float(__ldg(&in[(size_t)v[u].x * NZ_DIM + lane]));
#pragma unroll
            for (int u = 0; u < 8; u++)
                acc += __int_as_float(v[u].y) * r[u];
        }
        for (; j < m; j++) {
            int2 v = se[sub][j];
            acc += __int_as_float(v.y) *
                   __half2float(__ldg(&in[(size_t)v.x * NZ_DIM + lane]));
        }
    }
    float rv = fmaxf(acc, 0.f);
    out [(size_t)row * NZ_DIM + lane] = rv;
    outr[(size_t)row * NZ_DIM + lane] = __float2half_rn(rv);
}

// ---------------- gemm1: x(f32) @ W1t(f16)^T -> support1(f16) -------------------
// BM=256 BN=128 BK=32, 512 thr, warps 8x2, m16n8k16 fp16 mma.
__global__ void __launch_bounds__(512, 1)
k_gemm1h(const float* __restrict__ A, const __half* __restrict__ Bt,
         __half* __restrict__ C) {
    constexpr int K = F_IN, Nc = H1_DIM;
    constexpr int PA = 36;             // floats  (144B rows, 16B-aligned)
    constexpr int PB = 40;             // halfs   (80B rows, 16B-aligned)
    constexpr int ASZ = 256 * PA;      // floats per stage
    constexpr int BSZH = 128 * PB;     // halfs per stage

    extern __shared__ float sm[];
    float*  sA0 = sm;
    __half* sB0 = (__half*)(sm + 2 * ASZ);
    const uint32_t smem_u32 = (uint32_t)__cvta_generic_to_shared(sm);
    const uint32_t bb0 = smem_u32 + 2 * ASZ * 4;

    const int tid  = threadIdx.x;
    const int warp = tid >> 5, lane = tid & 31;
    const int wr = warp >> 1, wc = warp & 1;
    const int bm0 = blockIdx.y * 256, bn0 = blockIdx.x * 128;
    const int g = lane >> 2, c = lane & 3;

    float acc[2][8][4];
#pragma unroll
    for (int mi = 0; mi < 2; mi++)
#pragma unroll
        for (int ni = 0; ni < 8; ni++)
#pragma unroll
            for (int j = 0; j < 4; j++) acc[mi][ni][j] = 0.f;

    constexpr int NT = K / 32;

    auto load_tiles = [&](int kt, int st) {
        const float* Ag = A + (size_t)bm0 * K + kt * 32;
        uint32_t abase = smem_u32 + (uint32_t)(st * ASZ) * 4u;
#pragma unroll
        for (int i = 0; i < 4; i++) {
            int v = tid + i * 512;
            int r = v >> 3, col = (v & 7) * 4;
            cp16(abase + (uint32_t)(r * PA + col) * 4u, Ag + (size_t)r * K + col);
        }
        const __half* Bg = Bt + (size_t)bn0 * K + kt * 32;
        uint32_t bbase = bb0 + (uint32_t)(st * BSZH) * 2u;
        {
            int r = tid >> 2, ch = tid & 3;   // 128 rows x 4 16B chunks
            cp16(bbase + (uint32_t)(r * PB + ch * 8) * 2u,
                 Bg + (size_t)r * K + ch * 8);
        }
    };

    load_tiles(0, 0);
    cp_commit();

    for (int kt = 0; kt < NT; kt++) {
        if (kt + 1 < NT) {
            load_tiles(kt + 1, (kt + 1) & 1);
            cp_commit();
            cp_wait<1>();
        } else {
            cp_wait<0>();
        }
        __syncthreads();

        const float*  sA = sA0 + (kt & 1) * ASZ;
        const __half* sB = sB0 + (kt & 1) * BSZH;
#pragma unroll
        for (int ks = 0; ks < 2; ks++) {
            const int k0 = ks * 16;
            uint32_t af[2][4];
            uint32_t bf[8][2];
#pragma unroll
            for (int mi = 0; mi < 2; mi++) {
                int r = wr * 32 + mi * 16 + g;
                float2 p0 = *reinterpret_cast<const float2*>(&sA[r * PA + k0 + 2 * c]);
                float2 p1 = *reinterpret_cast<const float2*>(&sA[(r + 8) * PA + k0 + 2 * c]);
                float2 p2 = *reinterpret_cast<const float2*>(&sA[r * PA + k0 + 2 * c + 8]);
                float2 p3 = *reinterpret_cast<const float2*>(&sA[(r + 8) * PA + k0 + 2 * c + 8]);
                af[mi][0] = pack_h2(p0.x, p0.y);
                af[mi][1] = pack_h2(p1.x, p1.y);
                af[mi][2] = pack_h2(p2.x, p2.y);
                af[mi][3] = pack_h2(p3.x, p3.y);
            }
#pragma unroll
            for (int ni = 0; ni < 8; ni++) {
                int n = wc * 64 + ni * 8 + g;
                bf[ni][0] = *reinterpret_cast<const uint32_t*>(&sB[n * PB + k0 + 2 * c]);
                bf[ni][1] = *reinterpret_cast<const uint32_t*>(&sB[n * PB + k0 + 2 * c + 8]);
            }
#pragma unroll
            for (int mi = 0; mi < 2; mi++)
#pragma unroll
                for (int ni = 0; ni < 8; ni++)
                    mma_f16(acc[mi][ni], af[mi], bf[ni]);
        }
        __syncthreads();
    }

#pragma unroll
    for (int mi = 0; mi < 2; mi++)
#pragma unroll
        for (int ni = 0; ni < 8; ni++) {
            int r  = bm0 + wr * 32 + mi * 16 + g;
            int cc = bn0 + wc * 64 + ni * 8 + c * 2;
            *reinterpret_cast<uint32_t*>(&C[(size_t)r * Nc + cc]) =
                pack_h2(acc[mi][ni][0], acc[mi][ni][1]);
            *reinterpret_cast<uint32_t*>(&C[(size_t)(r + 8) * Nc + cc]) =
                pack_h2(acc[mi][ni][2], acc[mi][ni][3]);
        }
}

// ---------------- gemm2: h1(f16) @ W2t(f16)^T -> support2(f16) ------------------
// BM=128 BN=64 BK=32, 256 thr, warps 4x2 (WN=32, NI=4).
__global__ void __launch_bounds__(256, 2)
k_gemm2h(const __half* __restrict__ A, const __half* __restrict__ Bt,
         __half* __restrict__ C) {
    constexpr int K = H1_DIM, Nc = NZ_DIM;
    constexpr int P = 40;                 // halfs (80B rows, 16B-aligned)
    constexpr int ASZ = 128 * P, BSZ = 64 * P;

    extern __shared__ __half smh[];
    __half* sA0 = smh;
    __half* sB0 = smh + 2 * ASZ;
    const uint32_t smem_u32 = (uint32_t)__cvta_generic_to_shared(smh);

    const int tid  = threadIdx.x;
    const int warp = tid >> 5, lane = tid & 31;
    const int wr = warp >> 1, wc = warp & 1;
    const int bm0 = blockIdx.y * 128;
    const int g = lane >> 2, c = lane & 3;

    float acc[2][4][4];
#pragma unroll
    for (int mi = 0; mi < 2; mi++)
#pragma unroll
        for (int ni = 0; ni < 4; ni++)
#pragma unroll
            for (int j = 0; j < 4; j++) acc[mi][ni][j] = 0.f;

    constexpr int NT = K / 32;

    auto load_tiles = [&](int kt, int st) {
        const __half* Ag = A + (size_t)bm0 * K + kt * 32;
        uint32_t abase = smem_u32 + (uint32_t)(st * ASZ) * 2u;
#pragma unroll
        for (int i = 0; i < 2; i++) {
            int v = tid + i * 256;
            int r = v >> 2, ch = v & 3;    // 128 rows x 4 16B chunks
            cp16(abase + (uint32_t)(r * P + ch * 8) * 2u, Ag + (size_t)r * K + ch * 8);
        }
        const __half* Bg = Bt + (size_t)(kt * 32);
        uint32_t bbase = smem_u32 + (uint32_t)(2 * ASZ + st * BSZ) * 2u;
        {
            int r = tid >> 2, ch = tid & 3;  // 64 rows x 4 chunks = 256
            cp16(bbase + (uint32_t)(r * P + ch * 8) * 2u, Bg + (size_t)r * K + ch * 8);
        }
    };

    load_tiles(0, 0);
    cp_commit();

    for (int kt = 0; kt < NT; kt++) {
        if (kt + 1 < NT) {
            load_tiles(kt + 1, (kt + 1) & 1);
            cp_commit();
            cp_wait<1>();
        } else {
            cp_wait<0>();
        }
        __syncthreads();

        const __half* sA = sA0 + (kt & 1) * ASZ;
        const __half* sB = sB0 + (kt & 1) * BSZ;
#pragma unroll
        for (int ks = 0; ks < 2; ks++) {
            const int k0 = ks * 16;
            uint32_t af[2][4];
            uint32_t bf[4][2];
#pragma unroll
            for (int mi = 0; mi < 2; mi++) {
                int r = wr * 32 + mi * 16 + g;
                af[mi][0] = *reinterpret_cast<const uint32_t*>(&sA[r * P + k0 + 2 * c]);
                af[mi][1] = *reinterpret_cast<const uint32_t*>(&sA[(r + 8) * P + k0 + 2 * c]);
                af[mi][2] = *reinterpret_cast<const uint32_t*>(&sA[r * P + k0 + 2 * c + 8]);
                af[mi][3] = *reinterpret_cast<const uint32_t*>(&sA[(r + 8) * P + k0 + 2 * c + 8]);
            }
#pragma unroll
            for (int ni = 0; ni < 4; ni++) {
                int n = wc * 32 + ni * 8 + g;
                bf[ni][0] = *reinterpret_cast<const uint32_t*>(&sB[n * P + k0 + 2 * c]);
                bf[ni][1] = *reinterpret_cast<const uint32_t*>(&sB[n * P + k0 + 2 * c + 8]);
            }
#pragma unroll
            for (int mi = 0; mi < 2; mi++)
#pragma unroll
                for (int ni = 0; ni < 4; ni++)
                    mma_f16(acc[mi][ni], af[mi], bf[ni]);
        }
        __syncthreads();
    }

#pragma unroll
    for (int mi = 0; mi < 2; mi++)
#pragma unroll
        for (int ni = 0; ni < 4; ni++) {
            int r  = bm0 + wr * 32 + mi * 16 + g;
            int cc = wc * 32 + ni * 8 + c * 2;
            *reinterpret_cast<uint32_t*>(&C[(size_t)r * Nc + cc]) =
                pack_h2(acc[mi][ni][0], acc[mi][ni][1]);
            *reinterpret_cast<uint32_t*>(&C[(size_t)(r + 8) * Nc + cc]) =
                pack_h2(acc[mi][ni][2], acc[mi][ni][3]);
        }
}

// ---------------- z @ z^T (fp16 operands, symmetric triangular grid) -----------
__global__ void __launch_bounds__(256, 2)
k_zzt_h(const __half* __restrict__ Z, float* __restrict__ C) {
    constexpr int P  = 72;    // halfs (144B rows, 16B-aligned)
    constexpr int TP = 132;   // floats (transpose staging)
    extern __shared__ float sm[];
    __half* sAh = (__half*)sm;
    __half* sBh = sAh + 128 * P;
    const uint32_t smem_u32 = (uint32_t)__cvta_generic_to_shared(sm);

    const int tid  = threadIdx.x;
    const int warp = tid >> 5, lane = tid & 31;
    const int wm = warp & 1, wn = warp >> 1;
    const int g = lane >> 2, c = lane & 3;

    int t = blockIdx.x;
    int bi = (int)((sqrtf(8.f * (float)t + 1.f) - 1.f) * 0.5f);
    while ((bi + 1) * (bi + 2) / 2 <= t) bi++;
    while (bi * (bi + 1) / 2 > t) bi--;
    int bj = t - bi * (bi + 1) / 2;
    const int bm0 = bi * 128;
    const int bn0 = bj * 128;

#pragma unroll
    for (int i = 0; i < 4; i++) {
        int v = tid + i * 256;
        int r = v >> 3, ch = v & 7;
        cp16(smem_u32 + (uint32_t)(r * P + ch * 8) * 2u,
             Z + (size_t)(bm0 + r) * NZ_DIM + ch * 8);
    }
#pragma unroll
    for (int i = 0; i < 4; i++) {
        int v = tid + i * 256;
        int r = v >> 3, ch = v & 7;
        cp16(smem_u32 + (uint32_t)(128 * P + r * P + ch * 8) * 2u,
             Z + (size_t)(bn0 + r) * NZ_DIM + ch * 8);
    }
    cp_commit();
    cp_wait<0>();
    __syncthreads();

    float acc[4][4][4];
#pragma unroll
    for (int mi = 0; mi < 4; mi++)
#pragma unroll
        for (int ni = 0; ni < 4; ni++)
#pragma unroll
            for (int j = 0; j < 4; j++) acc[mi][ni][j] = 0.f;

#pragma unroll
    for (int ks = 0; ks < 4; ks++) {
        const int k0 = ks * 16;
        uint32_t af[4][4];
        uint32_t bf[4][2];
#pragma unroll
        for (int mi = 0; mi < 4; mi++) {
            int r = wm * 64 + mi * 16 + g;
            af[mi][0] = *reinterpret_cast<const uint32_t*>(&sAh[r * P + k0 + 2 * c]);
            af[mi][1] = *reinterpret_cast<const uint32_t*>(&sAh[(r + 8) * P + k0 + 2 * c]);
            af[mi][2] = *reinterpret_cast<const uint32_t*>(&sAh[r * P + k0 + 2 * c + 8]);
            af[mi][3] = *reinterpret_cast<const uint32_t*>(&sAh[(r + 8) * P + k0 + 2 * c + 8]);
        }
#pragma unroll
        for (int ni = 0; ni < 4; ni++) {
            int n = wn * 32 + ni * 8 + g;
            bf[ni][0] = *reinterpret_cast<const uint32_t*>(&sBh[n * P + k0 + 2 * c]);
            bf[ni][1] = *reinterpret_cast<const uint32_t*>(&sBh[n * P + k0 + 2 * c + 8]);
        }
#pragma unroll
        for (int mi = 0; mi < 4; mi++)
#pragma unroll
            for (int ni = 0; ni < 4; ni++)
                mma_f16(acc[mi][ni], af[mi], bf[ni]);
    }

#pragma unroll
    for (int mi = 0; mi < 4; mi++)
#pragma unroll
        for (int ni = 0; ni < 4; ni++) {
            int r  = bm0 + wm * 64 + mi * 16 + g;
            int cc = bn0 + wn * 32 + ni * 8 + c * 2;
            *reinterpret_cast<float2*>(&C[(size_t)r * N_NODES + cc]) =
                make_float2(acc[mi][ni][0], acc[mi][ni][1]);
            *reinterpret_cast<float2*>(&C[(size_t)(r + 8) * N_NODES + cc]) =
                make_float2(acc[mi][ni][2], acc[mi][ni][3]);
        }

    if (bi == bj) return;

    __syncthreads();
#pragma unroll
    for (int mi = 0; mi < 4; mi++)
#pragma unroll
        for (int ni = 0; ni < 4; ni++) {
            int r  = wm * 64 + mi * 16 + g;
            int cc = wn * 32 + ni * 8 + c * 2;
            sm[(size_t)cc * TP + r]           = acc[mi][ni][0];
            sm[(size_t)(cc + 1) * TP + r]     = acc[mi][ni][1];
            sm[(size_t)cc * TP + r + 8]       = acc[mi][ni][2];
            sm[(size_t)(cc + 1) * TP + r + 8] = acc[mi][ni][3];
        }
    __syncthreads();
#pragma unroll
    for (int i = 0; i < 16; i++) {
        int v = tid + i * 256;
        int j = v >> 5, col = (v & 31) * 4;
        float4 q = *reinterpret_cast<const float4*>(&sm[(size_t)j * TP + col]);
        *reinterpret_cast<float4*>(&C[(size_t)(bn0 + j) * N_NODES + bm0 + col]) = q;
    }
}

// ---------------- stream/event singletons --------------------------------------
struct AuxRes {
    cudaStream_t s2;
    cudaEvent_t  evFork, evJoin;
    AuxRes() {
        cudaStreamCreateWithFlags(&s2, cudaStreamNonBlocking);
        cudaEventCreateWithFlags(&evFork, cudaEventDisableTiming);
        cudaEventCreateWithFlags(&evJoin, cudaEventDisableTiming);
    }
};

// ---------------- launch --------------------------------------------------------
extern "C" void kernel_launch(void* const* d_in, const int* in_sizes, int n_in,
                              void* d_out, int out_size) {
    static AuxRes aux;

    const float* x  = (const float*)d_in[0];
    const float* W1 = (const float*)d_in[1];
    const float* W2 = (const float*)d_in[2];
    const float* ew = (const float*)d_in[3];
    const int*   ei = (const int*)d_in[4];

    float* out  = (float*)d_out;
    float* abar = out;
    float* z    = out + (size_t)N_NODES * N_NODES;

    __half *s1h, *h1h, *s2h, *w1t, *w2t, *zrh;
    cudaGetSymbolAddress((void**)&s1h, g_s1h);
    cudaGetSymbolAddress((void**)&h1h, g_h1h);
    cudaGetSymbolAddress((void**)&s2h, g_s2h);
    cudaGetSymbolAddress((void**)&w1t, g_w1t);
    cudaGetSymbolAddress((void**)&w2t, g_w2t);
    cudaGetSymbolAddress((void**)&zrh, g_zrh);

    constexpr int SM_G1  = 2 * (256 * 36 * 4 + 128 * 40 * 2);  // 94208
    constexpr int SM_G2  = 2 * (128 * 40 + 64 * 40) * 2;       // 30720
    constexpr int SM_ZZT = 69632;

    cudaFuncSetAttribute(k_gemm1h,
                         cudaFuncAttributeMaxDynamicSharedMemorySize, SM_G1);
    cudaFuncSetAttribute(k_gemm2h,
                         cudaFuncAttributeMaxDynamicSharedMemorySize, SM_G2);
    cudaFuncSetAttribute(k_zzt_h,
                         cudaFuncAttributeMaxDynamicSharedMemorySize, SM_ZZT);

    // fork: CSR chain on aux.s2; GEMM path on default stream
    cudaEventRecord(aux.evFork, 0);
    cudaStreamWaitEvent(aux.s2, aux.evFork, 0);

    k_transpose_h<<<dim3(H1_DIM / 32, F_IN / 32), dim3(32, 8)>>>(     // 1
        W1, w1t, F_IN, H1_DIM);
    k_zero_counts<<<N_NODES / 1024, 256, 0, aux.s2>>>();              // 2 (s2)
    k_transpose_h<<<dim3(NZ_DIM / 32, H1_DIM / 32), dim3(32, 8)>>>(   // 3
        W2, w2t, H1_DIM, NZ_DIM);
    k_gemm1h<<<dim3(H1_DIM / 128, N_NODES / 256), 512, SM_G1>>>(      // 4
        x, w1t, s1h);
    k_hist<<<E_EDGES / 256, 256, 0, aux.s2>>>(ei);                    // 5 (s2)
    k_scan<<<1, 256, 0, aux.s2>>>();                                  // 6 (s2)
    k_scatter<<<E_EDGES / 256, 256, 0, aux.s2>>>(ei, ew);             // 7 (s2)

    cudaEventRecord(aux.evJoin, aux.s2);
    cudaStreamWaitEvent(0, aux.evJoin, 0);

    k_spmm_relu_256h<<<N_NODES, 256>>>(s1h, h1h);                     // 8
    k_gemm2h<<<dim3(1, N_NODES / 128), 256, SM_G2>>>(h1h, w2t, s2h);  // 9
    k_spmm_relu_64h<<<N_NODES / 4, 256>>>(s2h, z, zrh);               // 10
    const int ntile = N_NODES / 128;
    k_zzt_h<<<ntile * (ntile + 1) / 2, 256, SM_ZZT>>>(zrh, abar);     // 11
}

// round 10
// speedup vs baseline: 1.3855x; 1.0394x over previous
#include <cuda_runtime.h>
#include <cuda_fp16.h>
#include <cstdint>
#include <cstddef>

#define N_NODES 16384
#define E_EDGES 262144
#define F_IN    1024
#define H1_DIM  256
#define NZ_DIM  64

// ---------------- scratch ----------------------------------------------------
__device__ __half g_xh [N_NODES * F_IN];     // x fp16 (32 MB)
__device__ __half g_s1h[N_NODES * H1_DIM];   // support1 (fp16)
__device__ __half g_h1h[N_NODES * H1_DIM];   // hidden1  (fp16)
__device__ __half g_s2h[N_NODES * NZ_DIM];   // support2 (fp16)
__device__ __half g_w1t[H1_DIM * F_IN];      // W1^T fp16
__device__ __half g_w2t[NZ_DIM * H1_DIM];    // W2^T fp16
__device__ __half g_zrh[N_NODES * NZ_DIM];   // z fp16 (zzt operand)
__device__ int    g_off   [N_NODES + 1];
__device__ int    g_cursor[N_NODES];
__device__ int2   g_srcw  [E_EDGES];

// ---------------- helpers -----------------------------------------------------
__device__ __forceinline__ void cp16(uint32_t s, const void* g) {
    asm volatile("cp.async.cg.shared.global [%0], [%1], 16;\n" ::"r"(s), "l"(g));
}
__device__ __forceinline__ void cp_commit() {
    asm volatile("cp.async.commit_group;\n");
}
template <int N>
__device__ __forceinline__ void cp_wait() {
    asm volatile("cp.async.wait_group %0;\n" ::"n"(N));
}
__device__ __forceinline__ uint32_t pack_h2(float lo, float hi) {
    __half2 h = __floats2half2_rn(lo, hi);
    return *reinterpret_cast<uint32_t*>(&h);
}
__device__ __forceinline__ void mma_f16(float (&d)[4], const uint32_t (&a)[4],
                                        const uint32_t (&b)[2]) {
    asm volatile(
        "mma.sync.aligned.m16n8k16.row.col.f32.f16.f16.f32 "
        "{%0,%1,%2,%3}, {%4,%5,%6,%7}, {%8,%9}, {%0,%1,%2,%3};"
        : "+f"(d[0]), "+f"(d[1]), "+f"(d[2]), "+f"(d[3])
        : "r"(a[0]), "r"(a[1]), "r"(a[2]), "r"(a[3]), "r"(b[0]), "r"(b[1]));
}

// ---------------- x -> fp16 convert --------------------------------------------
__global__ void k_x2h(const float4* __restrict__ in, uint2* __restrict__ out) {
    int i = blockIdx.x * blockDim.x + threadIdx.x;
    float4 v = in[i];
    out[i] = make_uint2(pack_h2(v.x, v.y), pack_h2(v.z, v.w));
}

// ---------------- CSR build ----------------------------------------------------
__global__ void k_zero_counts() {
    int i = blockIdx.x * blockDim.x + threadIdx.x;
    ((int4*)g_cursor)[i] = make_int4(0, 0, 0, 0);
}
__global__ void k_hist(const int* __restrict__ ei) {
    int e = blockIdx.x * blockDim.x + threadIdx.x;
    if (e < E_EDGES) atomicAdd(&g_cursor[ei[E_EDGES + e]], 1);
}
__global__ void k_scan() {
    __shared__ int part[256];
    const int t = threadIdx.x;
    const int base = t * (N_NODES / 256);
    int s = 0;
#pragma unroll
    for (int j = 0; j < N_NODES / 256; j++) s += g_cursor[base + j];
    part[t] = s;
    __syncthreads();
    for (int off = 1; off < 256; off <<= 1) {
        int v = (t >= off) ? part[t - off] : 0;
        __syncthreads();
        part[t] += v;
        __syncthreads();
    }
    int run = part[t] - s;
#pragma unroll
    for (int j = 0; j < N_NODES / 256; j++) {
        int idx = base + j;
        int c = g_cursor[idx];
        g_off[idx] = run;
        g_cursor[idx] = run;
        run += c;
    }
    if (t == 255) g_off[N_NODES] = run;
}
__global__ void k_scatter(const int* __restrict__ ei, const float* __restrict__ ew) {
    int e = blockIdx.x * blockDim.x + threadIdx.x;
    if (e < E_EDGES) {
        int d = ei[E_EDGES + e];
        int p = atomicAdd(&g_cursor[d], 1);
        g_srcw[p] = make_int2(ei[e], __float_as_int(ew[e]));
    }
}

// ---------------- weight transpose -> fp16 -------------------------------------
__global__ void k_transpose_h(const float* __restrict__ in, __half* __restrict__ out,
                              int R, int C) {
    __shared__ float tile[32][33];
    const int bx = blockIdx.x * 32;
    const int by = blockIdx.y * 32;
    const int x = threadIdx.x, y0 = threadIdx.y;
#pragma unroll
    for (int j = y0; j < 32; j += 8)
        tile[j][x] = in[(size_t)(by + j) * C + bx + x];
    __syncthreads();
#pragma unroll
    for (int j = y0; j < 32; j += 8)
        out[(size_t)(bx + j) * R + by + x] = __float2half_rn(tile[x][j]);
}

// ---------------- SpMM + ReLU (half2 lanes, fp32 accumulate) -------------------
// 2 rows per block, 128 half2 lanes each (d=256)
__global__ void __launch_bounds__(256) k_spmm_relu_256h2(
    const __half2* __restrict__ in2, __half2* __restrict__ out2) {
    __shared__ int2 se[2][128];
    __shared__ int sdeg[2];
    const int t    = threadIdx.x;
    const int sub  = t >> 7;
    const int lane = t & 127;
    const int row  = blockIdx.x * 2 + sub;
    if (t < 2) sdeg[t] = g_off[blockIdx.x * 2 + t + 1] - g_off[blockIdx.x * 2 + t];
    __syncthreads();
    const int beg = g_off[row];
    const int deg = sdeg[sub];
    const int nch = (max(sdeg[0], sdeg[1]) + 127) >> 7;
    float ax = 0.f, ay = 0.f;
    for (int ch = 0; ch < nch; ch++) {
        int m = min(128, deg - ch * 128);
        __syncthreads();
        if (lane < m) se[sub][lane] = g_srcw[beg + ch * 128 + lane];
        __syncthreads();
        int j = 0;
        for (; j + 8 <= m; j += 8) {
            int2 v[8];
            float2 f[8];
#pragma unroll
            for (int u = 0; u < 8; u++) v[u] = se[sub][j + u];
#pragma unroll
            for (int u = 0; u < 8; u++)
                f[u] = __half22float2(__ldg(&in2[(size_t)v[u].x * 128 + lane]));
#pragma unroll
            for (int u = 0; u < 8; u++) {
                float w = __int_as_float(v[u].y);
                ax += w * f[u].x;
                ay += w * f[u].y;
            }
        }
        for (; j < m; j++) {
            int2 v = se[sub][j];
            float2 f = __half22float2(__ldg(&in2[(size_t)v.x * 128 + lane]));
            float w = __int_as_float(v.y);
            ax += w * f.x;
            ay += w * f.y;
        }
    }
    out2[(size_t)row * 128 + lane] = __floats2half2_rn(fmaxf(ax, 0.f), fmaxf(ay, 0.f));
}

// 8 rows per block, 32 half2 lanes each (d=64)
__global__ void __launch_bounds__(256) k_spmm_relu_64h2(
    const __half2* __restrict__ in2, float2* __restrict__ out2,
    __half2* __restrict__ outr2) {
    __shared__ int2 se[8][32];
    __shared__ int sdeg[8];
    const int t    = threadIdx.x;
    const int sub  = t >> 5;
    const int lane = t & 31;
    const int row  = blockIdx.x * 8 + sub;
    if (t < 8) sdeg[t] = g_off[blockIdx.x * 8 + t + 1] - g_off[blockIdx.x * 8 + t];
    __syncthreads();
    const int beg = g_off[row];
    const int deg = sdeg[sub];
    int mx = sdeg[0];
#pragma unroll
    for (int q = 1; q < 8; q++) mx = max(mx, sdeg[q]);
    const int nch = (mx + 31) >> 5;
    float ax = 0.f, ay = 0.f;
    for (int ch = 0; ch < nch; ch++) {
        int m = min(32, deg - ch * 32);
        __syncthreads();
        if (lane < m) se[sub][lane] = g_srcw[beg + ch * 32 + lane];
        __syncthreads();
        int j = 0;
        for (; j + 8 <= m; j += 8) {
            int2 v[8];
            float2 f[8];
#pragma unroll
            for (int u = 0; u < 8; u++) v[u] = se[sub][j + u];
#pragma unroll
            for (int u = 0; u < 8; u++)
                f[u] = __half22float2(__ldg(&in2[(size_t)v[u].x * 32 + lane]));
#pragma unroll
            for (int u = 0; u < 8; u++) {
                float w = __int_as_float(v[u].y);
                ax += w * f[u].x;
                ay += w * f[u].y;
            }
        }
        for (; j < m; j++) {
            int2 v = se[sub][j];
            float2 f = __half22float2(__ldg(&in2[(size_t)v.x * 32 + lane]));
            float w = __int_as_float(v.y);
            ax += w * f.x;
            ay += w * f.y;
        }
    }
    float rx = fmaxf(ax, 0.f), ry = fmaxf(ay, 0.f);
    out2 [(size_t)row * 32 + lane] = make_float2(rx, ry);
    outr2[(size_t)row * 32 + lane] = __floats2half2_rn(rx, ry);
}

// ---------------- gemm1: xh(f16) @ W1t(f16)^T -> support1(f16) ------------------
// BM=128 BN=128 BK=32, 256 thr, warps 4x2 (warp tile 32x64), 4-stage pipeline.
__global__ void __launch_bounds__(256, 2)
k_gemm1hh(const __half* __restrict__ A, const __half* __restrict__ Bt,
          __half* __restrict__ C) {
    constexpr int K = F_IN, Nc = H1_DIM;
    constexpr int P = 40;              // halfs (80B rows, 16B-aligned, conflict-free)
    constexpr int ASZ = 128 * P;       // halfs per stage
    constexpr int BSZ = 128 * P;
    constexpr int STG = 4;
    constexpr int NT = K / 32;

    extern __shared__ __half smh[];
    __half* sA0 = smh;
    __half* sB0 = smh + STG * ASZ;
    const uint32_t smem_u32 = (uint32_t)__cvta_generic_to_shared(smh);
    const uint32_t bb0 = smem_u32 + STG * ASZ * 2;

    const int tid  = threadIdx.x;
    const int warp = tid >> 5, lane = tid & 31;
    const int wr = warp >> 1, wc = warp & 1;
    const int bm0 = blockIdx.y * 128, bn0 = blockIdx.x * 128;
    const int g = lane >> 2, c = lane & 3;

    float acc[2][8][4];
#pragma unroll
    for (int mi = 0; mi < 2; mi++)
#pragma unroll
        for (int ni = 0; ni < 8; ni++)
#pragma unroll
            for (int j = 0; j < 4; j++) acc[mi][ni][j] = 0.f;

    auto load_tiles = [&](int kt, int st) {
        const __half* Ag = A + (size_t)bm0 * K + kt * 32;
        uint32_t abase = smem_u32 + (uint32_t)(st * ASZ) * 2u;
#pragma unroll
        for (int i = 0; i < 2; i++) {
            int v = tid + i * 256;
            int r = v >> 2, ch = v & 3;    // 128 rows x 4 16B chunks
            cp16(abase + (uint32_t)(r * P + ch * 8) * 2u, Ag + (size_t)r * K + ch * 8);
        }
        const __half* Bg = Bt + (size_t)bn0 * K + kt * 32;
        uint32_t bbase = bb0 + (uint32_t)(st * BSZ) * 2u;
#pragma unroll
        for (int i = 0; i < 2; i++) {
            int v = tid + i * 256;
            int r = v >> 2, ch = v & 3;
            cp16(bbase + (uint32_t)(r * P + ch * 8) * 2u, Bg + (size_t)r * K + ch * 8);
        }
    };

    load_tiles(0, 0);
    cp_commit();
    load_tiles(1, 1);
    cp_commit();
    load_tiles(2, 2);
    cp_commit();

    for (int kt = 0; kt < NT; kt++) {
        cp_wait<2>();
        __syncthreads();

        int pf = kt + 3;
        if (pf < NT) load_tiles(pf, pf & 3);
        cp_commit();   // always commit (possibly empty) to keep group count exact

        const __half* sA = sA0 + (kt & 3) * ASZ;
        const __half* sB = sB0 + (kt & 3) * BSZ;
#pragma unroll
        for (int ks = 0; ks < 2; ks++) {
            const int k0 = ks * 16;
            uint32_t af[2][4];
            uint32_t bf[8][2];
#pragma unroll
            for (int mi = 0; mi < 2; mi++) {
                int r = wr * 32 + mi * 16 + g;
                af[mi][0] = *reinterpret_cast<const uint32_t*>(&sA[r * P + k0 + 2 * c]);
                af[mi][1] = *reinterpret_cast<const uint32_t*>(&sA[(r + 8) * P + k0 + 2 * c]);
                af[mi][2] = *reinterpret_cast<const uint32_t*>(&sA[r * P + k0 + 2 * c + 8]);
                af[mi][3] = *reinterpret_cast<const uint32_t*>(&sA[(r + 8) * P + k0 + 2 * c + 8]);
            }
#pragma unroll
            for (int ni = 0; ni < 8; ni++) {
                int n = wc * 64 + ni * 8 + g;
                bf[ni][0] = *reinterpret_cast<const uint32_t*>(&sB[n * P + k0 + 2 * c]);
                bf[ni][1] = *reinterpret_cast<const uint32_t*>(&sB[n * P + k0 + 2 * c + 8]);
            }
#pragma unroll
            for (int mi = 0; mi < 2; mi++)
#pragma unroll
                for (int ni = 0; ni < 8; ni++)
                    mma_f16(acc[mi][ni], af[mi], bf[ni]);
        }
    }

    __syncthreads();
#pragma unroll
    for (int mi = 0; mi < 2; mi++)
#pragma unroll
        for (int ni = 0; ni < 8; ni++) {
            int r  = bm0 + wr * 32 + mi * 16 + g;
            int cc = bn0 + wc * 64 + ni * 8 + c * 2;
            *reinterpret_cast<uint32_t*>(&C[(size_t)r * Nc + cc]) =
                pack_h2(acc[mi][ni][0], acc[mi][ni][1]);
            *reinterpret_cast<uint32_t*>(&C[(size_t)(r + 8) * Nc + cc]) =
                pack_h2(acc[mi][ni][2], acc[mi][ni][3]);
        }
}

// ---------------- gemm2: h1(f16) @ W2t(f16)^T -> support2(f16) ------------------
__global__ void __launch_bounds__(256, 2)
k_gemm2h(const __half* __restrict__ A, const __half* __restrict__ Bt,
         __half* __restrict__ C) {
    constexpr int K = H1_DIM, Nc = NZ_DIM;
    constexpr int P = 40;
    constexpr int ASZ = 128 * P, BSZ = 64 * P;

    extern __shared__ __half smh[];
    __half* sA0 = smh;
    __half* sB0 = smh + 2 * ASZ;
    const uint32_t smem_u32 = (uint32_t)__cvta_generic_to_shared(smh);

    const int tid  = threadIdx.x;
    const int warp = tid >> 5, lane = tid & 31;
    const int wr = warp >> 1, wc = warp & 1;
    const int bm0 = blockIdx.y * 128;
    const int g = lane >> 2, c = lane & 3;

    float acc[2][4][4];
#pragma unroll
    for (int mi = 0; mi < 2; mi++)
#pragma unroll
        for (int ni = 0; ni < 4; ni++)
#pragma unroll
            for (int j = 0; j < 4; j++) acc[mi][ni][j] = 0.f;

    constexpr int NT = K / 32;

    auto load_tiles = [&](int kt, int st) {
        const __half* Ag = A + (size_t)bm0 * K + kt * 32;
        uint32_t abase = smem_u32 + (uint32_t)(st * ASZ) * 2u;
#pragma unroll
        for (int i = 0; i < 2; i++) {
            int v = tid + i * 256;
            int r = v >> 2, ch = v & 3;
            cp16(abase + (uint32_t)(r * P + ch * 8) * 2u, Ag + (size_t)r * K + ch * 8);
        }
        const __half* Bg = Bt + (size_t)(kt * 32);
        uint32_t bbase = smem_u32 + (uint32_t)(2 * ASZ + st * BSZ) * 2u;
        {
            int r = tid >> 2, ch = tid & 3;
            cp16(bbase + (uint32_t)(r * P + ch * 8) * 2u, Bg + (size_t)r * K + ch * 8);
        }
    };

    load_tiles(0, 0);
    cp_commit();

    for (int kt = 0; kt < NT; kt++) {
        if (kt + 1 < NT) {
            load_tiles(kt + 1, (kt + 1) & 1);
            cp_commit();
            cp_wait<1>();
        } else {
            cp_wait<0>();
        }
        __syncthreads();

        const __half* sA = sA0 + (kt & 1) * ASZ;
        const __half* sB = sB0 + (kt & 1) * BSZ;
#pragma unroll
        for (int ks = 0; ks < 2; ks++) {
            const int k0 = ks * 16;
            uint32_t af[2][4];
            uint32_t bf[4][2];
#pragma unroll
            for (int mi = 0; mi < 2; mi++) {
                int r = wr * 32 + mi * 16 + g;
                af[mi][0] = *reinterpret_cast<const uint32_t*>(&sA[r * P + k0 + 2 * c]);
                af[mi][1] = *reinterpret_cast<const uint32_t*>(&sA[(r + 8) * P + k0 + 2 * c]);
                af[mi][2] = *reinterpret_cast<const uint32_t*>(&sA[r * P + k0 + 2 * c + 8]);
                af[mi][3] = *reinterpret_cast<const uint32_t*>(&sA[(r + 8) * P + k0 + 2 * c + 8]);
            }
#pragma unroll
            for (int ni = 0; ni < 4; ni++) {
                int n = wc * 32 + ni * 8 + g;
                bf[ni][0] = *reinterpret_cast<const uint32_t*>(&sB[n * P + k0 + 2 * c]);
                bf[ni][1] = *reinterpret_cast<const uint32_t*>(&sB[n * P + k0 + 2 * c + 8]);
            }
#pragma unroll
            for (int mi = 0; mi < 2; mi++)
#pragma unroll
                for (int ni = 0; ni < 4; ni++)
                    mma_f16(acc[mi][ni], af[mi], bf[ni]);
        }
        __syncthreads();
    }

#pragma unroll
    for (int mi = 0; mi < 2; mi++)
#pragma unroll
        for (int ni = 0; ni < 4; ni++) {
            int r  = bm0 + wr * 32 + mi * 16 + g;
            int cc = wc * 32 + ni * 8 + c * 2;
            *reinterpret_cast<uint32_t*>(&C[(size_t)r * Nc + cc]) =
                pack_h2(acc[mi][ni][0], acc[mi][ni][1]);
            *reinterpret_cast<uint32_t*>(&C[(size_t)(r + 8) * Nc + cc]) =
                pack_h2(acc[mi][ni][2], acc[mi][ni][3]);
        }
}

// ---------------- z @ z^T (fp16 operands, symmetric triangular grid) -----------
__global__ void __launch_bounds__(256, 2)
k_zzt_h(const __half* __restrict__ Z, float* __restrict__ C) {
    constexpr int P  = 72;    // halfs (144B rows, 16B-aligned)
    constexpr int TP = 132;   // floats (transpose staging)
    extern __shared__ float sm[];
    __half* sAh = (__half*)sm;
    __half* sBh = sAh + 128 * P;
    const uint32_t smem_u32 = (uint32_t)__cvta_generic_to_shared(sm);

    const int tid  = threadIdx.x;
    const int warp = tid >> 5, lane = tid & 31;
    const int wm = warp & 1, wn = warp >> 1;
    const int g = lane >> 2, c = lane & 3;

    int t = blockIdx.x;
    int bi = (int)((sqrtf(8.f * (float)t + 1.f) - 1.f) * 0.5f);
    while ((bi + 1) * (bi + 2) / 2 <= t) bi++;
    while (bi * (bi + 1) / 2 > t) bi--;
    int bj = t - bi * (bi + 1) / 2;
    const int bm0 = bi * 128;
    const int bn0 = bj * 128;

#pragma unroll
    for (int i = 0; i < 4; i++) {
        int v = tid + i * 256;
        int r = v >> 3, ch = v & 7;
        cp16(smem_u32 + (uint32_t)(r * P + ch * 8) * 2u,
             Z + (size_t)(bm0 + r) * NZ_DIM + ch * 8);
    }
#pragma unroll
    for (int i = 0; i < 4; i++) {
        int v = tid + i * 256;
        int r = v >> 3, ch = v & 7;
        cp16(smem_u32 + (uint32_t)(128 * P + r * P + ch * 8) * 2u,
             Z + (size_t)(bn0 + r) * NZ_DIM + ch * 8);
    }
    cp_commit();
    cp_wait<0>();
    __syncthreads();

    float acc[4][4][4];
#pragma unroll
    for (int mi = 0; mi < 4; mi++)
#pragma unroll
        for (int ni = 0; ni < 4; ni++)
#pragma unroll
            for (int j = 0; j < 4; j++) acc[mi][ni][j] = 0.f;

#pragma unroll
    for (int ks = 0; ks < 4; ks++) {
        const int k0 = ks * 16;
        uint32_t af[4][4];
        uint32_t bf[4][2];
#pragma unroll
        for (int mi = 0; mi < 4; mi++) {
            int r = wm * 64 + mi * 16 + g;
            af[mi][0] = *reinterpret_cast<const uint32_t*>(&sAh[r * P + k0 + 2 * c]);
            af[mi][1] = *reinterpret_cast<const uint32_t*>(&sAh[(r + 8) * P + k0 + 2 * c]);
            af[mi][2] = *reinterpret_cast<const uint32_t*>(&sAh[r * P + k0 + 2 * c + 8]);
            af[mi][3] = *reinterpret_cast<const uint32_t*>(&sAh[(r + 8) * P + k0 + 2 * c + 8]);
        }
#pragma unroll
        for (int ni = 0; ni < 4; ni++) {
            int n = wn * 32 + ni * 8 + g;
            bf[ni][0] = *reinterpret_cast<const uint32_t*>(&sBh[n * P + k0 + 2 * c]);
            bf[ni][1] = *reinterpret_cast<const uint32_t*>(&sBh[n * P + k0 + 2 * c + 8]);
        }
#pragma unroll
        for (int mi = 0; mi < 4; mi++)
#pragma unroll
            for (int ni = 0; ni < 4; ni++)
                mma_f16(acc[mi][ni], af[mi], bf[ni]);
    }

#pragma unroll
    for (int mi = 0; mi < 4; mi++)
#pragma unroll
        for (int ni = 0; ni < 4; ni++) {
            int r  = bm0 + wm * 64 + mi * 16 + g;
            int cc = bn0 + wn * 32 + ni * 8 + c * 2;
            *reinterpret_cast<float2*>(&C[(size_t)r * N_NODES + cc]) =
                make_float2(acc[mi][ni][0], acc[mi][ni][1]);
            *reinterpret_cast<float2*>(&C[(size_t)(r + 8) * N_NODES + cc]) =
                make_float2(acc[mi][ni][2], acc[mi][ni][3]);
        }

    if (bi == bj) return;

    __syncthreads();
#pragma unroll
    for (int mi = 0; mi < 4; mi++)
#pragma unroll
        for (int ni = 0; ni < 4; ni++) {
            int r  = wm * 64 + mi * 16 + g;
            int cc = wn * 32 + ni * 8 + c * 2;
            sm[(size_t)cc * TP + r]           = acc[mi][ni][0];
            sm[(size_t)(cc + 1) * TP + r]     = acc[mi][ni][1];
            sm[(size_t)cc * TP + r + 8]       = acc[mi][ni][2];
            sm[(size_t)(cc + 1) * TP + r + 8] = acc[mi][ni][3];
        }
    __syncthreads();
#pragma unroll
    for (int i = 0; i < 16; i++) {
        int v = tid + i * 256;
        int j = v >> 5, col = (v & 31) * 4;
        float4 q = *reinterpret_cast<const float4*>(&sm[(size_t)j * TP + col]);
        *reinterpret_cast<float4*>(&C[(size_t)(bn0 + j) * N_NODES + bm0 + col]) = q;
    }
}

// ---------------- stream/event singletons --------------------------------------
struct AuxRes {
    cudaStream_t s2;
    cudaEvent_t  evFork, evX, evJoin;
    AuxRes() {
        cudaStreamCreateWithFlags(&s2, cudaStreamNonBlocking);
        cudaEventCreateWithFlags(&evFork, cudaEventDisableTiming);
        cudaEventCreateWithFlags(&evX, cudaEventDisableTiming);
        cudaEventCreateWithFlags(&evJoin, cudaEventDisableTiming);
    }
};

// ---------------- launch --------------------------------------------------------
extern "C" void kernel_launch(void* const* d_in, const int* in_sizes, int n_in,
                              void* d_out, int out_size) {
    static AuxRes aux;

    const float* x  = (const float*)d_in[0];
    const float* W1 = (const float*)d_in[1];
    const float* W2 = (const float*)d_in[2];
    const float* ew = (const float*)d_in[3];
    const int*   ei = (const int*)d_in[4];

    float* out  = (float*)d_out;
    float* abar = out;
    float* z    = out + (size_t)N_NODES * N_NODES;

    __half *xh, *s1h, *h1h, *s2h, *w1t, *w2t, *zrh;
    cudaGetSymbolAddress((void**)&xh,  g_xh);
    cudaGetSymbolAddress((void**)&s1h, g_s1h);
    cudaGetSymbolAddress((void**)&h1h, g_h1h);
    cudaGetSymbolAddress((void**)&s2h, g_s2h);
    cudaGetSymbolAddress((void**)&w1t, g_w1t);
    cudaGetSymbolAddress((void**)&w2t, g_w2t);
    cudaGetSymbolAddress((void**)&zrh, g_zrh);

    constexpr int SM_G1  = 4 * (128 * 40 + 128 * 40) * 2;  // 81920
    constexpr int SM_G2  = 2 * (128 * 40 + 64 * 40) * 2;   // 30720
    constexpr int SM_ZZT = 69632;

    cudaFuncSetAttribute(k_gemm1hh,
                         cudaFuncAttributeMaxDynamicSharedMemorySize, SM_G1);
    cudaFuncSetAttribute(k_gemm2h,
                         cudaFuncAttributeMaxDynamicSharedMemorySize, SM_G2);
    cudaFuncSetAttribute(k_zzt_h,
                         cudaFuncAttributeMaxDynamicSharedMemorySize, SM_ZZT);

    // fork: side stream does x->fp16 convert then CSR chain
    cudaEventRecord(aux.evFork, 0);
    cudaStreamWaitEvent(aux.s2, aux.evFork, 0);

    k_transpose_h<<<dim3(H1_DIM / 32, F_IN / 32), dim3(32, 8)>>>(      // 1 (main)
        W1, w1t, F_IN, H1_DIM);
    k_x2h<<<N_NODES * F_IN / 4 / 256, 256, 0, aux.s2>>>(               // 2 (s2)
        (const float4*)x, (uint2*)xh);
    cudaEventRecord(aux.evX, aux.s2);
    k_transpose_h<<<dim3(NZ_DIM / 32, H1_DIM / 32), dim3(32, 8)>>>(    // 3 (main)
        W2, w2t, H1_DIM, NZ_DIM);

    cudaStreamWaitEvent(0, aux.evX, 0);
    k_gemm1hh<<<dim3(H1_DIM / 128, N_NODES / 128), 256, SM_G1>>>(      // 4 (main)
        xh, w1t, s1h);

    k_zero_counts<<<N_NODES / 1024, 256, 0, aux.s2>>>();               // (s2)
    k_hist<<<E_EDGES / 256, 256, 0, aux.s2>>>(ei);                     // (s2)
    k_scan<<<1, 256, 0, aux.s2>>>();                                   // (s2)
    k_scatter<<<E_EDGES / 256, 256, 0, aux.s2>>>(ei, ew);              // (s2)

    cudaEventRecord(aux.evJoin, aux.s2);
    cudaStreamWaitEvent(0, aux.evJoin, 0);

    k_spmm_relu_256h2<<<N_NODES / 2, 256>>>(                           // (main)
        (const __half2*)s1h, (__half2*)h1h);
    k_gemm2h<<<dim3(1, N_NODES / 128), 256, SM_G2>>>(h1h, w2t, s2h);   // (main)
    k_spmm_relu_64h2<<<N_NODES / 8, 256>>>(                            // (main)
        (const __half2*)s2h, (float2*)z, (__half2*)zrh);
    const int ntile = N_NODES / 128;
    k_zzt_h<<<ntile * (ntile + 1) / 2, 256, SM_ZZT>>>(zrh, abar);      // (main)
}

// round 11
// speedup vs baseline: 1.3950x; 1.0069x over previous
#include <cuda_runtime.h>
#include <cuda_fp16.h>
#include <cstdint>
#include <cstddef>

#define N_NODES 16384
#define E_EDGES 262144
#define F_IN    1024
#define H1_DIM  256
#define NZ_DIM  64

// ---------------- scratch ----------------------------------------------------
__device__ __half g_xh [N_NODES * F_IN];     // x fp16 (32 MB)
__device__ __half g_s1h[N_NODES * H1_DIM];   // support1 (fp16)
__device__ __half g_h1h[N_NODES * H1_DIM];   // hidden1  (fp16)
__device__ __half g_s2h[N_NODES * NZ_DIM];   // support2 (fp16)
__device__ __half g_w1t[H1_DIM * F_IN];      // W1^T fp16
__device__ __half g_w2t[NZ_DIM * H1_DIM];    // W2^T fp16
__device__ __half g_zrh[N_NODES * NZ_DIM];   // z fp16 (zzt operand)
__device__ int    g_off   [N_NODES + 1];
__device__ int    g_cursor[N_NODES];
__device__ int2   g_srcw  [E_EDGES];

// ---------------- helpers -----------------------------------------------------
__device__ __forceinline__ void cp16(uint32_t s, const void* g) {
    asm volatile("cp.async.cg.shared.global [%0], [%1], 16;\n" ::"r"(s), "l"(g));
}
__device__ __forceinline__ void cp_commit() {
    asm volatile("cp.async.commit_group;\n");
}
template <int N>
__device__ __forceinline__ void cp_wait() {
    asm volatile("cp.async.wait_group %0;\n" ::"n"(N));
}
__device__ __forceinline__ uint32_t pack_h2(float lo, float hi) {
    __half2 h = __floats2half2_rn(lo, hi);
    return *reinterpret_cast<uint32_t*>(&h);
}
__device__ __forceinline__ void mma_f16(float (&d)[4], const uint32_t (&a)[4],
                                        const uint32_t (&b)[2]) {
    asm volatile(
        "mma.sync.aligned.m16n8k16.row.col.f32.f16.f16.f32 "
        "{%0,%1,%2,%3}, {%4,%5,%6,%7}, {%8,%9}, {%0,%1,%2,%3};"
        : "+f"(d[0]), "+f"(d[1]), "+f"(d[2]), "+f"(d[3])
        : "r"(a[0]), "r"(a[1]), "r"(a[2]), "r"(a[3]), "r"(b[0]), "r"(b[1]));
}
__device__ __forceinline__ void ldsm_x4(uint32_t& r0, uint32_t& r1,
                                        uint32_t& r2, uint32_t& r3, uint32_t a) {
    asm volatile("ldmatrix.sync.aligned.m8n8.x4.shared.b16 {%0,%1,%2,%3}, [%4];"
                 : "=r"(r0), "=r"(r1), "=r"(r2), "=r"(r3) : "r"(a));
}

// ---------------- x -> fp16 convert --------------------------------------------
__global__ void k_x2h(const float4* __restrict__ in, uint2* __restrict__ out) {
    int i = blockIdx.x * blockDim.x + threadIdx.x;
    float4 v = in[i];
    out[i] = make_uint2(pack_h2(v.x, v.y), pack_h2(v.z, v.w));
}

// ---------------- CSR build ----------------------------------------------------
__global__ void k_zero_counts() {
    int i = blockIdx.x * blockDim.x + threadIdx.x;
    ((int4*)g_cursor)[i] = make_int4(0, 0, 0, 0);
}
__global__ void k_hist(const int* __restrict__ ei) {
    int e = blockIdx.x * blockDim.x + threadIdx.x;
    if (e < E_EDGES) atomicAdd(&g_cursor[ei[E_EDGES + e]], 1);
}
__global__ void k_scan() {
    __shared__ int part[256];
    const int t = threadIdx.x;
    const int base = t * (N_NODES / 256);
    int s = 0;
#pragma unroll
    for (int j = 0; j < N_NODES / 256; j++) s += g_cursor[base + j];
    part[t] = s;
    __syncthreads();
    for (int off = 1; off < 256; off <<= 1) {
        int v = (t >= off) ? part[t - off] : 0;
        __syncthreads();
        part[t] += v;
        __syncthreads();
    }
    int run = part[t] - s;
#pragma unroll
    for (int j = 0; j < N_NODES / 256; j++) {
        int idx = base + j;
        int c = g_cursor[idx];
        g_off[idx] = run;
        g_cursor[idx] = run;
        run += c;
    }
    if (t == 255) g_off[N_NODES] = run;
}
__global__ void k_scatter(const int* __restrict__ ei, const float* __restrict__ ew) {
    int e = blockIdx.x * blockDim.x + threadIdx.x;
    if (e < E_EDGES) {
        int d = ei[E_EDGES + e];
        int p = atomicAdd(&g_cursor[d], 1);
        g_srcw[p] = make_int2(ei[e], __float_as_int(ew[e]));
    }
}

// ---------------- weight transpose -> fp16 -------------------------------------
__global__ void k_transpose_h(const float* __restrict__ in, __half* __restrict__ out,
                              int R, int C) {
    __shared__ float tile[32][33];
    const int bx = blockIdx.x * 32;
    const int by = blockIdx.y * 32;
    const int x = threadIdx.x, y0 = threadIdx.y;
#pragma unroll
    for (int j = y0; j < 32; j += 8)
        tile[j][x] = in[(size_t)(by + j) * C + bx + x];
    __syncthreads();
#pragma unroll
    for (int j = y0; j < 32; j += 8)
        out[(size_t)(bx + j) * R + by + x] = __float2half_rn(tile[x][j]);
}

// ---------------- SpMM + ReLU (half2 lanes, fp32 accumulate) -------------------
__global__ void __launch_bounds__(256) k_spmm_relu_256h2(
    const __half2* __restrict__ in2, __half2* __restrict__ out2) {
    __shared__ int2 se[2][128];
    __shared__ int sdeg[2];
    const int t    = threadIdx.x;
    const int sub  = t >> 7;
    const int lane = t & 127;
    const int row  = blockIdx.x * 2 + sub;
    if (t < 2) sdeg[t] = g_off[blockIdx.x * 2 + t + 1] - g_off[blockIdx.x * 2 + t];
    __syncthreads();
    const int beg = g_off[row];
    const int deg = sdeg[sub];
    const int nch = (max(sdeg[0], sdeg[1]) + 127) >> 7;
    float ax = 0.f, ay = 0.f;
    for (int ch = 0; ch < nch; ch++) {
        int m = min(128, deg - ch * 128);
        __syncthreads();
        if (lane < m) se[sub][lane] = g_srcw[beg + ch * 128 + lane];
        __syncthreads();
        int j = 0;
        for (; j + 8 <= m; j += 8) {
            int2 v[8];
            float2 f[8];
#pragma unroll
            for (int u = 0; u < 8; u++) v[u] = se[sub][j + u];
#pragma unroll
            for (int u = 0; u < 8; u++)
                f[u] = __half22float2(__ldg(&in2[(size_t)v[u].x * 128 + lane]));
#pragma unroll
            for (int u = 0; u < 8; u++) {
                float w = __int_as_float(v[u].y);
                ax += w * f[u].x;
                ay += w * f[u].y;
            }
        }
        for (; j < m; j++) {
            int2 v = se[sub][j];
            float2 f = __half22float2(__ldg(&in2[(size_t)v.x * 128 + lane]));
            float w = __int_as_float(v.y);
            ax += w * f.x;
            ay += w * f.y;
        }
    }
    out2[(size_t)row * 128 + lane] = __floats2half2_rn(fmaxf(ax, 0.f), fmaxf(ay, 0.f));
}

__global__ void __launch_bounds__(256) k_spmm_relu_64h2(
    const __half2* __restrict__ in2, float2* __restrict__ out2,
    __half2* __restrict__ outr2) {
    __shared__ int2 se[8][32];
    __shared__ int sdeg[8];
    const int t    = threadIdx.x;
    const int sub  = t >> 5;
    const int lane = t & 31;
    const int row  = blockIdx.x * 8 + sub;
    if (t < 8) sdeg[t] = g_off[blockIdx.x * 8 + t + 1] - g_off[blockIdx.x * 8 + t];
    __syncthreads();
    const int beg = g_off[row];
    const int deg = sdeg[sub];
    int mx = sdeg[0];
#pragma unroll
    for (int q = 1; q < 8; q++) mx = max(mx, sdeg[q]);
    const int nch = (mx + 31) >> 5;
    float ax = 0.f, ay = 0.f;
    for (int ch = 0; ch < nch; ch++) {
        int m = min(32, deg - ch * 32);
        __syncthreads();
        if (lane < m) se[sub][lane] = g_srcw[beg + ch * 32 + lane];
        __syncthreads();
        int j = 0;
        for (; j + 8 <= m; j += 8) {
            int2 v[8];
            float2 f[8];
#pragma unroll
            for (int u = 0; u < 8; u++) v[u] = se[sub][j + u];
#pragma unroll
            for (int u = 0; u < 8; u++)
                f[u] = __half22float2(__ldg(&in2[(size_t)v[u].x * 32 + lane]));
#pragma unroll
            for (int u = 0; u < 8; u++) {
                float w = __int_as_float(v[u].y);
                ax += w * f[u].x;
                ay += w * f[u].y;
            }
        }
        for (; j < m; j++) {
            int2 v = se[sub][j];
            float2 f = __half22float2(__ldg(&in2[(size_t)v.x * 32 + lane]));
            float w = __int_as_float(v.y);
            ax += w * f.x;
            ay += w * f.y;
        }
    }
    float rx = fmaxf(ax, 0.f), ry = fmaxf(ay, 0.f);
    out2 [(size_t)row * 32 + lane] = make_float2(rx, ry);
    outr2[(size_t)row * 32 + lane] = __floats2half2_rn(rx, ry);
}

// ---------------- gemm1: xh(f16) @ W1t(f16)^T -> support1(f16) ------------------
// BM=128 BN=128 BK=32, 256 thr, warps 4x2 (warp tile 32x64), 4-stage, ldmatrix.
__global__ void __launch_bounds__(256, 2)
k_gemm1hh(const __half* __restrict__ A, const __half* __restrict__ Bt,
          __half* __restrict__ C) {
    constexpr int K = F_IN, Nc = H1_DIM;
    constexpr int P = 40;              // halfs (80B rows, 16B-aligned, conflict-free)
    constexpr int ASZ = 128 * P;       // halfs per stage
    constexpr int BSZ = 128 * P;
    constexpr int STG = 4;
    constexpr int NT = K / 32;

    extern __shared__ __half smh[];
    const uint32_t smem_u32 = (uint32_t)__cvta_generic_to_shared(smh);
    const uint32_t bb0 = smem_u32 + STG * ASZ * 2;

    const int tid  = threadIdx.x;
    const int warp = tid >> 5, lane = tid & 31;
    const int wr = warp >> 1, wc = warp & 1;
    const int bm0 = blockIdx.y * 128, bn0 = blockIdx.x * 128;
    const int g = lane >> 2, c = lane & 3;

    // ldmatrix per-lane byte offsets (within a stage, ks=0)
    const int lr = lane & 7, q = lane >> 3;
    uint32_t offA[2], offB[4];
#pragma unroll
    for (int mi = 0; mi < 2; mi++) {
        int row = wr * 32 + mi * 16 + lr + (q & 1) * 8;
        int col = (q >> 1) * 8;
        offA[mi] = (uint32_t)(row * P + col) * 2u;
    }
#pragma unroll
    for (int ii = 0; ii < 4; ii++) {
        int row = wc * 64 + (2 * ii + (q >> 1)) * 8 + lr;
        int col = (q & 1) * 8;
        offB[ii] = (uint32_t)(row * P + col) * 2u;
    }

    float acc[2][8][4];
#pragma unroll
    for (int mi = 0; mi < 2; mi++)
#pragma unroll
        for (int ni = 0; ni < 8; ni++)
#pragma unroll
            for (int j = 0; j < 4; j++) acc[mi][ni][j] = 0.f;

    auto load_tiles = [&](int kt, int st) {
        const __half* Ag = A + (size_t)bm0 * K + kt * 32;
        uint32_t abase = smem_u32 + (uint32_t)(st * ASZ) * 2u;
#pragma unroll
        for (int i = 0; i < 2; i++) {
            int v = tid + i * 256;
            int r = v >> 2, ch = v & 3;
            cp16(abase + (uint32_t)(r * P + ch * 8) * 2u, Ag + (size_t)r * K + ch * 8);
        }
        const __half* Bg = Bt + (size_t)bn0 * K + kt * 32;
        uint32_t bbase = bb0 + (uint32_t)(st * BSZ) * 2u;
#pragma unroll
        for (int i = 0; i < 2; i++) {
            int v = tid + i * 256;
            int r = v >> 2, ch = v & 3;
            cp16(bbase + (uint32_t)(r * P + ch * 8) * 2u, Bg + (size_t)r * K + ch * 8);
        }
    };

    load_tiles(0, 0);
    cp_commit();
    load_tiles(1, 1);
    cp_commit();
    load_tiles(2, 2);
    cp_commit();

    for (int kt = 0; kt < NT; kt++) {
        cp_wait<2>();
        __syncthreads();

        int pf = kt + 3;
        if (pf < NT) load_tiles(pf, pf & 3);
        cp_commit();

        uint32_t abase = smem_u32 + (uint32_t)((kt & 3) * ASZ) * 2u;
        uint32_t bbase = bb0 + (uint32_t)((kt & 3) * BSZ) * 2u;
#pragma unroll
        for (int ks = 0; ks < 2; ks++) {
            const uint32_t kofs = ks * 32;   // 16 halfs
            uint32_t af[2][4];
            uint32_t bf[8][2];
            ldsm_x4(af[0][0], af[0][1], af[0][2], af[0][3], abase + offA[0] + kofs);
            ldsm_x4(af[1][0], af[1][1], af[1][2], af[1][3], abase + offA[1] + kofs);
#pragma unroll
            for (int ii = 0; ii < 4; ii++)
                ldsm_x4(bf[2 * ii][0], bf[2 * ii][1], bf[2 * ii + 1][0],
                        bf[2 * ii + 1][1], bbase + offB[ii] + kofs);
#pragma unroll
            for (int mi = 0; mi < 2; mi++)
#pragma unroll
                for (int ni = 0; ni < 8; ni++)
                    mma_f16(acc[mi][ni], af[mi], bf[ni]);
        }
    }

    __syncthreads();
#pragma unroll
    for (int mi = 0; mi < 2; mi++)
#pragma unroll
        for (int ni = 0; ni < 8; ni++) {
            int r  = bm0 + wr * 32 + mi * 16 + g;
            int cc = bn0 + wc * 64 + ni * 8 + c * 2;
            *reinterpret_cast<uint32_t*>(&C[(size_t)r * Nc + cc]) =
                pack_h2(acc[mi][ni][0], acc[mi][ni][1]);
            *reinterpret_cast<uint32_t*>(&C[(size_t)(r + 8) * Nc + cc]) =
                pack_h2(acc[mi][ni][2], acc[mi][ni][3]);
        }
}

// ---------------- gemm2: h1(f16) @ W2t(f16)^T -> support2(f16), ldmatrix --------
__global__ void __launch_bounds__(256, 2)
k_gemm2h(const __half* __restrict__ A, const __half* __restrict__ Bt,
         __half* __restrict__ C) {
    constexpr int K = H1_DIM, Nc = NZ_DIM;
    constexpr int P = 40;
    constexpr int ASZ = 128 * P, BSZ = 64 * P;
    constexpr int NT = K / 32;

    extern __shared__ __half smh[];
    const uint32_t smem_u32 = (uint32_t)__cvta_generic_to_shared(smh);
    const uint32_t bb0 = smem_u32 + 2 * ASZ * 2;

    const int tid  = threadIdx.x;
    const int warp = tid >> 5, lane = tid & 31;
    const int wr = warp >> 1, wc = warp & 1;
    const int bm0 = blockIdx.y * 128;
    const int g = lane >> 2, c = lane & 3;

    const int lr = lane & 7, q = lane >> 3;
    uint32_t offA[2], offB[2];
#pragma unroll
    for (int mi = 0; mi < 2; mi++) {
        int row = wr * 32 + mi * 16 + lr + (q & 1) * 8;
        int col = (q >> 1) * 8;
        offA[mi] = (uint32_t)(row * P + col) * 2u;
    }
#pragma unroll
    for (int ii = 0; ii < 2; ii++) {
        int row = wc * 32 + (2 * ii + (q >> 1)) * 8 + lr;
        int col = (q & 1) * 8;
        offB[ii] = (uint32_t)(row * P + col) * 2u;
    }

    float acc[2][4][4];
#pragma unroll
    for (int mi = 0; mi < 2; mi++)
#pragma unroll
        for (int ni = 0; ni < 4; ni++)
#pragma unroll
            for (int j = 0; j < 4; j++) acc[mi][ni][j] = 0.f;

    auto load_tiles = [&](int kt, int st) {
        const __half* Ag = A + (size_t)bm0 * K + kt * 32;
        uint32_t abase = smem_u32 + (uint32_t)(st * ASZ) * 2u;
#pragma unroll
        for (int i = 0; i < 2; i++) {
            int v = tid + i * 256;
            int r = v >> 2, ch = v & 3;
            cp16(abase + (uint32_t)(r * P + ch * 8) * 2u, Ag + (size_t)r * K + ch * 8);
        }
        const __half* Bg = Bt + (size_t)(kt * 32);
        uint32_t bbase = bb0 + (uint32_t)(st * BSZ) * 2u;
        {
            int r = tid >> 2, ch = tid & 3;
            cp16(bbase + (uint32_t)(r * P + ch * 8) * 2u, Bg + (size_t)r * K + ch * 8);
        }
    };

    load_tiles(0, 0);
    cp_commit();

    for (int kt = 0; kt < NT; kt++) {
        if (kt + 1 < NT) {
            load_tiles(kt + 1, (kt + 1) & 1);
            cp_commit();
            cp_wait<1>();
        } else {
            cp_wait<0>();
        }
        __syncthreads();

        uint32_t abase = smem_u32 + (uint32_t)((kt & 1) * ASZ) * 2u;
        uint32_t bbase = bb0 + (uint32_t)((kt & 1) * BSZ) * 2u;
#pragma unroll
        for (int ks = 0; ks < 2; ks++) {
            const uint32_t kofs = ks * 32;
            uint32_t af[2][4];
            uint32_t bf[4][2];
            ldsm_x4(af[0][0], af[0][1], af[0][2], af[0][3], abase + offA[0] + kofs);
            ldsm_x4(af[1][0], af[1][1], af[1][2], af[1][3], abase + offA[1] + kofs);
#pragma unroll
            for (int ii = 0; ii < 2; ii++)
                ldsm_x4(bf[2 * ii][0], bf[2 * ii][1], bf[2 * ii + 1][0],
                        bf[2 * ii + 1][1], bbase + offB[ii] + kofs);
#pragma unroll
            for (int mi = 0; mi < 2; mi++)
#pragma unroll
                for (int ni = 0; ni < 4; ni++)
                    mma_f16(acc[mi][ni], af[mi], bf[ni]);
        }
        __syncthreads();
    }

#pragma unroll
    for (int mi = 0; mi < 2; mi++)
#pragma unroll
        for (int ni = 0; ni < 4; ni++) {
            int r  = bm0 + wr * 32 + mi * 16 + g;
            int cc = wc * 32 + ni * 8 + c * 2;
            *reinterpret_cast<uint32_t*>(&C[(size_t)r * Nc + cc]) =
                pack_h2(acc[mi][ni][0], acc[mi][ni][1]);
            *reinterpret_cast<uint32_t*>(&C[(size_t)(r + 8) * Nc + cc]) =
                pack_h2(acc[mi][ni][2], acc[mi][ni][3]);
        }
}

// ---------------- z @ z^T (fp16 operands, symmetric triangular grid) -----------
__global__ void __launch_bounds__(256, 2)
k_zzt_h(const __half* __restrict__ Z, float* __restrict__ C) {
    constexpr int P  = 72;    // halfs (144B rows, 16B-aligned)
    constexpr int TP = 132;   // floats (transpose staging)
    extern __shared__ float sm[];
    __half* sAh = (__half*)sm;
    __half* sBh = sAh + 128 * P;
    const uint32_t smem_u32 = (uint32_t)__cvta_generic_to_shared(sm);

    const int tid  = threadIdx.x;
    const int warp = tid >> 5, lane = tid & 31;
    const int wm = warp & 1, wn = warp >> 1;
    const int g = lane >> 2, c = lane & 3;

    int t = blockIdx.x;
    int bi = (int)((sqrtf(8.f * (float)t + 1.f) - 1.f) * 0.5f);
    while ((bi + 1) * (bi + 2) / 2 <= t) bi++;
    while (bi * (bi + 1) / 2 > t) bi--;
    int bj = t - bi * (bi + 1) / 2;
    const int bm0 = bi * 128;
    const int bn0 = bj * 128;

#pragma unroll
    for (int i = 0; i < 4; i++) {
        int v = tid + i * 256;
        int r = v >> 3, ch = v & 7;
        cp16(smem_u32 + (uint32_t)(r * P + ch * 8) * 2u,
             Z + (size_t)(bm0 + r) * NZ_DIM + ch * 8);
    }
#pragma unroll
    for (int i = 0; i < 4; i++) {
        int v = tid + i * 256;
        int r = v >> 3, ch = v & 7;
        cp16(smem_u32 + (uint32_t)(128 * P + r * P + ch * 8) * 2u,
             Z + (size_t)(bn0 + r) * NZ_DIM + ch * 8);
    }
    cp_commit();
    cp_wait<0>();
    __syncthreads();

    float acc[4][4][4];
#pragma unroll
    for (int mi = 0; mi < 4; mi++)
#pragma unroll
        for (int ni = 0; ni < 4; ni++)
#pragma unroll
            for (int j = 0; j < 4; j++) acc[mi][ni][j] = 0.f;

#pragma unroll
    for (int ks = 0; ks < 4; ks++) {
        const int k0 = ks * 16;
        uint32_t af[4][4];
        uint32_t bf[4][2];
#pragma unroll
        for (int mi = 0; mi < 4; mi++) {
            int r = wm * 64 + mi * 16 + g;
            af[mi][0] = *reinterpret_cast<const uint32_t*>(&sAh[r * P + k0 + 2 * c]);
            af[mi][1] = *reinterpret_cast<const uint32_t*>(&sAh[(r + 8) * P + k0 + 2 * c]);
            af[mi][2] = *reinterpret_cast<const uint32_t*>(&sAh[r * P + k0 + 2 * c + 8]);
            af[mi][3] = *reinterpret_cast<const uint32_t*>(&sAh[(r + 8) * P + k0 + 2 * c + 8]);
        }
#pragma unroll
        for (int ni = 0; ni < 4; ni++) {
            int n = wn * 32 + ni * 8 + g;
            bf[ni][0] = *reinterpret_cast<const uint32_t*>(&sBh[n * P + k0 + 2 * c]);
            bf[ni][1] = *reinterpret_cast<const uint32_t*>(&sBh[n * P + k0 + 2 * c + 8]);
        }
#pragma unroll
        for (int mi = 0; mi < 4; mi++)
#pragma unroll
            for (int ni = 0; ni < 4; ni++)
                mma_f16(acc[mi][ni], af[mi], bf[ni]);
    }

#pragma unroll
    for (int mi = 0; mi < 4; mi++)
#pragma unroll
        for (int ni = 0; ni < 4; ni++) {
            int r  = bm0 + wm * 64 + mi * 16 + g;
            int cc = bn0 + wn * 32 + ni * 8 + c * 2;
            *reinterpret_cast<float2*>(&C[(size_t)r * N_NODES + cc]) =
                make_float2(acc[mi][ni][0], acc[mi][ni][1]);
            *reinterpret_cast<float2*>(&C[(size_t)(r + 8) * N_NODES + cc]) =
                make_float2(acc[mi][ni][2], acc[mi][ni][3]);
        }

    if (bi == bj) return;

    __syncthreads();
#pragma unroll
    for (int mi = 0; mi < 4; mi++)
#pragma unroll
        for (int ni = 0; ni < 4; ni++) {
            int r  = wm * 64 + mi * 16 + g;
            int cc = wn * 32 + ni * 8 + c * 2;
            sm[(size_t)cc * TP + r]           = acc[mi][ni][0];
            sm[(size_t)(cc + 1) * TP + r]     = acc[mi][ni][1];
            sm[(size_t)cc * TP + r + 8]       = acc[mi][ni][2];
            sm[(size_t)(cc + 1) * TP + r + 8] = acc[mi][ni][3];
        }
    __syncthreads();
#pragma unroll
    for (int i = 0; i < 16; i++) {
        int v = tid + i * 256;
        int j = v >> 5, col = (v & 31) * 4;
        float4 qv = *reinterpret_cast<const float4*>(&sm[(size_t)j * TP + col]);
        *reinterpret_cast<float4*>(&C[(size_t)(bn0 + j) * N_NODES + bm0 + col]) = qv;
    }
}

// ---------------- stream/event singletons --------------------------------------
struct AuxRes {
    cudaStream_t s2;
    cudaEvent_t  evFork, evX, evJoin;
    AuxRes() {
        cudaStreamCreateWithFlags(&s2, cudaStreamNonBlocking);
        cudaEventCreateWithFlags(&evFork, cudaEventDisableTiming);
        cudaEventCreateWithFlags(&evX, cudaEventDisableTiming);
        cudaEventCreateWithFlags(&evJoin, cudaEventDisableTiming);
    }
};

// ---------------- launch --------------------------------------------------------
extern "C" void kernel_launch(void* const* d_in, const int* in_sizes, int n_in,
                              void* d_out, int out_size) {
    static AuxRes aux;

    const float* x  = (const float*)d_in[0];
    const float* W1 = (const float*)d_in[1];
    const float* W2 = (const float*)d_in[2];
    const float* ew = (const float*)d_in[3];
    const int*   ei = (const int*)d_in[4];

    float* out  = (float*)d_out;
    float* abar = out;
    float* z    = out + (size_t)N_NODES * N_NODES;

    __half *xh, *s1h, *h1h, *s2h, *w1t, *w2t, *zrh;
    cudaGetSymbolAddress((void**)&xh,  g_xh);
    cudaGetSymbolAddress((void**)&s1h, g_s1h);
    cudaGetSymbolAddress((void**)&h1h, g_h1h);
    cudaGetSymbolAddress((void**)&s2h, g_s2h);
    cudaGetSymbolAddress((void**)&w1t, g_w1t);
    cudaGetSymbolAddress((void**)&w2t, g_w2t);
    cudaGetSymbolAddress((void**)&zrh, g_zrh);

    constexpr int SM_G1  = 4 * (128 * 40 + 128 * 40) * 2;  // 81920
    constexpr int SM_G2  = 2 * (128 * 40 + 64 * 40) * 2;   // 30720
    constexpr int SM_ZZT = 69632;

    cudaFuncSetAttribute(k_gemm1hh,
                         cudaFuncAttributeMaxDynamicSharedMemorySize, SM_G1);
    cudaFuncSetAttribute(k_gemm2h,
                         cudaFuncAttributeMaxDynamicSharedMemorySize, SM_G2);
    cudaFuncSetAttribute(k_zzt_h,
                         cudaFuncAttributeMaxDynamicSharedMemorySize, SM_ZZT);

    // fork: side stream does x->fp16 convert then CSR chain
    cudaEventRecord(aux.evFork, 0);
    cudaStreamWaitEvent(aux.s2, aux.evFork, 0);

    k_transpose_h<<<dim3(H1_DIM / 32, F_IN / 32), dim3(32, 8)>>>(      // main
        W1, w1t, F_IN, H1_DIM);
    k_x2h<<<N_NODES * F_IN / 4 / 256, 256, 0, aux.s2>>>(               // s2
        (const float4*)x, (uint2*)xh);
    cudaEventRecord(aux.evX, aux.s2);
    k_transpose_h<<<dim3(NZ_DIM / 32, H1_DIM / 32), dim3(32, 8)>>>(    // main
        W2, w2t, H1_DIM, NZ_DIM);

    cudaStreamWaitEvent(0, aux.evX, 0);
    k_gemm1hh<<<dim3(H1_DIM / 128, N_NODES / 128), 256, SM_G1>>>(      // main
        xh, w1t, s1h);

    k_zero_counts<<<N_NODES / 1024, 256, 0, aux.s2>>>();               // s2
    k_hist<<<E_EDGES / 256, 256, 0, aux.s2>>>(ei);                     // s2
    k_scan<<<1, 256, 0, aux.s2>>>();                                   // s2
    k_scatter<<<E_EDGES / 256, 256, 0, aux.s2>>>(ei, ew);              // s2

    cudaEventRecord(aux.evJoin, aux.s2);
    cudaStreamWaitEvent(0, aux.evJoin, 0);

    k_spmm_relu_256h2<<<N_NODES / 2, 256>>>(                           // main
        (const __half2*)s1h, (__half2*)h1h);
    k_gemm2h<<<dim3(1, N_NODES / 128), 256, SM_G2>>>(h1h, w2t, s2h);   // main
    k_spmm_relu_64h2<<<N_NODES / 8, 256>>>(                            // main
        (const __half2*)s2h, (float2*)z, (__half2*)zrh);
    const int ntile = N_NODES / 128;
    k_zzt_h<<<ntile * (ntile + 1) / 2, 256, SM_ZZT>>>(zrh, abar);      // main
}

// round 12
// speedup vs baseline: 1.4047x; 1.0069x over previous
#include <cuda_runtime.h>
#include <cuda_fp16.h>
#include <cstdint>
#include <cstddef>

#define N_NODES 16384
#define E_EDGES 262144
#define F_IN    1024
#define H1_DIM  256
#define NZ_DIM  64

// ---------------- scratch ----------------------------------------------------
__device__ __half g_xh [N_NODES * F_IN];     // x fp16 (32 MB)
__device__ __half g_s1h[N_NODES * H1_DIM];   // support1 (fp16)
__device__ __half g_h1h[N_NODES * H1_DIM];   // hidden1  (fp16)
__device__ __half g_s2h[N_NODES * NZ_DIM];   // support2 (fp16)
__device__ __half g_w1t[H1_DIM * F_IN];      // W1^T fp16
__device__ __half g_w2t[NZ_DIM * H1_DIM];    // W2^T fp16
__device__ __half g_zrh[N_NODES * NZ_DIM];   // z fp16 (zzt operand)
__device__ int    g_off   [N_NODES + 1];
__device__ int    g_cursor[N_NODES];
__device__ int2   g_srcw  [E_EDGES];

// ---------------- helpers -----------------------------------------------------
__device__ __forceinline__ void cp16(uint32_t s, const void* g) {
    asm volatile("cp.async.cg.shared.global [%0], [%1], 16;\n" ::"r"(s), "l"(g));
}
__device__ __forceinline__ void cp_commit() {
    asm volatile("cp.async.commit_group;\n");
}
template <int N>
__device__ __forceinline__ void cp_wait() {
    asm volatile("cp.async.wait_group %0;\n" ::"n"(N));
}
__device__ __forceinline__ uint32_t pack_h2(float lo, float hi) {
    __half2 h = __floats2half2_rn(lo, hi);
    return *reinterpret_cast<uint32_t*>(&h);
}
__device__ __forceinline__ void mma_f16(float (&d)[4], const uint32_t (&a)[4],
                                        const uint32_t (&b)[2]) {
    asm volatile(
        "mma.sync.aligned.m16n8k16.row.col.f32.f16.f16.f32 "
        "{%0,%1,%2,%3}, {%4,%5,%6,%7}, {%8,%9}, {%0,%1,%2,%3};"
        : "+f"(d[0]), "+f"(d[1]), "+f"(d[2]), "+f"(d[3])
        : "r"(a[0]), "r"(a[1]), "r"(a[2]), "r"(a[3]), "r"(b[0]), "r"(b[1]));
}
__device__ __forceinline__ void ldsm_x4(uint32_t& r0, uint32_t& r1,
                                        uint32_t& r2, uint32_t& r3, uint32_t a) {
    asm volatile("ldmatrix.sync.aligned.m8n8.x4.shared.b16 {%0,%1,%2,%3}, [%4];"
                 : "=r"(r0), "=r"(r1), "=r"(r2), "=r"(r3) : "r"(a));
}
__device__ __forceinline__ void st_cs1(float* p, float v) {
    asm volatile("st.global.cs.f32 [%0], %1;" ::"l"(p), "f"(v) : "memory");
}
__device__ __forceinline__ void st_cs2(float* p, float v0, float v1) {
    asm volatile("st.global.cs.v2.f32 [%0], {%1, %2};"
                 ::"l"(p), "f"(v0), "f"(v1) : "memory");
}

// ---------------- x -> fp16 convert --------------------------------------------
__global__ void k_x2h(const float4* __restrict__ in, uint2* __restrict__ out) {
    int i = blockIdx.x * blockDim.x + threadIdx.x;
    float4 v = in[i];
    out[i] = make_uint2(pack_h2(v.x, v.y), pack_h2(v.z, v.w));
}

// ---------------- CSR build ----------------------------------------------------
__global__ void k_zero_counts() {
    int i = blockIdx.x * blockDim.x + threadIdx.x;
    ((int4*)g_cursor)[i] = make_int4(0, 0, 0, 0);
}
__global__ void k_hist(const int* __restrict__ ei) {
    int e = blockIdx.x * blockDim.x + threadIdx.x;
    if (e < E_EDGES) atomicAdd(&g_cursor[ei[E_EDGES + e]], 1);
}
__global__ void k_scan() {
    __shared__ int part[256];
    const int t = threadIdx.x;
    const int base = t * (N_NODES / 256);
    int s = 0;
#pragma unroll
    for (int j = 0; j < N_NODES / 256; j++) s += g_cursor[base + j];
    part[t] = s;
    __syncthreads();
    for (int off = 1; off < 256; off <<= 1) {
        int v = (t >= off) ? part[t - off] : 0;
        __syncthreads();
        part[t] += v;
        __syncthreads();
    }
    int run = part[t] - s;
#pragma unroll
    for (int j = 0; j < N_NODES / 256; j++) {
        int idx = base + j;
        int c = g_cursor[idx];
        g_off[idx] = run;
        g_cursor[idx] = run;
        run += c;
    }
    if (t == 255) g_off[N_NODES] = run;
}
__global__ void k_scatter(const int* __restrict__ ei, const float* __restrict__ ew) {
    int e = blockIdx.x * blockDim.x + threadIdx.x;
    if (e < E_EDGES) {
        int d = ei[E_EDGES + e];
        int p = atomicAdd(&g_cursor[d], 1);
        g_srcw[p] = make_int2(ei[e], __float_as_int(ew[e]));
    }
}

// ---------------- weight transpose -> fp16 -------------------------------------
__global__ void k_transpose_h(const float* __restrict__ in, __half* __restrict__ out,
                              int R, int C) {
    __shared__ float tile[32][33];
    const int bx = blockIdx.x * 32;
    const int by = blockIdx.y * 32;
    const int x = threadIdx.x, y0 = threadIdx.y;
#pragma unroll
    for (int j = y0; j < 32; j += 8)
        tile[j][x] = in[(size_t)(by + j) * C + bx + x];
    __syncthreads();
#pragma unroll
    for (int j = y0; j < 32; j += 8)
        out[(size_t)(bx + j) * R + by + x] = __float2half_rn(tile[x][j]);
}

// ---------------- SpMM + ReLU (half2 lanes, fp32 accumulate) -------------------
__global__ void __launch_bounds__(256) k_spmm_relu_256h2(
    const __half2* __restrict__ in2, __half2* __restrict__ out2) {
    __shared__ int2 se[2][128];
    __shared__ int sdeg[2];
    const int t    = threadIdx.x;
    const int sub  = t >> 7;
    const int lane = t & 127;
    const int row  = blockIdx.x * 2 + sub;
    if (t < 2) sdeg[t] = g_off[blockIdx.x * 2 + t + 1] - g_off[blockIdx.x * 2 + t];
    __syncthreads();
    const int beg = g_off[row];
    const int deg = sdeg[sub];
    const int nch = (max(sdeg[0], sdeg[1]) + 127) >> 7;
    float ax = 0.f, ay = 0.f;
    for (int ch = 0; ch < nch; ch++) {
        int m = min(128, deg - ch * 128);
        __syncthreads();
        if (lane < m) se[sub][lane] = g_srcw[beg + ch * 128 + lane];
        __syncthreads();
        int j = 0;
        for (; j + 8 <= m; j += 8) {
            int2 v[8];
            float2 f[8];
#pragma unroll
            for (int u = 0; u < 8; u++) v[u] = se[sub][j + u];
#pragma unroll
            for (int u = 0; u < 8; u++)
                f[u] = __half22float2(__ldg(&in2[(size_t)v[u].x * 128 + lane]));
#pragma unroll
            for (int u = 0; u < 8; u++) {
                float w = __int_as_float(v[u].y);
                ax += w * f[u].x;
                ay += w * f[u].y;
            }
        }
        for (; j < m; j++) {
            int2 v = se[sub][j];
            float2 f = __half22float2(__ldg(&in2[(size_t)v.x * 128 + lane]));
            float w = __int_as_float(v.y);
            ax += w * f.x;
            ay += w * f.y;
        }
    }
    out2[(size_t)row * 128 + lane] = __floats2half2_rn(fmaxf(ax, 0.f), fmaxf(ay, 0.f));
}

__global__ void __launch_bounds__(256) k_spmm_relu_64h2(
    const __half2* __restrict__ in2, float2* __restrict__ out2,
    __half2* __restrict__ outr2) {
    __shared__ int2 se[8][32];
    __shared__ int sdeg[8];
    const int t    = threadIdx.x;
    const int sub  = t >> 5;
    const int lane = t & 31;
    const int row  = blockIdx.x * 8 + sub;
    if (t < 8) sdeg[t] = g_off[blockIdx.x * 8 + t + 1] - g_off[blockIdx.x * 8 + t];
    __syncthreads();
    const int beg = g_off[row];
    const int deg = sdeg[sub];
    int mx = sdeg[0];
#pragma unroll
    for (int q = 1; q < 8; q++) mx = max(mx, sdeg[q]);
    const int nch = (mx + 31) >> 5;
    float ax = 0.f, ay = 0.f;
    for (int ch = 0; ch < nch; ch++) {
        int m = min(32, deg - ch * 32);
        __syncthreads();
        if (lane < m) se[sub][lane] = g_srcw[beg + ch * 32 + lane];
        __syncthreads();
        int j = 0;
        for (; j + 8 <= m; j += 8) {
            int2 v[8];
            float2 f[8];
#pragma unroll
            for (int u = 0; u < 8; u++) v[u] = se[sub][j + u];
#pragma unroll
            for (int u = 0; u < 8; u++)
                f[u] = __half22float2(__ldg(&in2[(size_t)v[u].x * 32 + lane]));
#pragma unroll
            for (int u = 0; u < 8; u++) {
                float w = __int_as_float(v[u].y);
                ax += w * f[u].x;
                ay += w * f[u].y;
            }
        }
        for (; j < m; j++) {
            int2 v = se[sub][j];
            float2 f = __half22float2(__ldg(&in2[(size_t)v.x * 32 + lane]));
            float w = __int_as_float(v.y);
            ax += w * f.x;
            ay += w * f.y;
        }
    }
    float rx = fmaxf(ax, 0.f), ry = fmaxf(ay, 0.f);
    out2 [(size_t)row * 32 + lane] = make_float2(rx, ry);
    outr2[(size_t)row * 32 + lane] = __floats2half2_rn(rx, ry);
}

// ---------------- gemm1: xh(f16) @ W1t(f16)^T -> support1(f16) ------------------
// BM=128 BN=128 BK=32, 256 thr, warps 4x2, 4-stage, batched ldmatrix per kt.
__global__ void __launch_bounds__(256, 2)
k_gemm1hh(const __half* __restrict__ A, const __half* __restrict__ Bt,
          __half* __restrict__ C) {
    constexpr int K = F_IN, Nc = H1_DIM;
    constexpr int P = 40;              // halfs (80B rows, 16B-aligned, conflict-free)
    constexpr int ASZ = 128 * P;       // halfs per stage
    constexpr int BSZ = 128 * P;
    constexpr int STG = 4;
    constexpr int NT = K / 32;

    extern __shared__ __half smh[];
    const uint32_t smem_u32 = (uint32_t)__cvta_generic_to_shared(smh);
    const uint32_t bb0 = smem_u32 + STG * ASZ * 2;

    const int tid  = threadIdx.x;
    const int warp = tid >> 5, lane = tid & 31;
    const int wr = warp >> 1, wc = warp & 1;
    const int bm0 = blockIdx.y * 128, bn0 = blockIdx.x * 128;
    const int g = lane >> 2, c = lane & 3;

    const int lr = lane & 7, q = lane >> 3;
    uint32_t offA[2], offB[4];
#pragma unroll
    for (int mi = 0; mi < 2; mi++) {
        int row = wr * 32 + mi * 16 + lr + (q & 1) * 8;
        int col = (q >> 1) * 8;
        offA[mi] = (uint32_t)(row * P + col) * 2u;
    }
#pragma unroll
    for (int ii = 0; ii < 4; ii++) {
        int row = wc * 64 + (2 * ii + (q >> 1)) * 8 + lr;
        int col = (q & 1) * 8;
        offB[ii] = (uint32_t)(row * P + col) * 2u;
    }

    float acc[2][8][4];
#pragma unroll
    for (int mi = 0; mi < 2; mi++)
#pragma unroll
        for (int ni = 0; ni < 8; ni++)
#pragma unroll
            for (int j = 0; j < 4; j++) acc[mi][ni][j] = 0.f;

    auto load_tiles = [&](int kt, int st) {
        const __half* Ag = A + (size_t)bm0 * K + kt * 32;
        uint32_t abase = smem_u32 + (uint32_t)(st * ASZ) * 2u;
#pragma unroll
        for (int i = 0; i < 2; i++) {
            int v = tid + i * 256;
            int r = v >> 2, ch = v & 3;
            cp16(abase + (uint32_t)(r * P + ch * 8) * 2u, Ag + (size_t)r * K + ch * 8);
        }
        const __half* Bg = Bt + (size_t)bn0 * K + kt * 32;
        uint32_t bbase = bb0 + (uint32_t)(st * BSZ) * 2u;
#pragma unroll
        for (int i = 0; i < 2; i++) {
            int v = tid + i * 256;
            int r = v >> 2, ch = v & 3;
            cp16(bbase + (uint32_t)(r * P + ch * 8) * 2u, Bg + (size_t)r * K + ch * 8);
        }
    };

    load_tiles(0, 0);
    cp_commit();
    load_tiles(1, 1);
    cp_commit();
    load_tiles(2, 2);
    cp_commit();

    for (int kt = 0; kt < NT; kt++) {
        cp_wait<2>();
        __syncthreads();

        int pf = kt + 3;
        if (pf < NT) load_tiles(pf, pf & 3);
        cp_commit();

        uint32_t abase = smem_u32 + (uint32_t)((kt & 3) * ASZ) * 2u;
        uint32_t bbase = bb0 + (uint32_t)((kt & 3) * BSZ) * 2u;

        // batch ALL fragment loads for the whole kt (both ks halves)
        uint32_t af[2][2][4];
        uint32_t bf[2][8][2];
#pragma unroll
        for (int ks = 0; ks < 2; ks++) {
            const uint32_t kofs = ks * 32;   // 16 halfs
            ldsm_x4(af[ks][0][0], af[ks][0][1], af[ks][0][2], af[ks][0][3],
                    abase + offA[0] + kofs);
            ldsm_x4(af[ks][1][0], af[ks][1][1], af[ks][1][2], af[ks][1][3],
                    abase + offA[1] + kofs);
#pragma unroll
            for (int ii = 0; ii < 4; ii++)
                ldsm_x4(bf[ks][2 * ii][0], bf[ks][2 * ii][1],
                        bf[ks][2 * ii + 1][0], bf[ks][2 * ii + 1][1],
                        bbase + offB[ii] + kofs);
        }
#pragma unroll
        for (int ks = 0; ks < 2; ks++)
#pragma unroll
            for (int mi = 0; mi < 2; mi++)
#pragma unroll
                for (int ni = 0; ni < 8; ni++)
                    mma_f16(acc[mi][ni], af[ks][mi], bf[ks][ni]);
    }

    __syncthreads();
#pragma unroll
    for (int mi = 0; mi < 2; mi++)
#pragma unroll
        for (int ni = 0; ni < 8; ni++) {
            int r  = bm0 + wr * 32 + mi * 16 + g;
            int cc = bn0 + wc * 64 + ni * 8 + c * 2;
            *reinterpret_cast<uint32_t*>(&C[(size_t)r * Nc + cc]) =
                pack_h2(acc[mi][ni][0], acc[mi][ni][1]);
            *reinterpret_cast<uint32_t*>(&C[(size_t)(r + 8) * Nc + cc]) =
                pack_h2(acc[mi][ni][2], acc[mi][ni][3]);
        }
}

// ---------------- gemm2: h1(f16) @ W2t(f16)^T -> support2(f16), ldmatrix --------
__global__ void __launch_bounds__(256, 2)
k_gemm2h(const __half* __restrict__ A, const __half* __restrict__ Bt,
         __half* __restrict__ C) {
    constexpr int K = H1_DIM, Nc = NZ_DIM;
    constexpr int P = 40;
    constexpr int ASZ = 128 * P, BSZ = 64 * P;
    constexpr int NT = K / 32;

    extern __shared__ __half smh[];
    const uint32_t smem_u32 = (uint32_t)__cvta_generic_to_shared(smh);
    const uint32_t bb0 = smem_u32 + 2 * ASZ * 2;

    const int tid  = threadIdx.x;
    const int warp = tid >> 5, lane = tid & 31;
    const int wr = warp >> 1, wc = warp & 1;
    const int bm0 = blockIdx.y * 128;
    const int g = lane >> 2, c = lane & 3;

    const int lr = lane & 7, q = lane >> 3;
    uint32_t offA[2], offB[2];
#pragma unroll
    for (int mi = 0; mi < 2; mi++) {
        int row = wr * 32 + mi * 16 + lr + (q & 1) * 8;
        int col = (q >> 1) * 8;
        offA[mi] = (uint32_t)(row * P + col) * 2u;
    }
#pragma unroll
    for (int ii = 0; ii < 2; ii++) {
        int row = wc * 32 + (2 * ii + (q >> 1)) * 8 + lr;
        int col = (q & 1) * 8;
        offB[ii] = (uint32_t)(row * P + col) * 2u;
    }

    float acc[2][4][4];
#pragma unroll
    for (int mi = 0; mi < 2; mi++)
#pragma unroll
        for (int ni = 0; ni < 4; ni++)
#pragma unroll
            for (int j = 0; j < 4; j++) acc[mi][ni][j] = 0.f;

    auto load_tiles = [&](int kt, int st) {
        const __half* Ag = A + (size_t)bm0 * K + kt * 32;
        uint32_t abase = smem_u32 + (uint32_t)(st * ASZ) * 2u;
#pragma unroll
        for (int i = 0; i < 2; i++) {
            int v = tid + i * 256;
            int r = v >> 2, ch = v & 3;
            cp16(abase + (uint32_t)(r * P + ch * 8) * 2u, Ag + (size_t)r * K + ch * 8);
        }
        const __half* Bg = Bt + (size_t)(kt * 32);
        uint32_t bbase = bb0 + (uint32_t)(st * BSZ) * 2u;
        {
            int r = tid >> 2, ch = tid & 3;
            cp16(bbase + (uint32_t)(r * P + ch * 8) * 2u, Bg + (size_t)r * K + ch * 8);
        }
    };

    load_tiles(0, 0);
    cp_commit();

    for (int kt = 0; kt < NT; kt++) {
        if (kt + 1 < NT) {
            load_tiles(kt + 1, (kt + 1) & 1);
            cp_commit();
            cp_wait<1>();
        } else {
            cp_wait<0>();
        }
        __syncthreads();

        uint32_t abase = smem_u32 + (uint32_t)((kt & 1) * ASZ) * 2u;
        uint32_t bbase = bb0 + (uint32_t)((kt & 1) * BSZ) * 2u;
#pragma unroll
        for (int ks = 0; ks < 2; ks++) {
            const uint32_t kofs = ks * 32;
            uint32_t af[2][4];
            uint32_t bf[4][2];
            ldsm_x4(af[0][0], af[0][1], af[0][2], af[0][3], abase + offA[0] + kofs);
            ldsm_x4(af[1][0], af[1][1], af[1][2], af[1][3], abase + offA[1] + kofs);
#pragma unroll
            for (int ii = 0; ii < 2; ii++)
                ldsm_x4(bf[2 * ii][0], bf[2 * ii][1], bf[2 * ii + 1][0],
                        bf[2 * ii + 1][1], bbase + offB[ii] + kofs);
#pragma unroll
            for (int mi = 0; mi < 2; mi++)
#pragma unroll
                for (int ni = 0; ni < 4; ni++)
                    mma_f16(acc[mi][ni], af[mi], bf[ni]);
        }
        __syncthreads();
    }

#pragma unroll
    for (int mi = 0; mi < 2; mi++)
#pragma unroll
        for (int ni = 0; ni < 4; ni++) {
            int r  = bm0 + wr * 32 + mi * 16 + g;
            int cc = wc * 32 + ni * 8 + c * 2;
            *reinterpret_cast<uint32_t*>(&C[(size_t)r * Nc + cc]) =
                pack_h2(acc[mi][ni][0], acc[mi][ni][1]);
            *reinterpret_cast<uint32_t*>(&C[(size_t)(r + 8) * Nc + cc]) =
                pack_h2(acc[mi][ni][2], acc[mi][ni][3]);
        }
}

// ---------------- z @ z^T (fp16 operands, symmetric, streaming stores) ---------
__global__ void __launch_bounds__(256, 2)
k_zzt_h(const __half* __restrict__ Z, float* __restrict__ C) {
    constexpr int P = 72;     // halfs (144B rows, 16B-aligned)
    extern __shared__ __half smz[];
    __half* sAh = smz;
    __half* sBh = smz + 128 * P;
    const uint32_t smem_u32 = (uint32_t)__cvta_generic_to_shared(smz);

    const int tid  = threadIdx.x;
    const int warp = tid >> 5, lane = tid & 31;
    const int wm = warp & 1, wn = warp >> 1;
    const int g = lane >> 2, c = lane & 3;

    int t = blockIdx.x;
    int bi = (int)((sqrtf(8.f * (float)t + 1.f) - 1.f) * 0.5f);
    while ((bi + 1) * (bi + 2) / 2 <= t) bi++;
    while (bi * (bi + 1) / 2 > t) bi--;
    int bj = t - bi * (bi + 1) / 2;
    const int bm0 = bi * 128;
    const int bn0 = bj * 128;

#pragma unroll
    for (int i = 0; i < 4; i++) {
        int v = tid + i * 256;
        int r = v >> 3, ch = v & 7;
        cp16(smem_u32 + (uint32_t)(r * P + ch * 8) * 2u,
             Z + (size_t)(bm0 + r) * NZ_DIM + ch * 8);
    }
#pragma unroll
    for (int i = 0; i < 4; i++) {
        int v = tid + i * 256;
        int r = v >> 3, ch = v & 7;
        cp16(smem_u32 + (uint32_t)(128 * P + r * P + ch * 8) * 2u,
             Z + (size_t)(bn0 + r) * NZ_DIM + ch * 8);
    }
    cp_commit();
    cp_wait<0>();
    __syncthreads();

    float acc[4][4][4];
#pragma unroll
    for (int mi = 0; mi < 4; mi++)
#pragma unroll
        for (int ni = 0; ni < 4; ni++)
#pragma unroll
            for (int j = 0; j < 4; j++) acc[mi][ni][j] = 0.f;

#pragma unroll
    for (int ks = 0; ks < 4; ks++) {
        const int k0 = ks * 16;
        uint32_t af[4][4];
        uint32_t bf[4][2];
#pragma unroll
        for (int mi = 0; mi < 4; mi++) {
            int r = wm * 64 + mi * 16 + g;
            af[mi][0] = *reinterpret_cast<const uint32_t*>(&sAh[r * P + k0 + 2 * c]);
            af[mi][1] = *reinterpret_cast<const uint32_t*>(&sAh[(r + 8) * P + k0 + 2 * c]);
            af[mi][2] = *reinterpret_cast<const uint32_t*>(&sAh[r * P + k0 + 2 * c + 8]);
            af[mi][3] = *reinterpret_cast<const uint32_t*>(&sAh[(r + 8) * P + k0 + 2 * c + 8]);
        }
#pragma unroll
        for (int ni = 0; ni < 4; ni++) {
            int n = wn * 32 + ni * 8 + g;
            bf[ni][0] = *reinterpret_cast<const uint32_t*>(&sBh[n * P + k0 + 2 * c]);
            bf[ni][1] = *reinterpret_cast<const uint32_t*>(&sBh[n * P + k0 + 2 * c + 8]);
        }
#pragma unroll
        for (int mi = 0; mi < 4; mi++)
#pragma unroll
            for (int ni = 0; ni < 4; ni++)
                mma_f16(acc[mi][ni], af[mi], bf[ni]);
    }

    // direct tile store (rows bm0.., cols bn0..) with streaming hint
#pragma unroll
    for (int mi = 0; mi < 4; mi++)
#pragma unroll
        for (int ni = 0; ni < 4; ni++) {
            int r  = bm0 + wm * 64 + mi * 16 + g;
            int cc = bn0 + wn * 32 + ni * 8 + c * 2;
            st_cs2(&C[(size_t)r * N_NODES + cc], acc[mi][ni][0], acc[mi][ni][1]);
            st_cs2(&C[(size_t)(r + 8) * N_NODES + cc], acc[mi][ni][2], acc[mi][ni][3]);
        }

    if (bi == bj) return;

    // transposed tile store (rows bn0.., cols bm0..): scalar streaming stores.
    // each warp-level STG.32 covers 4 full 32B sectors (rows cc/cc+1 x 8 lanes).
#pragma unroll
    for (int mi = 0; mi < 4; mi++)
#pragma unroll
        for (int ni = 0; ni < 4; ni++) {
            int r  = bm0 + wm * 64 + mi * 16 + g;
            int cc = bn0 + wn * 32 + ni * 8 + c * 2;
            st_cs1(&C[(size_t)cc * N_NODES + r],           acc[mi][ni][0]);
            st_cs1(&C[(size_t)(cc + 1) * N_NODES + r],     acc[mi][ni][1]);
            st_cs1(&C[(size_t)cc * N_NODES + r + 8],       acc[mi][ni][2]);
            st_cs1(&C[(size_t)(cc + 1) * N_NODES + r + 8], acc[mi][ni][3]);
        }
}

// ---------------- stream/event singletons --------------------------------------
struct AuxRes {
    cudaStream_t s2;
    cudaEvent_t  evFork, evX, evJoin;
    AuxRes() {
        cudaStreamCreateWithFlags(&s2, cudaStreamNonBlocking);
        cudaEventCreateWithFlags(&evFork, cudaEventDisableTiming);
        cudaEventCreateWithFlags(&evX, cudaEventDisableTiming);
        cudaEventCreateWithFlags(&evJoin, cudaEventDisableTiming);
    }
};

// ---------------- launch --------------------------------------------------------
extern "C" void kernel_launch(void* const* d_in, const int* in_sizes, int n_in,
                              void* d_out, int out_size) {
    static AuxRes aux;

    const float* x  = (const float*)d_in[0];
    const float* W1 = (const float*)d_in[1];
    const float* W2 = (const float*)d_in[2];
    const float* ew = (const float*)d_in[3];
    const int*   ei = (const int*)d_in[4];

    float* out  = (float*)d_out;
    float* abar = out;
    float* z    = out + (size_t)N_NODES * N_NODES;

    __half *xh, *s1h, *h1h, *s2h, *w1t, *w2t, *zrh;
    cudaGetSymbolAddress((void**)&xh,  g_xh);
    cudaGetSymbolAddress((void**)&s1h, g_s1h);
    cudaGetSymbolAddress((void**)&h1h, g_h1h);
    cudaGetSymbolAddress((void**)&s2h, g_s2h);
    cudaGetSymbolAddress((void**)&w1t, g_w1t);
    cudaGetSymbolAddress((void**)&w2t, g_w2t);
    cudaGetSymbolAddress((void**)&zrh, g_zrh);

    constexpr int SM_G1  = 4 * (128 * 40 + 128 * 40) * 2;  // 81920
    constexpr int SM_G2  = 2 * (128 * 40 + 64 * 40) * 2;   // 30720
    constexpr int SM_ZZT = 2 * 128 * 72 * 2;               // 36864

    cudaFuncSetAttribute(k_gemm1hh,
                         cudaFuncAttributeMaxDynamicSharedMemorySize, SM_G1);
    cudaFuncSetAttribute(k_gemm2h,
                         cudaFuncAttributeMaxDynamicSharedMemorySize, SM_G2);
    cudaFuncSetAttribute(k_zzt_h,
                         cudaFuncAttributeMaxDynamicSharedMemorySize, SM_ZZT);

    // fork: side stream does x->fp16 convert then CSR chain
    cudaEventRecord(aux.evFork, 0);
    cudaStreamWaitEvent(aux.s2, aux.evFork, 0);

    k_transpose_h<<<dim3(H1_DIM / 32, F_IN / 32), dim3(32, 8)>>>(      // main
        W1, w1t, F_IN, H1_DIM);
    k_x2h<<<N_NODES * F_IN / 4 / 256, 256, 0, aux.s2>>>(               // s2
        (const float4*)x, (uint2*)xh);
    cudaEventRecord(aux.evX, aux.s2);
    k_transpose_h<<<dim3(NZ_DIM / 32, H1_DIM / 32), dim3(32, 8)>>>(    // main
        W2, w2t, H1_DIM, NZ_DIM);

    cudaStreamWaitEvent(0, aux.evX, 0);
    k_gemm1hh<<<dim3(H1_DIM / 128, N_NODES / 128), 256, SM_G1>>>(      // main
        xh, w1t, s1h);

    k_zero_counts<<<N_NODES / 1024, 256, 0, aux.s2>>>();               // s2
    k_hist<<<E_EDGES / 256, 256, 0, aux.s2>>>(ei);                     // s2
    k_scan<<<1, 256, 0, aux.s2>>>();                                   // s2
    k_scatter<<<E_EDGES / 256, 256, 0, aux.s2>>>(ei, ew);              // s2

    cudaEventRecord(aux.evJoin, aux.s2);
    cudaStreamWaitEvent(0, aux.evJoin, 0);

    k_spmm_relu_256h2<<<N_NODES / 2, 256>>>(                           // main
        (const __half2*)s1h, (__half2*)h1h);
    k_gemm2h<<<dim3(1, N_NODES / 128), 256, SM_G2>>>(h1h, w2t, s2h);   // main
    k_spmm_relu_64h2<<<N_NODES / 8, 256>>>(                            // main
        (const __half2*)s2h, (float2*)z, (__half2*)zrh);
    const int ntile = N_NODES / 128;
    k_zzt_h<<<ntile * (ntile + 1) / 2, 256, SM_ZZT>>>(zrh, abar);      // main
}

// round 13
// speedup vs baseline: 1.4050x; 1.0002x over previous
#include <cuda_runtime.h>
#include <cuda_fp16.h>
#include <cstdint>
#include <cstddef>

#define N_NODES 16384
#define E_EDGES 262144
#define F_IN    1024
#define H1_DIM  256
#define NZ_DIM  64

// ---------------- scratch ----------------------------------------------------
__device__ __half g_xh [N_NODES * F_IN];
__device__ __half g_s1h[N_NODES * H1_DIM];
__device__ __half g_h1h[N_NODES * H1_DIM];
__device__ __half g_s2h[N_NODES * NZ_DIM];
__device__ __half g_w1t[H1_DIM * F_IN];
__device__ __half g_w2t[NZ_DIM * H1_DIM];
__device__ __half g_zrh[N_NODES * NZ_DIM];
__device__ int    g_off   [N_NODES + 1];
__device__ int    g_cursor[N_NODES];
__device__ int2   g_srcw  [E_EDGES];

// ---------------- helpers -----------------------------------------------------
__device__ __forceinline__ void cp16(uint32_t s, const void* g) {
    asm volatile("cp.async.cg.shared.global [%0], [%1], 16;\n" ::"r"(s), "l"(g));
}
__device__ __forceinline__ void cp_commit() {
    asm volatile("cp.async.commit_group;\n");
}
template <int N>
__device__ __forceinline__ void cp_wait() {
    asm volatile("cp.async.wait_group %0;\n" ::"n"(N));
}
__device__ __forceinline__ uint32_t pack_h2(float lo, float hi) {
    __half2 h = __floats2half2_rn(lo, hi);
    return *reinterpret_cast<uint32_t*>(&h);
}
__device__ __forceinline__ void mma_f16(float (&d)[4], const uint32_t (&a)[4],
                                        const uint32_t (&b)[2]) {
    asm volatile(
        "mma.sync.aligned.m16n8k16.row.col.f32.f16.f16.f32 "
        "{%0,%1,%2,%3}, {%4,%5,%6,%7}, {%8,%9}, {%0,%1,%2,%3};"
        : "+f"(d[0]), "+f"(d[1]), "+f"(d[2]), "+f"(d[3])
        : "r"(a[0]), "r"(a[1]), "r"(a[2]), "r"(a[3]), "r"(b[0]), "r"(b[1]));
}
__device__ __forceinline__ void ldsm_x4(uint32_t& r0, uint32_t& r1,
                                        uint32_t& r2, uint32_t& r3, uint32_t a) {
    asm volatile("ldmatrix.sync.aligned.m8n8.x4.shared.b16 {%0,%1,%2,%3}, [%4];"
                 : "=r"(r0), "=r"(r1), "=r"(r2), "=r"(r3) : "r"(a));
}
__device__ __forceinline__ void st_cs1(float* p, float v) {
    asm volatile("st.global.cs.f32 [%0], %1;" ::"l"(p), "f"(v) : "memory");
}
__device__ __forceinline__ void st_cs2(float* p, float v0, float v1) {
    asm volatile("st.global.cs.v2.f32 [%0], {%1, %2};"
                 ::"l"(p), "f"(v0), "f"(v1) : "memory");
}

// ---------------- x -> fp16 convert --------------------------------------------
__global__ void k_x2h(const float4* __restrict__ in, uint2* __restrict__ out) {
    int i = blockIdx.x * blockDim.x + threadIdx.x;
    float4 v = in[i];
    out[i] = make_uint2(pack_h2(v.x, v.y), pack_h2(v.z, v.w));
}

// ---------------- CSR build ----------------------------------------------------
__global__ void k_zero_counts() {
    int i = blockIdx.x * blockDim.x + threadIdx.x;
    ((int4*)g_cursor)[i] = make_int4(0, 0, 0, 0);
}
__global__ void k_hist(const int* __restrict__ ei) {
    int e = blockIdx.x * blockDim.x + threadIdx.x;
    if (e < E_EDGES) atomicAdd(&g_cursor[ei[E_EDGES + e]], 1);
}
__global__ void k_scan() {
    __shared__ int part[256];
    const int t = threadIdx.x;
    const int base = t * (N_NODES / 256);
    int s = 0;
#pragma unroll
    for (int j = 0; j < N_NODES / 256; j++) s += g_cursor[base + j];
    part[t] = s;
    __syncthreads();
    for (int off = 1; off < 256; off <<= 1) {
        int v = (t >= off) ? part[t - off] : 0;
        __syncthreads();
        part[t] += v;
        __syncthreads();
    }
    int run = part[t] - s;
#pragma unroll
    for (int j = 0; j < N_NODES / 256; j++) {
        int idx = base + j;
        int c = g_cursor[idx];
        g_off[idx] = run;
        g_cursor[idx] = run;
        run += c;
    }
    if (t == 255) g_off[N_NODES] = run;
}
__global__ void k_scatter(const int* __restrict__ ei, const float* __restrict__ ew) {
    int e = blockIdx.x * blockDim.x + threadIdx.x;
    if (e < E_EDGES) {
        int d = ei[E_EDGES + e];
        int p = atomicAdd(&g_cursor[d], 1);
        g_srcw[p] = make_int2(ei[e], __float_as_int(ew[e]));
    }
}

// ---------------- weight transpose -> fp16 -------------------------------------
__global__ void k_transpose_h(const float* __restrict__ in, __half* __restrict__ out,
                              int R, int C) {
    __shared__ float tile[32][33];
    const int bx = blockIdx.x * 32;
    const int by = blockIdx.y * 32;
    const int x = threadIdx.x, y0 = threadIdx.y;
#pragma unroll
    for (int j = y0; j < 32; j += 8)
        tile[j][x] = in[(size_t)(by + j) * C + bx + x];
    __syncthreads();
#pragma unroll
    for (int j = y0; j < 32; j += 8)
        out[(size_t)(bx + j) * R + by + x] = __float2half_rn(tile[x][j]);
}

// ---------------- SpMM + ReLU (half2 lanes, fp32 accumulate) -------------------
__global__ void __launch_bounds__(256) k_spmm_relu_256h2(
    const __half2* __restrict__ in2, __half2* __restrict__ out2) {
    __shared__ int2 se[2][128];
    __shared__ int sdeg[2];
    const int t    = threadIdx.x;
    const int sub  = t >> 7;
    const int lane = t & 127;
    const int row  = blockIdx.x * 2 + sub;
    if (t < 2) sdeg[t] = g_off[blockIdx.x * 2 + t + 1] - g_off[blockIdx.x * 2 + t];
    __syncthreads();
    const int beg = g_off[row];
    const int deg = sdeg[sub];
    const int nch = (max(sdeg[0], sdeg[1]) + 127) >> 7;
    float ax = 0.f, ay = 0.f;
    for (int ch = 0; ch < nch; ch++) {
        int m = min(128, deg - ch * 128);
        __syncthreads();
        if (lane < m) se[sub][lane] = g_srcw[beg + ch * 128 + lane];
        __syncthreads();
        int j = 0;
        for (; j + 8 <= m; j += 8) {
            int2 v[8];
            float2 f[8];
#pragma unroll
            for (int u = 0; u < 8; u++) v[u] = se[sub][j + u];
#pragma unroll
            for (int u = 0; u < 8; u++)
                f[u] = __half22float2(__ldg(&in2[(size_t)v[u].x * 128 + lane]));
#pragma unroll
            for (int u = 0; u < 8; u++) {
                float w = __int_as_float(v[u].y);
                ax += w * f[u].x;
                ay += w * f[u].y;
            }
        }
        for (; j < m; j++) {
            int2 v = se[sub][j];
            float2 f = __half22float2(__ldg(&in2[(size_t)v.x * 128 + lane]));
            float w = __int_as_float(v.y);
            ax += w * f.x;
            ay += w * f.y;
        }
    }
    out2[(size_t)row * 128 + lane] = __floats2half2_rn(fmaxf(ax, 0.f), fmaxf(ay, 0.f));
}

__global__ void __launch_bounds__(256) k_spmm_relu_64h2(
    const __half2* __restrict__ in2, float2* __restrict__ out2,
    __half2* __restrict__ outr2) {
    __shared__ int2 se[8][32];
    __shared__ int sdeg[8];
    const int t    = threadIdx.x;
    const int sub  = t >> 5;
    const int lane = t & 31;
    const int row  = blockIdx.x * 8 + sub;
    if (t < 8) sdeg[t] = g_off[blockIdx.x * 8 + t + 1] - g_off[blockIdx.x * 8 + t];
    __syncthreads();
    const int beg = g_off[row];
    const int deg = sdeg[sub];
    int mx = sdeg[0];
#pragma unroll
    for (int q = 1; q < 8; q++) mx = max(mx, sdeg[q]);
    const int nch = (mx + 31) >> 5;
    float ax = 0.f, ay = 0.f;
    for (int ch = 0; ch < nch; ch++) {
        int m = min(32, deg - ch * 32);
        __syncthreads();
        if (lane < m) se[sub][lane] = g_srcw[beg + ch * 32 + lane];
        __syncthreads();
        int j = 0;
        for (; j + 8 <= m; j += 8) {
            int2 v[8];
            float2 f[8];
#pragma unroll
            for (int u = 0; u < 8; u++) v[u] = se[sub][j + u];
#pragma unroll
            for (int u = 0; u < 8; u++)
                f[u] = __half22float2(__ldg(&in2[(size_t)v[u].x * 32 + lane]));
#pragma unroll
            for (int u = 0; u < 8; u++) {
                float w = __int_as_float(v[u].y);
                ax += w * f[u].x;
                ay += w * f[u].y;
            }
        }
        for (; j < m; j++) {
            int2 v = se[sub][j];
            float2 f = __half22float2(__ldg(&in2[(size_t)v.x * 32 + lane]));
            float w = __int_as_float(v.y);
            ax += w * f.x;
            ay += w * f.y;
        }
    }
    float rx = fmaxf(ax, 0.f), ry = fmaxf(ay, 0.f);
    out2 [(size_t)row * 32 + lane] = make_float2(rx, ry);
    outr2[(size_t)row * 32 + lane] = __floats2half2_rn(rx, ry);
}

// ---------------- gemm1: BM=128 BN=128 BK=64, SW128 swizzle, 3 stages -----------
__global__ void __launch_bounds__(256, 2)
k_gemm1hh(const __half* __restrict__ A, const __half* __restrict__ Bt,
          __half* __restrict__ C) {
    constexpr int K = F_IN, Nc = H1_DIM;
    constexpr int STAGE = 16384;       // bytes per tile stage (128 rows x 128B)
    constexpr int STG = 3;
    constexpr int NT = K / 64;

    extern __shared__ __half smh[];
    const uint32_t smem_u32 = (uint32_t)__cvta_generic_to_shared(smh);
    const uint32_t bb0 = smem_u32 + STG * STAGE;

    const int tid  = threadIdx.x;
    const int warp = tid >> 5, lane = tid & 31;
    const int wr = warp >> 1, wc = warp & 1;
    const int bm0 = blockIdx.y * 128, bn0 = blockIdx.x * 128;
    const int g = lane >> 2, c = lane & 3;

    // ldmatrix per-lane: row base + constant XOR mask; k-offset added pre-XOR
    const int lr = lane & 7, q = lane >> 3;
    uint32_t baseA[2], colA, xormA[2];
#pragma unroll
    for (int mi = 0; mi < 2; mi++) {
        int row = wr * 32 + mi * 16 + lr + (q & 1) * 8;
        baseA[mi] = (uint32_t)row * 128u;
        xormA[mi] = (uint32_t)((row & 7) << 4);
    }
    colA = (uint32_t)((q >> 1) * 16);
    uint32_t baseB[4], colB, xormB[4];
#pragma unroll
    for (int ii = 0; ii < 4; ii++) {
        int row = wc * 64 + (2 * ii + (q >> 1)) * 8 + lr;
        baseB[ii] = (uint32_t)row * 128u;
        xormB[ii] = (uint32_t)((row & 7) << 4);
    }
    colB = (uint32_t)((q & 1) * 16);

    float acc[2][8][4];
#pragma unroll
    for (int mi = 0; mi < 2; mi++)
#pragma unroll
        for (int ni = 0; ni < 8; ni++)
#pragma unroll
            for (int j = 0; j < 4; j++) acc[mi][ni][j] = 0.f;

    auto load_tiles = [&](int kt, int st) {
        const __half* Ag = A + (size_t)bm0 * K + kt * 64;
        uint32_t abase = smem_u32 + (uint32_t)(st * STAGE);
#pragma unroll
        for (int i = 0; i < 4; i++) {
            int v = tid + i * 256;
            int r = v >> 3, ch = v & 7;
            uint32_t off = (uint32_t)(r * 128 + ch * 16);
            uint32_t sw  = off ^ (uint32_t)((r & 7) << 4);
            cp16(abase + sw, Ag + (size_t)r * K + ch * 8);
        }
        const __half* Bg = Bt + (size_t)bn0 * K + kt * 64;
        uint32_t bbase = bb0 + (uint32_t)(st * STAGE);
#pragma unroll
        for (int i = 0; i < 4; i++) {
            int v = tid + i * 256;
            int r = v >> 3, ch = v & 7;
            uint32_t off = (uint32_t)(r * 128 + ch * 16);
            uint32_t sw  = off ^ (uint32_t)((r & 7) << 4);
            cp16(bbase + sw, Bg + (size_t)r * K + ch * 8);
        }
    };

    load_tiles(0, 0);
    cp_commit();
    load_tiles(1, 1);
    cp_commit();

    int st = 0;
    for (int kt = 0; kt < NT; kt++) {
        cp_wait<1>();
        __syncthreads();

        int pf = kt + 2;
        if (pf < NT) load_tiles(pf, (st + 2) % STG);
        cp_commit();

        uint32_t abase = smem_u32 + (uint32_t)(st * STAGE);
        uint32_t bbase = bb0 + (uint32_t)(st * STAGE);
#pragma unroll
        for (int ks = 0; ks < 4; ks++) {
            const uint32_t kofs = ks * 32;   // bytes (16 halfs)
            uint32_t af[2][4];
            uint32_t bf[8][2];
#pragma unroll
            for (int mi = 0; mi < 2; mi++)
                ldsm_x4(af[mi][0], af[mi][1], af[mi][2], af[mi][3],
                        abase + baseA[mi] + ((colA + kofs) ^ xormA[mi]));
#pragma unroll
            for (int ii = 0; ii < 4; ii++)
                ldsm_x4(bf[2 * ii][0], bf[2 * ii][1], bf[2 * ii + 1][0],
                        bf[2 * ii + 1][1],
                        bbase + baseB[ii] + ((colB + kofs) ^ xormB[ii]));
#pragma unroll
            for (int mi = 0; mi < 2; mi++)
#pragma unroll
                for (int ni = 0; ni < 8; ni++)
                    mma_f16(acc[mi][ni], af[mi], bf[ni]);
        }
        st = (st + 1) % STG;
    }

    __syncthreads();
#pragma unroll
    for (int mi = 0; mi < 2; mi++)
#pragma unroll
        for (int ni = 0; ni < 8; ni++) {
            int r  = bm0 + wr * 32 + mi * 16 + g;
            int cc = bn0 + wc * 64 + ni * 8 + c * 2;
            *reinterpret_cast<uint32_t*>(&C[(size_t)r * Nc + cc]) =
                pack_h2(acc[mi][ni][0], acc[mi][ni][1]);
            *reinterpret_cast<uint32_t*>(&C[(size_t)(r + 8) * Nc + cc]) =
                pack_h2(acc[mi][ni][2], acc[mi][ni][3]);
        }
}

// ---------------- gemm2: single-shot (full K in smem, no loop barriers) --------
__global__ void __launch_bounds__(256, 2)
k_gemm2h(const __half* __restrict__ A, const __half* __restrict__ Bt,
         __half* __restrict__ C) {
    constexpr int K = H1_DIM, Nc = NZ_DIM;
    constexpr int P = 264;             // halfs per row (528B, 16B-aligned)
    // ldmatrix bank check: row stride 132 words -> 8 rows x 4-bank groups cover 32

    extern __shared__ __half smh[];
    const uint32_t smem_u32 = (uint32_t)__cvta_generic_to_shared(smh);
    const uint32_t bb0 = smem_u32 + (uint32_t)(128 * P) * 2u;

    const int tid  = threadIdx.x;
    const int warp = tid >> 5, lane = tid & 31;
    const int wr = warp >> 1, wc = warp & 1;
    const int bm0 = blockIdx.y * 128;
    const int g = lane >> 2, c = lane & 3;

    const int lr = lane & 7, q = lane >> 3;
    uint32_t offA[2], offB[2];
#pragma unroll
    for (int mi = 0; mi < 2; mi++) {
        int row = wr * 32 + mi * 16 + lr + (q & 1) * 8;
        int col = (q >> 1) * 8;
        offA[mi] = (uint32_t)(row * P + col) * 2u;
    }
#pragma unroll
    for (int ii = 0; ii < 2; ii++) {
        int row = wc * 32 + (2 * ii + (q >> 1)) * 8 + lr;
        int col = (q & 1) * 8;
        offB[ii] = (uint32_t)(row * P + col) * 2u;
    }

    // load full A (128x256) and B (64x256) tiles
    {
        const __half* Ag = A + (size_t)bm0 * K;
#pragma unroll
        for (int i = 0; i < 16; i++) {
            int v = tid + i * 256;
            int r = v >> 5, ch = v & 31;
            cp16(smem_u32 + (uint32_t)(r * P + ch * 8) * 2u,
                 Ag + (size_t)r * K + ch * 8);
        }
#pragma unroll
        for (int i = 0; i < 8; i++) {
            int v = tid + i * 256;
            int r = v >> 5, ch = v & 31;
            cp16(bb0 + (uint32_t)(r * P + ch * 8) * 2u,
                 Bt + (size_t)r * K + ch * 8);
        }
    }
    cp_commit();

    float acc[2][4][4];
#pragma unroll
    for (int mi = 0; mi < 2; mi++)
#pragma unroll
        for (int ni = 0; ni < 4; ni++)
#pragma unroll
            for (int j = 0; j < 4; j++) acc[mi][ni][j] = 0.f;

    cp_wait<0>();
    __syncthreads();

#pragma unroll
    for (int kk = 0; kk < K / 16; kk++) {
        const uint32_t kofs = (uint32_t)(kk * 16) * 2u;
        uint32_t af[2][4];
        uint32_t bf[4][2];
        ldsm_x4(af[0][0], af[0][1], af[0][2], af[0][3],
                smem_u32 + offA[0] + kofs);
        ldsm_x4(af[1][0], af[1][1], af[1][2], af[1][3],
                smem_u32 + offA[1] + kofs);
#pragma unroll
        for (int ii = 0; ii < 2; ii++)
            ldsm_x4(bf[2 * ii][0], bf[2 * ii][1], bf[2 * ii + 1][0],
                    bf[2 * ii + 1][1], bb0 + offB[ii] + kofs);
#pragma unroll
        for (int mi = 0; mi < 2; mi++)
#pragma unroll
            for (int ni = 0; ni < 4; ni++)
                mma_f16(acc[mi][ni], af[mi], bf[ni]);
    }

#pragma unroll
    for (int mi = 0; mi < 2; mi++)
#pragma unroll
        for (int ni = 0; ni < 4; ni++) {
            int r  = bm0 + wr * 32 + mi * 16 + g;
            int cc = wc * 32 + ni * 8 + c * 2;
            *reinterpret_cast<uint32_t*>(&C[(size_t)r * Nc + cc]) =
                pack_h2(acc[mi][ni][0], acc[mi][ni][1]);
            *reinterpret_cast<uint32_t*>(&C[(size_t)(r + 8) * Nc + cc]) =
                pack_h2(acc[mi][ni][2], acc[mi][ni][3]);
        }
}

// ---------------- z @ z^T (fp16 operands, symmetric, streaming stores) ---------
__global__ void __launch_bounds__(256, 2)
k_zzt_h(const __half* __restrict__ Z, float* __restrict__ C) {
    constexpr int P = 72;
    extern __shared__ __half smz[];
    __half* sAh = smz;
    __half* sBh = smz + 128 * P;
    const uint32_t smem_u32 = (uint32_t)__cvta_generic_to_shared(smz);

    const int tid  = threadIdx.x;
    const int warp = tid >> 5, lane = tid & 31;
    const int wm = warp & 1, wn = warp >> 1;
    const int g = lane >> 2, c = lane & 3;

    int t = blockIdx.x;
    int bi = (int)((sqrtf(8.f * (float)t + 1.f) - 1.f) * 0.5f);
    while ((bi + 1) * (bi + 2) / 2 <= t) bi++;
    while (bi * (bi + 1) / 2 > t) bi--;
    int bj = t - bi * (bi + 1) / 2;
    const int bm0 = bi * 128;
    const int bn0 = bj * 128;

#pragma unroll
    for (int i = 0; i < 4; i++) {
        int v = tid + i * 256;
        int r = v >> 3, ch = v & 7;
        cp16(smem_u32 + (uint32_t)(r * P + ch * 8) * 2u,
             Z + (size_t)(bm0 + r) * NZ_DIM + ch * 8);
    }
#pragma unroll
    for (int i = 0; i < 4; i++) {
        int v = tid + i * 256;
        int r = v >> 3, ch = v & 7;
        cp16(smem_u32 + (uint32_t)(128 * P + r * P + ch * 8) * 2u,
             Z + (size_t)(bn0 + r) * NZ_DIM + ch * 8);
    }
    cp_commit();
    cp_wait<0>();
    __syncthreads();

    float acc[4][4][4];
#pragma unroll
    for (int mi = 0; mi < 4; mi++)
#pragma unroll
        for (int ni = 0; ni < 4; ni++)
#pragma unroll
            for (int j = 0; j < 4; j++) acc[mi][ni][j] = 0.f;

#pragma unroll
    for (int ks = 0; ks < 4; ks++) {
        const int k0 = ks * 16;
        uint32_t af[4][4];
        uint32_t bf[4][2];
#pragma unroll
        for (int mi = 0; mi < 4; mi++) {
            int r = wm * 64 + mi * 16 + g;
            af[mi][0] = *reinterpret_cast<const uint32_t*>(&sAh[r * P + k0 + 2 * c]);
            af[mi][1] = *reinterpret_cast<const uint32_t*>(&sAh[(r + 8) * P + k0 + 2 * c]);
            af[mi][2] = *reinterpret_cast<const uint32_t*>(&sAh[r * P + k0 + 2 * c + 8]);
            af[mi][3] = *reinterpret_cast<const uint32_t*>(&sAh[(r + 8) * P + k0 + 2 * c + 8]);
        }
#pragma unroll
        for (int ni = 0; ni < 4; ni++) {
            int n = wn * 32 + ni * 8 + g;
            bf[ni][0] = *reinterpret_cast<const uint32_t*>(&sBh[n * P + k0 + 2 * c]);
            bf[ni][1] = *reinterpret_cast<const uint32_t*>(&sBh[n * P + k0 + 2 * c + 8]);
        }
#pragma unroll
        for (int mi = 0; mi < 4; mi++)
#pragma unroll
            for (int ni = 0; ni < 4; ni++)
                mma_f16(acc[mi][ni], af[mi], bf[ni]);
    }

#pragma unroll
    for (int mi = 0; mi < 4; mi++)
#pragma unroll
        for (int ni = 0; ni < 4; ni++) {
            int r  = bm0 + wm * 64 + mi * 16 + g;
            int cc = bn0 + wn * 32 + ni * 8 + c * 2;
            st_cs2(&C[(size_t)r * N_NODES + cc], acc[mi][ni][0], acc[mi][ni][1]);
            st_cs2(&C[(size_t)(r + 8) * N_NODES + cc], acc[mi][ni][2], acc[mi][ni][3]);
        }

    if (bi == bj) return;

#pragma unroll
    for (int mi = 0; mi < 4; mi++)
#pragma unroll
        for (int ni = 0; ni < 4; ni++) {
            int r  = bm0 + wm * 64 + mi * 16 + g;
            int cc = bn0 + wn * 32 + ni * 8 + c * 2;
            st_cs1(&C[(size_t)cc * N_NODES + r],           acc[mi][ni][0]);
            st_cs1(&C[(size_t)(cc + 1) * N_NODES + r],     acc[mi][ni][1]);
            st_cs1(&C[(size_t)cc * N_NODES + r + 8],       acc[mi][ni][2]);
            st_cs1(&C[(size_t)(cc + 1) * N_NODES + r + 8], acc[mi][ni][3]);
        }
}

// ---------------- stream/event singletons --------------------------------------
struct AuxRes {
    cudaStream_t s2;
    cudaEvent_t  evFork, evX, evJoin;
    AuxRes() {
        cudaStreamCreateWithFlags(&s2, cudaStreamNonBlocking);
        cudaEventCreateWithFlags(&evFork, cudaEventDisableTiming);
        cudaEventCreateWithFlags(&evX, cudaEventDisableTiming);
        cudaEventCreateWithFlags(&evJoin, cudaEventDisableTiming);
    }
};

// ---------------- launch --------------------------------------------------------
extern "C" void kernel_launch(void* const* d_in, const int* in_sizes, int n_in,
                              void* d_out, int out_size) {
    static AuxRes aux;

    const float* x  = (const float*)d_in[0];
    const float* W1 = (const float*)d_in[1];
    const float* W2 = (const float*)d_in[2];
    const float* ew = (const float*)d_in[3];
    const int*   ei = (const int*)d_in[4];

    float* out  = (float*)d_out;
    float* abar = out;
    float* z    = out + (size_t)N_NODES * N_NODES;

    __half *xh, *s1h, *h1h, *s2h, *w1t, *w2t, *zrh;
    cudaGetSymbolAddress((void**)&xh,  g_xh);
    cudaGetSymbolAddress((void**)&s1h, g_s1h);
    cudaGetSymbolAddress((void**)&h1h, g_h1h);
    cudaGetSymbolAddress((void**)&s2h, g_s2h);
    cudaGetSymbolAddress((void**)&w1t, g_w1t);
    cudaGetSymbolAddress((void**)&w2t, g_w2t);
    cudaGetSymbolAddress((void**)&zrh, g_zrh);

    constexpr int SM_G1  = 3 * 2 * 16384;                  // 98304
    constexpr int SM_G2  = (128 * 264 + 64 * 264) * 2;     // 101376
    constexpr int SM_ZZT = 2 * 128 * 72 * 2;               // 36864

    cudaFuncSetAttribute(k_gemm1hh,
                         cudaFuncAttributeMaxDynamicSharedMemorySize, SM_G1);
    cudaFuncSetAttribute(k_gemm2h,
                         cudaFuncAttributeMaxDynamicSharedMemorySize, SM_G2);
    cudaFuncSetAttribute(k_zzt_h,
                         cudaFuncAttributeMaxDynamicSharedMemorySize, SM_ZZT);

    // fork: side stream does x->fp16 convert then CSR chain
    cudaEventRecord(aux.evFork, 0);
    cudaStreamWaitEvent(aux.s2, aux.evFork, 0);

    k_transpose_h<<<dim3(H1_DIM / 32, F_IN / 32), dim3(32, 8)>>>(      // main
        W1, w1t, F_IN, H1_DIM);
    k_x2h<<<N_NODES * F_IN / 4 / 256, 256, 0, aux.s2>>>(               // s2
        (const float4*)x, (uint2*)xh);
    cudaEventRecord(aux.evX, aux.s2);
    k_transpose_h<<<dim3(NZ_DIM / 32, H1_DIM / 32), dim3(32, 8)>>>(    // main
        W2, w2t, H1_DIM, NZ_DIM);

    cudaStreamWaitEvent(0, aux.evX, 0);
    k_gemm1hh<<<dim3(H1_DIM / 128, N_NODES / 128), 256, SM_G1>>>(      // main
        xh, w1t, s1h);

    k_zero_counts<<<N_NODES / 1024, 256, 0, aux.s2>>>();               // s2
    k_hist<<<E_EDGES / 256, 256, 0, aux.s2>>>(ei);                     // s2
    k_scan<<<1, 256, 0, aux.s2>>>();                                   // s2
    k_scatter<<<E_EDGES / 256, 256, 0, aux.s2>>>(ei, ew);              // s2

    cudaEventRecord(aux.evJoin, aux.s2);
    cudaStreamWaitEvent(0, aux.evJoin, 0);

    k_spmm_relu_256h2<<<N_NODES / 2, 256>>>(                           // main
        (const __half2*)s1h, (__half2*)h1h);
    k_gemm2h<<<dim3(1, N_NODES / 128), 256, SM_G2>>>(h1h, w2t, s2h);   // main
    k_spmm_relu_64h2<<<N_NODES / 8, 256>>>(                            // main
        (const __half2*)s2h, (float2*)z, (__half2*)zrh);
    const int ntile = N_NODES / 128;
    k_zzt_h<<<ntile * (ntile + 1) / 2, 256, SM_ZZT>>>(zrh, abar);      // main
}

// round 14
// speedup vs baseline: 1.4763x; 1.0507x over previous
#include <cuda_runtime.h>
#include <cuda_fp16.h>
#include <cstdint>
#include <cstddef>

#define N_NODES 16384
#define E_EDGES 262144
#define F_IN    1024
#define H1_DIM  256
#define NZ_DIM  64

// ---------------- scratch ----------------------------------------------------
__device__ __half g_xh [N_NODES * F_IN];
__device__ __half g_s1h[N_NODES * H1_DIM];
__device__ __half g_h1h[N_NODES * H1_DIM];
__device__ __half g_s2h[N_NODES * NZ_DIM];
__device__ __half g_w1t[H1_DIM * F_IN];
__device__ __half g_w2t[NZ_DIM * H1_DIM];
__device__ __half g_zrh[N_NODES * NZ_DIM];
__device__ int    g_off   [N_NODES + 1];
__device__ int    g_cursor[N_NODES];
__device__ int2   g_srcw  [E_EDGES];

// ---------------- helpers -----------------------------------------------------
__device__ __forceinline__ void cp16(uint32_t s, const void* g) {
    asm volatile("cp.async.cg.shared.global [%0], [%1], 16;\n" ::"r"(s), "l"(g));
}
__device__ __forceinline__ void cp_commit() {
    asm volatile("cp.async.commit_group;\n");
}
template <int N>
__device__ __forceinline__ void cp_wait() {
    asm volatile("cp.async.wait_group %0;\n" ::"n"(N));
}
__device__ __forceinline__ uint32_t pack_h2(float lo, float hi) {
    __half2 h = __floats2half2_rn(lo, hi);
    return *reinterpret_cast<uint32_t*>(&h);
}
__device__ __forceinline__ void mma_f16(float (&d)[4], const uint32_t (&a)[4],
                                        const uint32_t (&b)[2]) {
    asm volatile(
        "mma.sync.aligned.m16n8k16.row.col.f32.f16.f16.f32 "
        "{%0,%1,%2,%3}, {%4,%5,%6,%7}, {%8,%9}, {%0,%1,%2,%3};"
        : "+f"(d[0]), "+f"(d[1]), "+f"(d[2]), "+f"(d[3])
        : "r"(a[0]), "r"(a[1]), "r"(a[2]), "r"(a[3]), "r"(b[0]), "r"(b[1]));
}
__device__ __forceinline__ void ldsm_x4(uint32_t& r0, uint32_t& r1,
                                        uint32_t& r2, uint32_t& r3, uint32_t a) {
    asm volatile("ldmatrix.sync.aligned.m8n8.x4.shared.b16 {%0,%1,%2,%3}, [%4];"
                 : "=r"(r0), "=r"(r1), "=r"(r2), "=r"(r3) : "r"(a));
}
__device__ __forceinline__ void st_cs1(float* p, float v) {
    asm volatile("st.global.cs.f32 [%0], %1;" ::"l"(p), "f"(v) : "memory");
}
__device__ __forceinline__ void st_cs2(float* p, float v0, float v1) {
    asm volatile("st.global.cs.v2.f32 [%0], {%1, %2};"
                 ::"l"(p), "f"(v0), "f"(v1) : "memory");
}

// ---------------- x -> fp16 convert --------------------------------------------
__global__ void k_x2h(const float4* __restrict__ in, uint2* __restrict__ out) {
    int i = blockIdx.x * blockDim.x + threadIdx.x;
    float4 v = in[i];
    out[i] = make_uint2(pack_h2(v.x, v.y), pack_h2(v.z, v.w));
}

// ---------------- CSR build ----------------------------------------------------
__global__ void k_zero_counts() {
    int i = blockIdx.x * blockDim.x + threadIdx.x;
    ((int4*)g_cursor)[i] = make_int4(0, 0, 0, 0);
}
__global__ void k_hist(const int* __restrict__ ei) {
    int e = blockIdx.x * blockDim.x + threadIdx.x;
    if (e < E_EDGES) atomicAdd(&g_cursor[ei[E_EDGES + e]], 1);
}
__global__ void k_scan() {
    __shared__ int part[256];
    const int t = threadIdx.x;
    const int base = t * (N_NODES / 256);
    int s = 0;
#pragma unroll
    for (int j = 0; j < N_NODES / 256; j++) s += g_cursor[base + j];
    part[t] = s;
    __syncthreads();
    for (int off = 1; off < 256; off <<= 1) {
        int v = (t >= off) ? part[t - off] : 0;
        __syncthreads();
        part[t] += v;
        __syncthreads();
    }
    int run = part[t] - s;
#pragma unroll
    for (int j = 0; j < N_NODES / 256; j++) {
        int idx = base + j;
        int c = g_cursor[idx];
        g_off[idx] = run;
        g_cursor[idx] = run;
        run += c;
    }
    if (t == 255) g_off[N_NODES] = run;
}
__global__ void k_scatter(const int* __restrict__ ei, const float* __restrict__ ew) {
    int e = blockIdx.x * blockDim.x + threadIdx.x;
    if (e < E_EDGES) {
        int d = ei[E_EDGES + e];
        int p = atomicAdd(&g_cursor[d], 1);
        g_srcw[p] = make_int2(ei[e], __float_as_int(ew[e]));
    }
}

// ---------------- weight transpose -> fp16 -------------------------------------
__global__ void k_transpose_h(const float* __restrict__ in, __half* __restrict__ out,
                              int R, int C) {
    __shared__ float tile[32][33];
    const int bx = blockIdx.x * 32;
    const int by = blockIdx.y * 32;
    const int x = threadIdx.x, y0 = threadIdx.y;
#pragma unroll
    for (int j = y0; j < 32; j += 8)
        tile[j][x] = in[(size_t)(by + j) * C + bx + x];
    __syncthreads();
#pragma unroll
    for (int j = y0; j < 32; j += 8)
        out[(size_t)(bx + j) * R + by + x] = __float2half_rn(tile[x][j]);
}

// ---------------- SpMM + ReLU (half2 lanes, fp32 accumulate) -------------------
__global__ void __launch_bounds__(256) k_spmm_relu_256h2(
    const __half2* __restrict__ in2, __half2* __restrict__ out2) {
    __shared__ int2 se[2][128];
    __shared__ int sdeg[2];
    const int t    = threadIdx.x;
    const int sub  = t >> 7;
    const int lane = t & 127;
    const int row  = blockIdx.x * 2 + sub;
    if (t < 2) sdeg[t] = g_off[blockIdx.x * 2 + t + 1] - g_off[blockIdx.x * 2 + t];
    __syncthreads();
    const int beg = g_off[row];
    const int deg = sdeg[sub];
    const int nch = (max(sdeg[0], sdeg[1]) + 127) >> 7;
    float ax = 0.f, ay = 0.f;
    for (int ch = 0; ch < nch; ch++) {
        int m = min(128, deg - ch * 128);
        __syncthreads();
        if (lane < m) se[sub][lane] = g_srcw[beg + ch * 128 + lane];
        __syncthreads();
        int j = 0;
        for (; j + 8 <= m; j += 8) {
            int2 v[8];
            float2 f[8];
#pragma unroll
            for (int u = 0; u < 8; u++) v[u] = se[sub][j + u];
#pragma unroll
            for (int u = 0; u < 8; u++)
                f[u] = __half22float2(__ldg(&in2[(size_t)v[u].x * 128 + lane]));
#pragma unroll
            for (int u = 0; u < 8; u++) {
                float w = __int_as_float(v[u].y);
                ax += w * f[u].x;
                ay += w * f[u].y;
            }
        }
        for (; j < m; j++) {
            int2 v = se[sub][j];
            float2 f = __half22float2(__ldg(&in2[(size_t)v.x * 128 + lane]));
            float w = __int_as_float(v.y);
            ax += w * f.x;
            ay += w * f.y;
        }
    }
    out2[(size_t)row * 128 + lane] = __floats2half2_rn(fmaxf(ax, 0.f), fmaxf(ay, 0.f));
}

__global__ void __launch_bounds__(256) k_spmm_relu_64h2(
    const __half2* __restrict__ in2, float2* __restrict__ out2,
    __half2* __restrict__ outr2) {
    __shared__ int2 se[8][32];
    __shared__ int sdeg[8];
    const int t    = threadIdx.x;
    const int sub  = t >> 5;
    const int lane = t & 31;
    const int row  = blockIdx.x * 8 + sub;
    if (t < 8) sdeg[t] = g_off[blockIdx.x * 8 + t + 1] - g_off[blockIdx.x * 8 + t];
    __syncthreads();
    const int beg = g_off[row];
    const int deg = sdeg[sub];
    int mx = sdeg[0];
#pragma unroll
    for (int q = 1; q < 8; q++) mx = max(mx, sdeg[q]);
    const int nch = (mx + 31) >> 5;
    float ax = 0.f, ay = 0.f;
    for (int ch = 0; ch < nch; ch++) {
        int m = min(32, deg - ch * 32);
        __syncthreads();
        if (lane < m) se[sub][lane] = g_srcw[beg + ch * 32 + lane];
        __syncthreads();
        int j = 0;
        for (; j + 8 <= m; j += 8) {
            int2 v[8];
            float2 f[8];
#pragma unroll
            for (int u = 0; u < 8; u++) v[u] = se[sub][j + u];
#pragma unroll
            for (int u = 0; u < 8; u++)
                f[u] = __half22float2(__ldg(&in2[(size_t)v[u].x * 32 + lane]));
#pragma unroll
            for (int u = 0; u < 8; u++) {
                float w = __int_as_float(v[u].y);
                ax += w * f[u].x;
                ay += w * f[u].y;
            }
        }
        for (; j < m; j++) {
            int2 v = se[sub][j];
            float2 f = __half22float2(__ldg(&in2[(size_t)v.x * 32 + lane]));
            float w = __int_as_float(v.y);
            ax += w * f.x;
            ay += w * f.y;
        }
    }
    float rx = fmaxf(ax, 0.f), ry = fmaxf(ay, 0.f);
    out2 [(size_t)row * 32 + lane] = make_float2(rx, ry);
    outr2[(size_t)row * 32 + lane] = __floats2half2_rn(rx, ry);
}

// ---------------- gemm1: BM=128 BN=128 BK=64, SW128 swizzle, 3 stages -----------
__global__ void __launch_bounds__(256, 2)
k_gemm1hh(const __half* __restrict__ A, const __half* __restrict__ Bt,
          __half* __restrict__ C) {
    constexpr int K = F_IN, Nc = H1_DIM;
    constexpr int STAGE = 16384;
    constexpr int STG = 3;
    constexpr int NT = K / 64;

    extern __shared__ __half smh[];
    const uint32_t smem_u32 = (uint32_t)__cvta_generic_to_shared(smh);
    const uint32_t bb0 = smem_u32 + STG * STAGE;

    const int tid  = threadIdx.x;
    const int warp = tid >> 5, lane = tid & 31;
    const int wr = warp >> 1, wc = warp & 1;
    const int bm0 = blockIdx.y * 128, bn0 = blockIdx.x * 128;
    const int g = lane >> 2, c = lane & 3;

    const int lr = lane & 7, q = lane >> 3;
    uint32_t baseA[2], colA, xormA[2];
#pragma unroll
    for (int mi = 0; mi < 2; mi++) {
        int row = wr * 32 + mi * 16 + lr + (q & 1) * 8;
        baseA[mi] = (uint32_t)row * 128u;
        xormA[mi] = (uint32_t)((row & 7) << 4);
    }
    colA = (uint32_t)((q >> 1) * 16);
    uint32_t baseB[4], colB, xormB[4];
#pragma unroll
    for (int ii = 0; ii < 4; ii++) {
        int row = wc * 64 + (2 * ii + (q >> 1)) * 8 + lr;
        baseB[ii] = (uint32_t)row * 128u;
        xormB[ii] = (uint32_t)((row & 7) << 4);
    }
    colB = (uint32_t)((q & 1) * 16);

    float acc[2][8][4];
#pragma unroll
    for (int mi = 0; mi < 2; mi++)
#pragma unroll
        for (int ni = 0; ni < 8; ni++)
#pragma unroll
            for (int j = 0; j < 4; j++) acc[mi][ni][j] = 0.f;

    auto load_tiles = [&](int kt, int st) {
        const __half* Ag = A + (size_t)bm0 * K + kt * 64;
        uint32_t abase = smem_u32 + (uint32_t)(st * STAGE);
#pragma unroll
        for (int i = 0; i < 4; i++) {
            int v = tid + i * 256;
            int r = v >> 3, ch = v & 7;
            uint32_t off = (uint32_t)(r * 128 + ch * 16);
            uint32_t sw  = off ^ (uint32_t)((r & 7) << 4);
            cp16(abase + sw, Ag + (size_t)r * K + ch * 8);
        }
        const __half* Bg = Bt + (size_t)bn0 * K + kt * 64;
        uint32_t bbase = bb0 + (uint32_t)(st * STAGE);
#pragma unroll
        for (int i = 0; i < 4; i++) {
            int v = tid + i * 256;
            int r = v >> 3, ch = v & 7;
            uint32_t off = (uint32_t)(r * 128 + ch * 16);
            uint32_t sw  = off ^ (uint32_t)((r & 7) << 4);
            cp16(bbase + sw, Bg + (size_t)r * K + ch * 8);
        }
    };

    load_tiles(0, 0);
    cp_commit();
    load_tiles(1, 1);
    cp_commit();

    int st = 0;
    for (int kt = 0; kt < NT; kt++) {
        cp_wait<1>();
        __syncthreads();

        int pf = kt + 2;
        if (pf < NT) load_tiles(pf, (st + 2) % STG);
        cp_commit();

        uint32_t abase = smem_u32 + (uint32_t)(st * STAGE);
        uint32_t bbase = bb0 + (uint32_t)(st * STAGE);
#pragma unroll
        for (int ks = 0; ks < 4; ks++) {
            const uint32_t kofs = ks * 32;
            uint32_t af[2][4];
            uint32_t bf[8][2];
#pragma unroll
            for (int mi = 0; mi < 2; mi++)
                ldsm_x4(af[mi][0], af[mi][1], af[mi][2], af[mi][3],
                        abase + baseA[mi] + ((colA + kofs) ^ xormA[mi]));
#pragma unroll
            for (int ii = 0; ii < 4; ii++)
                ldsm_x4(bf[2 * ii][0], bf[2 * ii][1], bf[2 * ii + 1][0],
                        bf[2 * ii + 1][1],
                        bbase + baseB[ii] + ((colB + kofs) ^ xormB[ii]));
#pragma unroll
            for (int mi = 0; mi < 2; mi++)
#pragma unroll
                for (int ni = 0; ni < 8; ni++)
                    mma_f16(acc[mi][ni], af[mi], bf[ni]);
        }
        st = (st + 1) % STG;
    }

    __syncthreads();
#pragma unroll
    for (int mi = 0; mi < 2; mi++)
#pragma unroll
        for (int ni = 0; ni < 8; ni++) {
            int r  = bm0 + wr * 32 + mi * 16 + g;
            int cc = bn0 + wc * 64 + ni * 8 + c * 2;
            *reinterpret_cast<uint32_t*>(&C[(size_t)r * Nc + cc]) =
                pack_h2(acc[mi][ni][0], acc[mi][ni][1]);
            *reinterpret_cast<uint32_t*>(&C[(size_t)(r + 8) * Nc + cc]) =
                pack_h2(acc[mi][ni][2], acc[mi][ni][3]);
        }
}

// ---------------- gemm2: single-shot (full K in smem, no loop barriers) --------
__global__ void __launch_bounds__(256, 2)
k_gemm2h(const __half* __restrict__ A, const __half* __restrict__ Bt,
         __half* __restrict__ C) {
    constexpr int K = H1_DIM, Nc = NZ_DIM;
    constexpr int P = 264;

    extern __shared__ __half smh[];
    const uint32_t smem_u32 = (uint32_t)__cvta_generic_to_shared(smh);
    const uint32_t bb0 = smem_u32 + (uint32_t)(128 * P) * 2u;

    const int tid  = threadIdx.x;
    const int warp = tid >> 5, lane = tid & 31;
    const int wr = warp >> 1, wc = warp & 1;
    const int bm0 = blockIdx.y * 128;
    const int g = lane >> 2, c = lane & 3;

    const int lr = lane & 7, q = lane >> 3;
    uint32_t offA[2], offB[2];
#pragma unroll
    for (int mi = 0; mi < 2; mi++) {
        int row = wr * 32 + mi * 16 + lr + (q & 1) * 8;
        int col = (q >> 1) * 8;
        offA[mi] = (uint32_t)(row * P + col) * 2u;
    }
#pragma unroll
    for (int ii = 0; ii < 2; ii++) {
        int row = wc * 32 + (2 * ii + (q >> 1)) * 8 + lr;
        int col = (q & 1) * 8;
        offB[ii] = (uint32_t)(row * P + col) * 2u;
    }

    {
        const __half* Ag = A + (size_t)bm0 * K;
#pragma unroll
        for (int i = 0; i < 16; i++) {
            int v = tid + i * 256;
            int r = v >> 5, ch = v & 31;
            cp16(smem_u32 + (uint32_t)(r * P + ch * 8) * 2u,
                 Ag + (size_t)r * K + ch * 8);
        }
#pragma unroll
        for (int i = 0; i < 8; i++) {
            int v = tid + i * 256;
            int r = v >> 5, ch = v & 31;
            cp16(bb0 + (uint32_t)(r * P + ch * 8) * 2u,
                 Bt + (size_t)r * K + ch * 8);
        }
    }
    cp_commit();

    float acc[2][4][4];
#pragma unroll
    for (int mi = 0; mi < 2; mi++)
#pragma unroll
        for (int ni = 0; ni < 4; ni++)
#pragma unroll
            for (int j = 0; j < 4; j++) acc[mi][ni][j] = 0.f;

    cp_wait<0>();
    __syncthreads();

#pragma unroll
    for (int kk = 0; kk < K / 16; kk++) {
        const uint32_t kofs = (uint32_t)(kk * 16) * 2u;
        uint32_t af[2][4];
        uint32_t bf[4][2];
        ldsm_x4(af[0][0], af[0][1], af[0][2], af[0][3],
                smem_u32 + offA[0] + kofs);
        ldsm_x4(af[1][0], af[1][1], af[1][2], af[1][3],
                smem_u32 + offA[1] + kofs);
#pragma unroll
        for (int ii = 0; ii < 2; ii++)
            ldsm_x4(bf[2 * ii][0], bf[2 * ii][1], bf[2 * ii + 1][0],
                    bf[2 * ii + 1][1], bb0 + offB[ii] + kofs);
#pragma unroll
        for (int mi = 0; mi < 2; mi++)
#pragma unroll
            for (int ni = 0; ni < 4; ni++)
                mma_f16(acc[mi][ni], af[mi], bf[ni]);
    }

#pragma unroll
    for (int mi = 0; mi < 2; mi++)
#pragma unroll
        for (int ni = 0; ni < 4; ni++) {
            int r  = bm0 + wr * 32 + mi * 16 + g;
            int cc = wc * 32 + ni * 8 + c * 2;
            *reinterpret_cast<uint32_t*>(&C[(size_t)r * Nc + cc]) =
                pack_h2(acc[mi][ni][0], acc[mi][ni][1]);
            *reinterpret_cast<uint32_t*>(&C[(size_t)(r + 8) * Nc + cc]) =
                pack_h2(acc[mi][ni][2], acc[mi][ni][3]);
        }
}

// ---------------- z @ z^T: 2 column tiles per CTA, symmetric, streaming --------
// grid (64, 128): bi = blockIdx.y, bjp = blockIdx.x; active iff 2*bjp <= bi.
__global__ void __launch_bounds__(256, 2)
k_zzt_h(const __half* __restrict__ Z, float* __restrict__ C) {
    constexpr int P = 72;
    const int bi  = blockIdx.y;
    const int bj0 = blockIdx.x * 2;
    if (bj0 > bi) return;
    const bool has1 = (bj0 + 1 <= bi);

    extern __shared__ __half smz[];
    __half* sAh = smz;
    __half* sBh = smz + 128 * P;
    const uint32_t smem_u32 = (uint32_t)__cvta_generic_to_shared(smz);

    const int tid  = threadIdx.x;
    const int warp = tid >> 5, lane = tid & 31;
    const int wm = warp & 1, wn = warp >> 1;
    const int g = lane >> 2, c = lane & 3;

    const int bm0 = bi * 128;
    const int bn0 = bj0 * 128;

    // A tile (128 rows at bm0), B tile (128 or 256 rows at bn0)
#pragma unroll
    for (int i = 0; i < 4; i++) {
        int v = tid + i * 256;
        int r = v >> 3, ch = v & 7;
        cp16(smem_u32 + (uint32_t)(r * P + ch * 8) * 2u,
             Z + (size_t)(bm0 + r) * NZ_DIM + ch * 8);
    }
    const int brows = has1 ? 256 : 128;
#pragma unroll
    for (int i = 0; i < 8; i++) {
        int v = tid + i * 256;
        int r = v >> 3, ch = v & 7;
        if (r < brows)
            cp16(smem_u32 + (uint32_t)(128 * P + r * P + ch * 8) * 2u,
                 Z + (size_t)(bn0 + r) * NZ_DIM + ch * 8);
    }
    cp_commit();
    cp_wait<0>();
    __syncthreads();

    for (int tile = 0; tile < (has1 ? 2 : 1); tile++) {
        const int bj = bj0 + tile;
        const int bncur = bj * 128;
        const __half* sB = sBh + tile * 128 * P;

        float acc[4][4][4];
#pragma unroll
        for (int mi = 0; mi < 4; mi++)
#pragma unroll
            for (int ni = 0; ni < 4; ni++)
#pragma unroll
                for (int j = 0; j < 4; j++) acc[mi][ni][j] = 0.f;

#pragma unroll
        for (int ks = 0; ks < 4; ks++) {
            const int k0 = ks * 16;
            uint32_t af[4][4];
            uint32_t bf[4][2];
#pragma unroll
            for (int mi = 0; mi < 4; mi++) {
                int r = wm * 64 + mi * 16 + g;
                af[mi][0] = *reinterpret_cast<const uint32_t*>(&sAh[r * P + k0 + 2 * c]);
                af[mi][1] = *reinterpret_cast<const uint32_t*>(&sAh[(r + 8) * P + k0 + 2 * c]);
                af[mi][2] = *reinterpret_cast<const uint32_t*>(&sAh[r * P + k0 + 2 * c + 8]);
                af[mi][3] = *reinterpret_cast<const uint32_t*>(&sAh[(r + 8) * P + k0 + 2 * c + 8]);
            }
#pragma unroll
            for (int ni = 0; ni < 4; ni++) {
                int n = wn * 32 + ni * 8 + g;
                bf[ni][0] = *reinterpret_cast<const uint32_t*>(&sB[n * P + k0 + 2 * c]);
                bf[ni][1] = *reinterpret_cast<const uint32_t*>(&sB[n * P + k0 + 2 * c + 8]);
            }
#pragma unroll
            for (int mi = 0; mi < 4; mi++)
#pragma unroll
                for (int ni = 0; ni < 4; ni++)
                    mma_f16(acc[mi][ni], af[mi], bf[ni]);
        }

        // direct store (rows bm0.., cols bncur..)
#pragma unroll
        for (int mi = 0; mi < 4; mi++)
#pragma unroll
            for (int ni = 0; ni < 4; ni++) {
                int r  = bm0 + wm * 64 + mi * 16 + g;
                int cc = bncur + wn * 32 + ni * 8 + c * 2;
                st_cs2(&C[(size_t)r * N_NODES + cc], acc[mi][ni][0], acc[mi][ni][1]);
                st_cs2(&C[(size_t)(r + 8) * N_NODES + cc], acc[mi][ni][2], acc[mi][ni][3]);
            }

        if (bi != bj) {
            // transposed store (rows bncur.., cols bm0..)
#pragma unroll
            for (int mi = 0; mi < 4; mi++)
#pragma unroll
                for (int ni = 0; ni < 4; ni++) {
                    int r  = bm0 + wm * 64 + mi * 16 + g;
                    int cc = bncur + wn * 32 + ni * 8 + c * 2;
                    st_cs1(&C[(size_t)cc * N_NODES + r],           acc[mi][ni][0]);
                    st_cs1(&C[(size_t)(cc + 1) * N_NODES + r],     acc[mi][ni][1]);
                    st_cs1(&C[(size_t)cc * N_NODES + r + 8],       acc[mi][ni][2]);
                    st_cs1(&C[(size_t)(cc + 1) * N_NODES + r + 8], acc[mi][ni][3]);
                }
        }
    }
}

// ---------------- stream/event singletons --------------------------------------
struct AuxRes {
    cudaStream_t s2;
    cudaEvent_t  evFork, evX, evJoin;
    AuxRes() {
        cudaStreamCreateWithFlags(&s2, cudaStreamNonBlocking);
        cudaEventCreateWithFlags(&evFork, cudaEventDisableTiming);
        cudaEventCreateWithFlags(&evX, cudaEventDisableTiming);
        cudaEventCreateWithFlags(&evJoin, cudaEventDisableTiming);
    }
};

// ---------------- launch --------------------------------------------------------
extern "C" void kernel_launch(void* const* d_in, const int* in_sizes, int n_in,
                              void* d_out, int out_size) {
    static AuxRes aux;

    const float* x  = (const float*)d_in[0];
    const float* W1 = (const float*)d_in[1];
    const float* W2 = (const float*)d_in[2];
    const float* ew = (const float*)d_in[3];
    const int*   ei = (const int*)d_in[4];

    float* out  = (float*)d_out;
    float* abar = out;
    float* z    = out + (size_t)N_NODES * N_NODES;

    __half *xh, *s1h, *h1h, *s2h, *w1t, *w2t, *zrh;
    cudaGetSymbolAddress((void**)&xh,  g_xh);
    cudaGetSymbolAddress((void**)&s1h, g_s1h);
    cudaGetSymbolAddress((void**)&h1h, g_h1h);
    cudaGetSymbolAddress((void**)&s2h, g_s2h);
    cudaGetSymbolAddress((void**)&w1t, g_w1t);
    cudaGetSymbolAddress((void**)&w2t, g_w2t);
    cudaGetSymbolAddress((void**)&zrh, g_zrh);

    constexpr int SM_G1  = 3 * 2 * 16384;                  // 98304
    constexpr int SM_G2  = (128 * 264 + 64 * 264) * 2;     // 101376
    constexpr int SM_ZZT = (128 + 256) * 72 * 2;           // 55296

    cudaFuncSetAttribute(k_gemm1hh,
                         cudaFuncAttributeMaxDynamicSharedMemorySize, SM_G1);
    cudaFuncSetAttribute(k_gemm2h,
                         cudaFuncAttributeMaxDynamicSharedMemorySize, SM_G2);
    cudaFuncSetAttribute(k_zzt_h,
                         cudaFuncAttributeMaxDynamicSharedMemorySize, SM_ZZT);

    // fork: side stream does x->fp16 convert then CSR chain
    cudaEventRecord(aux.evFork, 0);
    cudaStreamWaitEvent(aux.s2, aux.evFork, 0);

    k_transpose_h<<<dim3(H1_DIM / 32, F_IN / 32), dim3(32, 8)>>>(      // main
        W1, w1t, F_IN, H1_DIM);
    k_x2h<<<N_NODES * F_IN / 4 / 256, 256, 0, aux.s2>>>(               // s2
        (const float4*)x, (uint2*)xh);
    cudaEventRecord(aux.evX, aux.s2);
    k_transpose_h<<<dim3(NZ_DIM / 32, H1_DIM / 32), dim3(32, 8)>>>(    // main
        W2, w2t, H1_DIM, NZ_DIM);

    cudaStreamWaitEvent(0, aux.evX, 0);
    k_gemm1hh<<<dim3(H1_DIM / 128, N_NODES / 128), 256, SM_G1>>>(      // main
        xh, w1t, s1h);

    k_zero_counts<<<N_NODES / 1024, 256, 0, aux.s2>>>();               // s2
    k_hist<<<E_EDGES / 256, 256, 0, aux.s2>>>(ei);                     // s2
    k_scan<<<1, 256, 0, aux.s2>>>();                                   // s2
    k_scatter<<<E_EDGES / 256, 256, 0, aux.s2>>>(ei, ew);              // s2

    cudaEventRecord(aux.evJoin, aux.s2);
    cudaStreamWaitEvent(0, aux.evJoin, 0);

    k_spmm_relu_256h2<<<N_NODES / 2, 256>>>(                           // main
        (const __half2*)s1h, (__half2*)h1h);
    k_gemm2h<<<dim3(1, N_NODES / 128), 256, SM_G2>>>(h1h, w2t, s2h);   // main
    k_spmm_relu_64h2<<<N_NODES / 8, 256>>>(                            // main
        (const __half2*)s2h, (float2*)z, (__half2*)zrh);
    k_zzt_h<<<dim3(64, 128), 256, SM_ZZT>>>(zrh, abar);                // main
}